// round 12
// baseline (speedup 1.0000x reference)
#include <cuda_runtime.h>
#include <cuda_bf16.h>
#include <math.h>
#include <stdint.h>

#define NN 50000
#define NE 200000
#define ND 160
#define ED 64
#define RD 8
#define HD 256
#define EH 128

// ---------------- scratch (device globals; no runtime allocation) ----------
__device__ float g_init_edge[NE*ED];
__device__ float g_edge_lat [NE*ED];
__device__ float g_node_lat [NN*ND];
__device__ float g_msg      [NE*HD];
__device__ float g_logit    [NE];
__device__ float g_P        [(size_t)NN*768];
__device__ float g_Pbase    [(size_t)NN*768];
__device__ float g_Penc     [(size_t)NN*256];
__device__ uint32_t gWPh[768*160], gWPl[768*160];
__device__ uint32_t gWEh[256*80],  gWEl[256*80];
__device__ uint32_t gB1h[256*64],  gB1l[256*64];
__device__ uint32_t gB2h[64*128],  gB2l[64*128];
__device__ uint32_t gB3h[256*32],  gB3l[256*32];
__device__ int   g_deg      [NN];
__device__ int   g_rowptr   [NN+1];
__device__ int   g_fill     [NN];
__device__ int   g_eids     [NE];
__device__ int   g_part     [64];

// ---------------- helpers ----------------------------------------------------
__device__ __forceinline__ void split2(float x, float y, uint32_t& hi, uint32_t& lo){
    __nv_bfloat162 h = __floats2bfloat162_rn(x, y);
    hi = *(uint32_t*)&h;
    float rx = x - __bfloat162float(h.x);
    float ry = y - __bfloat162float(h.y);
    __nv_bfloat162 l = __floats2bfloat162_rn(rx, ry);
    lo = *(uint32_t*)&l;
}
__device__ __forceinline__ void mma_bf16(
    float& c0, float& c1, float& c2, float& c3,
    uint32_t a0, uint32_t a1, uint32_t a2, uint32_t a3, uint32_t b0, uint32_t b1)
{
    asm volatile(
        "mma.sync.aligned.m16n8k16.row.col.f32.bf16.bf16.f32 "
        "{%0,%1,%2,%3}, {%4,%5,%6,%7}, {%8,%9}, {%0,%1,%2,%3};"
        : "+f"(c0), "+f"(c1), "+f"(c2), "+f"(c3)
        : "r"(a0), "r"(a1), "r"(a2), "r"(a3), "r"(b0), "r"(b1));
}
__device__ __forceinline__ void ldsm_x4(uint32_t& r0, uint32_t& r1, uint32_t& r2, uint32_t& r3, uint32_t a){
    asm volatile("ldmatrix.sync.aligned.m8n8.x4.shared.b16 {%0,%1,%2,%3}, [%4];"
        : "=r"(r0), "=r"(r1), "=r"(r2), "=r"(r3) : "r"(a));
}

// ---------------- CSR build --------------------------------------------------
__global__ void k_hist(const int* __restrict__ row){
    int e = blockIdx.x*blockDim.x + threadIdx.x;
    if (e < NE) atomicAdd(&g_deg[row[e]], 1);
}

__global__ void k_scan1(){
    __shared__ int ss[256];
    int b = blockIdx.x, base = b*1024, tid = threadIdx.x;
    int v[4], tsum = 0;
#pragma unroll
    for (int r = 0; r < 4; r++){
        int idx = base + tid*4 + r;
        v[r] = (idx < NN) ? g_deg[idx] : 0;
        tsum += v[r];
    }
    ss[tid] = tsum; __syncthreads();
    for (int off = 1; off < 256; off <<= 1){
        int add = (tid >= off) ? ss[tid-off] : 0;
        __syncthreads();
        ss[tid] += add;
        __syncthreads();
    }
    int run = ss[tid] - tsum;
#pragma unroll
    for (int r = 0; r < 4; r++){
        int idx = base + tid*4 + r;
        if (idx < NN) g_rowptr[idx] = run;
        run += v[r];
    }
    if (tid == 255) g_part[b] = ss[255];
}

__global__ void k_scan2(){
    if (threadIdx.x == 0){
        int run = 0;
        for (int i = 0; i < 49; i++){ int t = g_part[i]; g_part[i] = run; run += t; }
    }
}

__global__ void k_scan3(){
    int i = blockIdx.x*blockDim.x + threadIdx.x;
    if (i < NN) g_rowptr[i] += g_part[i >> 10];
    if (i == 0) g_rowptr[NN] = NE;
}

__global__ void k_scatter(const int* __restrict__ row){
    int e = blockIdx.x*blockDim.x + threadIdx.x;
    if (e < NE){
        int p = atomicAdd(&g_fill[row[e]], 1);
        g_eids[p] = e;
    }
}

// ---------------- pack all weight tables (bf16 hi/lo, K-major) ---------------
__global__ void k_prep(const float* __restrict__ eW1, const float* __restrict__ mW1,
                       const float* __restrict__ encW1, const float* __restrict__ eW2)
{
    int i = blockIdx.x*blockDim.x + threadIdx.x;
    if (i < 768*160){
        int n = i/160, w = i - n*160, k = w*2;
        float f0, f1;
        if (n < 256){ f0 = eW1[k*256+n]; f1 = eW1[(k+1)*256+n]; }
        else if (n < 512){ int nn = n-256; f0 = eW1[(320+k)*256+nn]; f1 = eW1[(321+k)*256+nn]; }
        else { int nn = n-512; f0 = mW1[k*256+nn]; f1 = mW1[(k+1)*256+nn]; }
        split2(f0, f1, gWPh[i], gWPl[i]);
    }
    if (i < 256*80){
        int n = i/80, w = i - n*80, k = w*2;
        float f0, f1;
        if (n < 128){ f0 = encW1[k*128+n]; f1 = encW1[(k+1)*128+n]; }
        else { int nn = n-128; f0 = encW1[(160+k)*128+nn]; f1 = encW1[(161+k)*128+nn]; }
        split2(f0, f1, gWEh[i], gWEl[i]);
    }
    if (i < 256*64){
        int n = i/64, w = i - n*64, k = w*2;
        split2(eW1[(640+k)*256+n], eW1[(641+k)*256+n], gB1h[i], gB1l[i]);
    }
    if (i < 64*128){
        int n = i/128, w = i - n*128, k = w*2;
        split2(eW2[k*64+n], eW2[(k+1)*64+n], gB2h[i], gB2l[i]);
    }
    if (i < 256*32){
        int n = i/32, w = i - n*32, k = w*2;
        split2(mW1[(320+k)*256+n], mW1[(321+k)*256+n], gB3h[i], gB3l[i]);
    }
}

// ---------------- bf16 3-split dense GEMM (m16n8k16) -------------------------
__global__ __launch_bounds__(256,2) void k_gemm_bf(
    const float* __restrict__ A0, const float* __restrict__ A1,
    const uint32_t* __restrict__ Bh, const uint32_t* __restrict__ Bl,
    int K, int bstrW,
    float* __restrict__ out, int ostride, const float* __restrict__ base)
{
    __shared__ uint32_t sAh[128*20], sAl[128*20], sBh[128*20], sBl[128*20];
    const int tid = threadIdx.x, wid = tid>>5, lane = tid&31;
    const int gid = lane>>2, tq = lane&3;
    const int warp_m = (wid & 1)*64, warp_n = (wid >> 1)*32;
    const int m0 = blockIdx.x*128, n0 = blockIdx.y*128;

    float c[4][4][4];
#pragma unroll
    for (int i = 0; i < 4; i++)
#pragma unroll
        for (int j = 0; j < 4; j++)
#pragma unroll
            for (int r = 0; r < 4; r++) c[i][j][r] = 0.f;

    const int nk = K >> 5;
    for (int ch = 0; ch < nk; ch++){
        const int kc = ch*32;
        const float* A = (kc < 160) ? A0 : A1;
        const int ac = (kc < 160) ? kc : (kc - 160);
#pragma unroll
        for (int p = 0; p < 4; p++){
            int lin = tid + p*256;
            int row = lin>>3, f4 = lin&7;
            int gm = m0 + row;
            float4 v = make_float4(0.f,0.f,0.f,0.f);
            if (gm < NN) v = *(const float4*)&A[(size_t)gm*ND + ac + f4*4];
            uint32_t h0,l0,h1,l1;
            split2(v.x, v.y, h0, l0);
            split2(v.z, v.w, h1, l1);
            sAh[row*20 + f4*2]   = h0; sAh[row*20 + f4*2+1] = h1;
            sAl[row*20 + f4*2]   = l0; sAl[row*20 + f4*2+1] = l1;
        }
#pragma unroll
        for (int p = 0; p < 2; p++){
            int lin = tid + p*256;
            int row = lin>>2, q = lin&3;
            size_t gofs = (size_t)(n0+row)*bstrW + (kc>>1) + q*4;
            *(uint4*)&sBh[row*20 + q*4] = *(const uint4*)&Bh[gofs];
            *(uint4*)&sBl[row*20 + q*4] = *(const uint4*)&Bl[gofs];
        }
        __syncthreads();
#pragma unroll
        for (int s = 0; s < 2; s++){
            const int kb = s*8 + tq;
            uint32_t bh0[4], bh1[4], bl0[4], bl1[4];
#pragma unroll
            for (int nt = 0; nt < 4; nt++){
                int nr = warp_n + nt*8 + gid;
                bh0[nt] = sBh[nr*20 + kb]; bh1[nt] = sBh[nr*20 + kb + 4];
                bl0[nt] = sBl[nr*20 + kb]; bl1[nt] = sBl[nr*20 + kb + 4];
            }
#pragma unroll
            for (int mt = 0; mt < 4; mt++){
                int ar = warp_m + mt*16 + gid;
                uint32_t ah0 = sAh[ar*20+kb],     ah1 = sAh[(ar+8)*20+kb];
                uint32_t ah2 = sAh[ar*20+kb+4],   ah3 = sAh[(ar+8)*20+kb+4];
                uint32_t al0 = sAl[ar*20+kb],     al1 = sAl[(ar+8)*20+kb];
                uint32_t al2 = sAl[ar*20+kb+4],   al3 = sAl[(ar+8)*20+kb+4];
#pragma unroll
                for (int nt = 0; nt < 4; nt++){
                    mma_bf16(c[mt][nt][0], c[mt][nt][1], c[mt][nt][2], c[mt][nt][3],
                             ah0, ah1, ah2, ah3, bh0[nt], bh1[nt]);
                    mma_bf16(c[mt][nt][0], c[mt][nt][1], c[mt][nt][2], c[mt][nt][3],
                             ah0, ah1, ah2, ah3, bl0[nt], bl1[nt]);
                    mma_bf16(c[mt][nt][0], c[mt][nt][1], c[mt][nt][2], c[mt][nt][3],
                             al0, al1, al2, al3, bh0[nt], bh1[nt]);
                }
            }
        }
        __syncthreads();
    }

#pragma unroll
    for (int mt = 0; mt < 4; mt++){
        int r0 = m0 + warp_m + mt*16 + gid;
        int r1 = r0 + 8;
#pragma unroll
        for (int nt = 0; nt < 4; nt++){
            int gn = n0 + warp_n + nt*8 + tq*2;
            if (r0 < NN){
                float2 v = make_float2(c[mt][nt][0], c[mt][nt][1]);
                if (base){ float2 b = *(const float2*)&base[(size_t)r0*ostride + gn]; v.x += b.x; v.y += b.y; }
                *(float2*)&out[(size_t)r0*ostride + gn] = v;
            }
            if (r1 < NN){
                float2 v = make_float2(c[mt][nt][2], c[mt][nt][3]);
                if (base){ float2 b = *(const float2*)&base[(size_t)r1*ostride + gn]; v.x += b.x; v.y += b.y; }
                *(float2*)&out[(size_t)r1*ostride + gn] = v;
            }
        }
    }
}

// ---------------- fused edge kernel: ldmatrix A-operands ---------------------
__global__ __launch_bounds__(512,1) void k_edge_tc(
    const int* __restrict__ row, const int* __restrict__ col,
    const float* __restrict__ eb1, const float* __restrict__ eb2,
    const float* __restrict__ mb1, const float* __restrict__ attv,
    const float* __restrict__ lgE, const float* __restrict__ lbE)
{
    extern __shared__ uint32_t esm[];
    uint32_t* Ah  = esm;              // [128][68]
    uint32_t* Al  = esm + 8704;
    uint32_t* B1h = esm + 17408;      // [256][20]
    uint32_t* B1l = esm + 22528;
    uint32_t* Hh  = esm;              // [128][132] overlay (phase2)
    uint32_t* Hl  = esm + 16896;
    uint32_t* B2h = esm + 33792;      // [64][36]
    uint32_t* B2l = esm + 36096;
    uint32_t* NEh = esm;              // [128][36] overlay
    uint32_t* NEl = esm + 4608;
    uint32_t* B3h = esm + 9216;       // [256][36]
    uint32_t* B3l = esm + 18432;
    __shared__ int sR[128], sC[128];
    __shared__ float sAtt[256];
    __shared__ float sLog[128];
    __shared__ float sSum[128], sSq[128], sMu[128], sInv[128];

    const int tid = threadIdx.x, wid = tid>>5, lane = tid&31;
    const int gid = lane>>2, tq = lane&3;
    const int warp_m  = (wid & 1)*64;
    const int warp_n  = (wid >> 1)*32;
    const int warp_n2 = (wid >> 1)*8;
    const int e0 = blockIdx.x*128;

    const int lrow = lane & 15;
    const int lkh  = (lane >> 4) << 2;
    const uint32_t aAh = (uint32_t)__cvta_generic_to_shared(Ah);
    const uint32_t aAl = (uint32_t)__cvta_generic_to_shared(Al);
    const uint32_t aHh = (uint32_t)__cvta_generic_to_shared(Hh);
    const uint32_t aHl = (uint32_t)__cvta_generic_to_shared(Hl);
    const uint32_t aNh = (uint32_t)__cvta_generic_to_shared(NEh);
    const uint32_t aNl = (uint32_t)__cvta_generic_to_shared(NEl);
    uint32_t offA[4], offH[4], offN[4];
#pragma unroll
    for (int mt = 0; mt < 4; mt++){
        int r = warp_m + mt*16 + lrow;
        offA[mt] = (uint32_t)((r*68  + lkh) * 4);
        offH[mt] = (uint32_t)((r*132 + lkh) * 4);
        offN[mt] = (uint32_t)((r*36  + lkh) * 4);
    }

    if (tid < 128){
        int ge = e0 + tid;
        sR[tid] = (ge < NE) ? row[ge] : 0;
        sC[tid] = (ge < NE) ? col[ge] : 0;
        sLog[tid] = 0.f; sSum[tid] = 0.f; sSq[tid] = 0.f;
    }
    if (tid < 256) sAtt[tid] = attv[tid];
    __syncthreads();

    // ---- phase 1: stage A + C init from P gathers ---------------------------
    for (int lin = tid; lin < 8192; lin += 512){
        int r = lin>>6, w = lin&63, k = w*2;
        float2 v = make_float2(0.f, 0.f);
        if (e0 + r < NE)
            v = (k < 64) ? *(const float2*)&g_init_edge[(size_t)(e0+r)*ED + k]
                         : *(const float2*)&g_edge_lat [(size_t)(e0+r)*ED + (k-64)];
        split2(v.x, v.y, Ah[r*68+w], Al[r*68+w]);
    }
    float c1[4][4][4];
#pragma unroll
    for (int mt = 0; mt < 4; mt++){
        int rA = warp_m + mt*16 + gid, rB = rA + 8;
        size_t prA = (size_t)sR[rA]*768, pcA = (size_t)sC[rA]*768;
        size_t prB = (size_t)sR[rB]*768, pcB = (size_t)sC[rB]*768;
#pragma unroll
        for (int nt = 0; nt < 4; nt++){
            int cn = warp_n + nt*8 + tq*2;
            float2 b  = *(const float2*)&eb1[cn];
            float2 a1 = *(const float2*)&g_P[prA + cn];
            float2 a2 = *(const float2*)&g_P[pcA + 256 + cn];
            float2 a3 = *(const float2*)&g_P[prB + cn];
            float2 a4 = *(const float2*)&g_P[pcB + 256 + cn];
            c1[mt][nt][0] = a1.x + a2.x + b.x;
            c1[mt][nt][1] = a1.y + a2.y + b.y;
            c1[mt][nt][2] = a3.x + a4.x + b.x;
            c1[mt][nt][3] = a3.y + a4.y + b.y;
        }
    }
    __syncthreads();

#pragma unroll
    for (int ch = 0; ch < 4; ch++){
        for (int lin = tid; lin < 1024; lin += 512){
            int r = lin>>2, q = lin&3;
            size_t gofs = (size_t)r*64 + ch*16 + q*4;
            *(uint4*)&B1h[r*20 + q*4] = *(const uint4*)&gB1h[gofs];
            *(uint4*)&B1l[r*20 + q*4] = *(const uint4*)&gB1l[gofs];
        }
        __syncthreads();
#pragma unroll
        for (int s = 0; s < 2; s++){
            int kb = s*8 + tq;
            uint32_t kw = (uint32_t)((ch*16 + s*8) * 4);
            uint32_t bh0[4], bh1[4], bl0[4], bl1[4];
#pragma unroll
            for (int nt = 0; nt < 4; nt++){
                int nr = warp_n + nt*8 + gid;
                bh0[nt] = B1h[nr*20+kb]; bh1[nt] = B1h[nr*20+kb+4];
                bl0[nt] = B1l[nr*20+kb]; bl1[nt] = B1l[nr*20+kb+4];
            }
#pragma unroll
            for (int mt = 0; mt < 4; mt++){
                uint32_t ah0,ah1,ah2,ah3, al0,al1,al2,al3;
                ldsm_x4(ah0,ah1,ah2,ah3, aAh + offA[mt] + kw);
                ldsm_x4(al0,al1,al2,al3, aAl + offA[mt] + kw);
#pragma unroll
                for (int nt = 0; nt < 4; nt++){
                    mma_bf16(c1[mt][nt][0],c1[mt][nt][1],c1[mt][nt][2],c1[mt][nt][3],
                             ah0,ah1,ah2,ah3, bh0[nt],bh1[nt]);
                    mma_bf16(c1[mt][nt][0],c1[mt][nt][1],c1[mt][nt][2],c1[mt][nt][3],
                             ah0,ah1,ah2,ah3, bl0[nt],bl1[nt]);
                    mma_bf16(c1[mt][nt][0],c1[mt][nt][1],c1[mt][nt][2],c1[mt][nt][3],
                             al0,al1,al2,al3, bh0[nt],bh1[nt]);
                }
            }
        }
        __syncthreads();
    }

    // write hidden (relu, bf16 split) over A/B1 region
#pragma unroll
    for (int mt = 0; mt < 4; mt++){
        int rA = warp_m + mt*16 + gid, rB = rA + 8;
#pragma unroll
        for (int nt = 0; nt < 4; nt++){
            int wcol = (warp_n>>1) + nt*4 + tq;
            float v0 = fmaxf(c1[mt][nt][0], 0.f), v1 = fmaxf(c1[mt][nt][1], 0.f);
            float v2 = fmaxf(c1[mt][nt][2], 0.f), v3 = fmaxf(c1[mt][nt][3], 0.f);
            split2(v0, v1, Hh[rA*132+wcol], Hl[rA*132+wcol]);
            split2(v2, v3, Hh[rB*132+wcol], Hl[rB*132+wcol]);
        }
    }
    __syncthreads();

    // ---- phase 2 ------------------------------------------------------------
    float c2[4][4];
#pragma unroll
    for (int mt = 0; mt < 4; mt++){
        float2 b = *(const float2*)&eb2[warp_n2 + tq*2];
        c2[mt][0] = b.x; c2[mt][1] = b.y; c2[mt][2] = b.x; c2[mt][3] = b.y;
    }
#pragma unroll
    for (int ch = 0; ch < 4; ch++){
        {
            int r = tid>>3, q = tid&7;
            size_t gofs = (size_t)r*128 + ch*32 + q*4;
            *(uint4*)&B2h[r*36 + q*4] = *(const uint4*)&gB2h[gofs];
            *(uint4*)&B2l[r*36 + q*4] = *(const uint4*)&gB2l[gofs];
        }
        __syncthreads();
#pragma unroll
        for (int s = 0; s < 4; s++){
            int kb = s*8 + tq;
            uint32_t kw = (uint32_t)((ch*32 + s*8) * 4);
            int nr = warp_n2 + gid;
            uint32_t bh0 = B2h[nr*36+kb], bh1 = B2h[nr*36+kb+4];
            uint32_t bl0 = B2l[nr*36+kb], bl1 = B2l[nr*36+kb+4];
#pragma unroll
            for (int mt = 0; mt < 4; mt++){
                uint32_t ah0,ah1,ah2,ah3, al0,al1,al2,al3;
                ldsm_x4(ah0,ah1,ah2,ah3, aHh + offH[mt] + kw);
                ldsm_x4(al0,al1,al2,al3, aHl + offH[mt] + kw);
                mma_bf16(c2[mt][0],c2[mt][1],c2[mt][2],c2[mt][3], ah0,ah1,ah2,ah3, bh0,bh1);
                mma_bf16(c2[mt][0],c2[mt][1],c2[mt][2],c2[mt][3], ah0,ah1,ah2,ah3, bl0,bl1);
                mma_bf16(c2[mt][0],c2[mt][1],c2[mt][2],c2[mt][3], al0,al1,al2,al3, bh0,bh1);
            }
        }
        __syncthreads();
    }

    // ---- NE pack + LN stats; stage full B3 (stride 36) -----------------------
#pragma unroll
    for (int mt = 0; mt < 4; mt++){
        int rA = warp_m + mt*16 + gid, rB = rA + 8;
        int cn = warp_n2 + tq*2;
        int wcol = (warp_n2>>1) + tq;
        split2(c2[mt][0], c2[mt][1], NEh[rA*36+wcol], NEl[rA*36+wcol]);
        split2(c2[mt][2], c2[mt][3], NEh[rB*36+wcol], NEl[rB*36+wcol]);
        float2 iA = make_float2(0.f,0.f), iB = make_float2(0.f,0.f);
        if (e0 + rA < NE) iA = *(const float2*)&g_init_edge[(size_t)(e0+rA)*ED + cn];
        if (e0 + rB < NE) iB = *(const float2*)&g_init_edge[(size_t)(e0+rB)*ED + cn];
        c2[mt][0] += iA.x; c2[mt][1] += iA.y;
        c2[mt][2] += iB.x; c2[mt][3] += iB.y;
        atomicAdd(&sSum[rA], c2[mt][0] + c2[mt][1]);
        atomicAdd(&sSq [rA], c2[mt][0]*c2[mt][0] + c2[mt][1]*c2[mt][1]);
        atomicAdd(&sSum[rB], c2[mt][2] + c2[mt][3]);
        atomicAdd(&sSq [rB], c2[mt][2]*c2[mt][2] + c2[mt][3]*c2[mt][3]);
    }
    for (int lin = tid; lin < 2048; lin += 512){
        int r = lin>>3, q = lin&7;
        size_t gofs = (size_t)r*32 + q*4;
        *(uint4*)&B3h[r*36 + q*4] = *(const uint4*)&gB3h[gofs];
        *(uint4*)&B3l[r*36 + q*4] = *(const uint4*)&gB3l[gofs];
    }
    float c3[4][4][4];
#pragma unroll
    for (int mt = 0; mt < 4; mt++){
        int rA = warp_m + mt*16 + gid, rB = rA + 8;
        size_t pcA = (size_t)sC[rA]*768, pcB = (size_t)sC[rB]*768;
#pragma unroll
        for (int nt = 0; nt < 4; nt++){
            int cn = warp_n + nt*8 + tq*2;
            float2 b  = *(const float2*)&mb1[cn];
            float2 a1 = *(const float2*)&g_P[pcA + 512 + cn];
            float2 a2 = *(const float2*)&g_P[pcB + 512 + cn];
            c3[mt][nt][0] = a1.x + b.x; c3[mt][nt][1] = a1.y + b.y;
            c3[mt][nt][2] = a2.x + b.x; c3[mt][nt][3] = a2.y + b.y;
        }
    }
    __syncthreads();

    if (tid < 128){
        float mu = sSum[tid] * (1.f/ED);
        float var = sSq[tid] * (1.f/ED) - mu*mu;
        sMu[tid] = mu;
        sInv[tid] = rsqrtf(var + 1e-5f);
    }
    __syncthreads();

#pragma unroll
    for (int mt = 0; mt < 4; mt++){
        int rA = warp_m + mt*16 + gid, rB = rA + 8;
        int cn = warp_n2 + tq*2;
        float g0 = lgE[cn], g1 = lgE[cn+1], b0 = lbE[cn], b1 = lbE[cn+1];
        if (e0 + rA < NE){
            float mu = sMu[rA], inv = sInv[rA];
            *(float2*)&g_edge_lat[(size_t)(e0+rA)*ED + cn] =
                make_float2((c2[mt][0]-mu)*inv*g0 + b0, (c2[mt][1]-mu)*inv*g1 + b1);
        }
        if (e0 + rB < NE){
            float mu = sMu[rB], inv = sInv[rB];
            *(float2*)&g_edge_lat[(size_t)(e0+rB)*ED + cn] =
                make_float2((c2[mt][2]-mu)*inv*g0 + b0, (c2[mt][3]-mu)*inv*g1 + b1);
        }
    }

    // ---- phase 3 MMA loop ----------------------------------------------------
#pragma unroll
    for (int s = 0; s < 4; s++){
        int ka = s*8 + tq;
        uint32_t kw = (uint32_t)((s*8) * 4);
        uint32_t bh0[4], bh1[4], bl0[4], bl1[4];
#pragma unroll
        for (int nt = 0; nt < 4; nt++){
            int nr = warp_n + nt*8 + gid;
            bh0[nt] = B3h[nr*36+ka]; bh1[nt] = B3h[nr*36+ka+4];
            bl0[nt] = B3l[nr*36+ka]; bl1[nt] = B3l[nr*36+ka+4];
        }
#pragma unroll
        for (int mt = 0; mt < 4; mt++){
            uint32_t ah0,ah1,ah2,ah3, al0,al1,al2,al3;
            ldsm_x4(ah0,ah1,ah2,ah3, aNh + offN[mt] + kw);
            ldsm_x4(al0,al1,al2,al3, aNl + offN[mt] + kw);
#pragma unroll
            for (int nt = 0; nt < 4; nt++){
                mma_bf16(c3[mt][nt][0],c3[mt][nt][1],c3[mt][nt][2],c3[mt][nt][3],
                         ah0,ah1,ah2,ah3, bh0[nt],bh1[nt]);
                mma_bf16(c3[mt][nt][0],c3[mt][nt][1],c3[mt][nt][2],c3[mt][nt][3],
                         ah0,ah1,ah2,ah3, bl0[nt],bl1[nt]);
                mma_bf16(c3[mt][nt][0],c3[mt][nt][1],c3[mt][nt][2],c3[mt][nt][3],
                         al0,al1,al2,al3, bh0[nt],bh1[nt]);
            }
        }
    }

    // epilogue: relu -> g_msg, attention partial dot, logit
    float pa[4][2];
#pragma unroll
    for (int mt = 0; mt < 4; mt++){ pa[mt][0] = 0.f; pa[mt][1] = 0.f; }
#pragma unroll
    for (int mt = 0; mt < 4; mt++){
        int rA = warp_m + mt*16 + gid, rB = rA + 8;
#pragma unroll
        for (int nt = 0; nt < 4; nt++){
            int cn = warp_n + nt*8 + tq*2;
            float av0 = sAtt[cn], av1 = sAtt[cn+1];
            float v0 = fmaxf(c3[mt][nt][0], 0.f), v1 = fmaxf(c3[mt][nt][1], 0.f);
            float v2 = fmaxf(c3[mt][nt][2], 0.f), v3 = fmaxf(c3[mt][nt][3], 0.f);
            if (e0 + rA < NE)
                *(float2*)&g_msg[(size_t)(e0+rA)*HD + cn] = make_float2(v0, v1);
            if (e0 + rB < NE)
                *(float2*)&g_msg[(size_t)(e0+rB)*HD + cn] = make_float2(v2, v3);
            pa[mt][0] += v0*av0 + v1*av1;
            pa[mt][1] += v2*av0 + v3*av1;
        }
    }
#pragma unroll
    for (int off = 1; off <= 2; off <<= 1){
#pragma unroll
        for (int mt = 0; mt < 4; mt++){
            pa[mt][0] += __shfl_xor_sync(0xffffffffu, pa[mt][0], off, 4);
            pa[mt][1] += __shfl_xor_sync(0xffffffffu, pa[mt][1], off, 4);
        }
    }
    if (tq == 0){
#pragma unroll
        for (int mt = 0; mt < 4; mt++){
            atomicAdd(&sLog[warp_m + mt*16 + gid],     pa[mt][0]);
            atomicAdd(&sLog[warp_m + mt*16 + gid + 8], pa[mt][1]);
        }
    }
    __syncthreads();
    if (tid < 128 && e0 + tid < NE){
        float p = sLog[tid];
        g_logit[e0+tid] = (p > 0.f) ? p : 0.2f*p;
    }
}

// ---------------- edge encoder tail: per-edge part (FFMA, small) -------------
// dual-writes g_init_edge and g_edge_lat (removes prologue copy)
__global__ __launch_bounds__(256,2) void k_enc_edge(
    const float* __restrict__ ea,
    const int* __restrict__ row, const int* __restrict__ col,
    const float* __restrict__ encW1, const float* __restrict__ encb1,
    const float* __restrict__ encW2, const float* __restrict__ encb2)
{
    __shared__ float As[64*9];
    __shared__ float Bs[16*64];
    __shared__ float Hid[64*132];
    __shared__ int sR[64], sC[64];

    const int e0 = blockIdx.x*64;
    const int tid = threadIdx.x, ty = tid>>4, tx = tid&15;
    if (tid < 64){ sR[tid] = row[e0+tid]; sC[tid] = col[e0+tid]; }
    __syncthreads();

    float c[4][8];
#pragma unroll
    for (int i = 0; i < 4; i++){
        int r = ty*4+i;
#pragma unroll
        for (int j = 0; j < 8; j++){
            int n = tx + 16*j;
            c[i][j] = g_Penc[(size_t)sR[r]*256 + n]
                    + g_Penc[(size_t)sC[r]*256 + 128 + n]
                    + encb1[n];
        }
    }
    for (int t = tid; t < 512; t += 256){
        int el = t>>3, kk = t&7;
        As[el*9+kk] = ea[(e0+el)*RD + kk];
    }
    for (int t = tid; t < 1024; t += 256){
        int kk = t>>7, n = t&127;
        Bs[t] = encW1[(320+kk)*EH + n];
    }
    __syncthreads();
#pragma unroll
    for (int kk = 0; kk < 8; kk++){
        float a0 = As[(ty*4+0)*9+kk], a1 = As[(ty*4+1)*9+kk];
        float a2 = As[(ty*4+2)*9+kk], a3 = As[(ty*4+3)*9+kk];
#pragma unroll
        for (int j = 0; j < 8; j++){
            float b = Bs[kk*128 + tx + 16*j];
            c[0][j] += a0*b; c[1][j] += a1*b; c[2][j] += a2*b; c[3][j] += a3*b;
        }
    }
    __syncthreads();
#pragma unroll
    for (int i = 0; i < 4; i++)
#pragma unroll
        for (int j = 0; j < 8; j++){
            int n = tx + 16*j;
            Hid[(ty*4+i)*132 + n] = fmaxf(c[i][j], 0.f);
        }
    __syncthreads();

    float c2[4][4];
#pragma unroll
    for (int i = 0; i < 4; i++)
#pragma unroll
        for (int j = 0; j < 4; j++) c2[i][j] = encb2[tx+16*j];

    for (int kc = 0; kc < 128; kc += 16){
        for (int t = tid; t < 1024; t += 256){
            int kk = t>>6, n = t&63;
            Bs[t] = encW2[(kc+kk)*ED + n];
        }
        __syncthreads();
#pragma unroll
        for (int kk = 0; kk < 16; kk++){
            float a0 = Hid[(ty*4+0)*132 + kc+kk], a1 = Hid[(ty*4+1)*132 + kc+kk];
            float a2 = Hid[(ty*4+2)*132 + kc+kk], a3 = Hid[(ty*4+3)*132 + kc+kk];
#pragma unroll
            for (int j = 0; j < 4; j++){
                float b = Bs[kk*64 + tx + 16*j];
                c2[0][j] += a0*b; c2[1][j] += a1*b; c2[2][j] += a2*b; c2[3][j] += a3*b;
            }
        }
        __syncthreads();
    }
#pragma unroll
    for (int i = 0; i < 4; i++)
#pragma unroll
        for (int j = 0; j < 4; j++){
            size_t o = (size_t)(e0+ty*4+i)*ED + tx + 16*j;
            g_init_edge[o] = c2[i][j];
            g_edge_lat[o]  = c2[i][j];
        }
}

// ---------------- node update: 32 threads/node, 8 nodes/block ----------------
__global__ __launch_bounds__(256,2) void k_node(
    const float* __restrict__ x, const float* __restrict__ nW1,
    const float* __restrict__ nb1,
    const float* __restrict__ lg, const float* __restrict__ lb)
{
    __shared__ float agg[8*260];
    __shared__ float Bs[32*160];

    const int n0 = blockIdx.x*8;
    const int tid = threadIdx.x, g = tid>>5, t = tid&31;
    const int n = n0 + g;
    const int beg = g_rowptr[n], end = g_rowptr[n+1];

    float m = -1e30f;
    for (int i = beg+t; i < end; i += 32) m = fmaxf(m, g_logit[g_eids[i]]);
#pragma unroll
    for (int off = 16; off >= 1; off >>= 1) m = fmaxf(m, __shfl_xor_sync(0xffffffffu, m, off));

    float den = 0.f;
    for (int i = beg+t; i < end; i += 32) den += expf(g_logit[g_eids[i]] - m);
#pragma unroll
    for (int off = 16; off >= 1; off >>= 1) den += __shfl_xor_sync(0xffffffffu, den, off);
    den += 1e-16f;
    float inv_den = 1.f/den;

    float acc[8];
#pragma unroll
    for (int q = 0; q < 8; q++) acc[q] = 0.f;
    for (int i = beg; i < end; i++){
        int e = g_eids[i];
        float w = expf(g_logit[e] - m) * inv_den;
        const float* mr = g_msg + (size_t)e*HD;
#pragma unroll
        for (int q = 0; q < 8; q++) acc[q] += w * mr[t + 32*q];
    }
#pragma unroll
    for (int q = 0; q < 8; q++) agg[g*260 + t + 32*q] = acc[q];
    __syncthreads();

    float c[5];
#pragma unroll
    for (int j = 0; j < 5; j++) c[j] = 0.f;
    for (int kc = 0; kc < 256; kc += 32){
        for (int t2 = tid; t2 < 5120; t2 += 256){
            int kk = t2/160, nn = t2 - kk*160;
            Bs[t2] = nW1[(kc+kk)*ND + nn];
        }
        __syncthreads();
#pragma unroll 4
        for (int kk = 0; kk < 32; kk++){
            float a = agg[g*260 + kc+kk];
#pragma unroll
            for (int j = 0; j < 5; j++) c[j] += a * Bs[kk*160 + t + 32*j];
        }
        __syncthreads();
    }

    float rv[5], s = 0.f, s2 = 0.f;
#pragma unroll
    for (int j = 0; j < 5; j++){
        int cc = t + 32*j;
        float v = x[n*ND + cc] + c[j] + nb1[cc];
        rv[j] = v; s += v; s2 += v*v;
    }
#pragma unroll
    for (int off = 16; off >= 1; off >>= 1){
        s  += __shfl_xor_sync(0xffffffffu, s,  off);
        s2 += __shfl_xor_sync(0xffffffffu, s2, off);
    }
    float mu  = s * (1.f/ND);
    float var = s2 * (1.f/ND) - mu*mu;
    float inv = rsqrtf(var + 1e-5f);
#pragma unroll
    for (int j = 0; j < 5; j++){
        int cc = t + 32*j;
        g_node_lat[n*ND + cc] = (rv[j] - mu)*inv*lg[cc] + lb[cc];
    }
}

// ---------------- launch -----------------------------------------------------
extern "C" void kernel_launch(void* const* d_in, const int* in_sizes, int n_in,
                              void* d_out, int out_size)
{
    const float* x     = (const float*)d_in[0];
    const float* ea    = (const float*)d_in[1];
    const float* encW1 = (const float*)d_in[2];
    const float* encb1 = (const float*)d_in[3];
    const float* encW2 = (const float*)d_in[4];
    const float* encb2 = (const float*)d_in[5];
    const float* eW1   = (const float*)d_in[6];
    const float* eb1   = (const float*)d_in[7];
    const float* eW2   = (const float*)d_in[8];
    const float* eb2   = (const float*)d_in[9];
    const float* mW1   = (const float*)d_in[10];
    const float* mb1   = (const float*)d_in[11];
    const float* attv  = (const float*)d_in[12];
    const float* nW1   = (const float*)d_in[13];
    const float* nb1   = (const float*)d_in[14];
    const float* ln_ng = (const float*)d_in[15];
    const float* ln_nb = (const float*)d_in[16];
    const float* ln_eg = (const float*)d_in[17];
    const float* ln_eb = (const float*)d_in[18];
    const int*   erow  = (const int*)d_in[19];
    const int*   ecol  = (const int*)d_in[20];

    void *p_deg, *p_rowptr, *p_fill, *p_node, *p_edge, *p_init, *p_P, *p_Pbase, *p_Penc;
    void *p_WEh, *p_WEl, *p_WPh, *p_WPl;
    cudaGetSymbolAddress(&p_deg,    g_deg);
    cudaGetSymbolAddress(&p_rowptr, g_rowptr);
    cudaGetSymbolAddress(&p_fill,   g_fill);
    cudaGetSymbolAddress(&p_node,   g_node_lat);
    cudaGetSymbolAddress(&p_edge,   g_edge_lat);
    cudaGetSymbolAddress(&p_init,   g_init_edge);
    cudaGetSymbolAddress(&p_P,      g_P);
    cudaGetSymbolAddress(&p_Pbase,  g_Pbase);
    cudaGetSymbolAddress(&p_Penc,   g_Penc);
    cudaGetSymbolAddress(&p_WEh,    gWEh);
    cudaGetSymbolAddress(&p_WEl,    gWEl);
    cudaGetSymbolAddress(&p_WPh,    gWPh);
    cudaGetSymbolAddress(&p_WPl,    gWPl);

    cudaFuncSetAttribute(k_edge_tc, cudaFuncAttributeMaxDynamicSharedMemorySize, 153600);

    static cudaStream_t s1 = nullptr;
    static cudaEvent_t evA = nullptr, evB = nullptr;
    if (s1 == nullptr){
        cudaStreamCreateWithFlags(&s1, cudaStreamNonBlocking);
        cudaEventCreateWithFlags(&evA, cudaEventDisableTiming);
        cudaEventCreateWithFlags(&evB, cudaEventDisableTiming);
    }

    // fork: CSR build on s1, GEMM prologue on stream 0
    cudaEventRecord(evA, 0);
    cudaStreamWaitEvent(s1, evA, 0);

    cudaMemsetAsync(p_deg, 0, NN*sizeof(int), s1);
    k_hist<<<(NE+255)/256, 256, 0, s1>>>(erow);
    k_scan1<<<49, 256, 0, s1>>>();
    k_scan2<<<1, 32, 0, s1>>>();
    k_scan3<<<(NN+255)/256, 256, 0, s1>>>();
    cudaMemcpyAsync(p_fill, p_rowptr, NN*sizeof(int), cudaMemcpyDeviceToDevice, s1);
    k_scatter<<<(NE+255)/256, 256, 0, s1>>>(erow);

    k_prep<<<480, 256>>>(eW1, mW1, encW1, eW2);
    {
        dim3 g((NN+127)/128, 6);
        k_gemm_bf<<<g, 256>>>(x, x, (const uint32_t*)p_WPh, (const uint32_t*)p_WPl,
                              160, 160, (float*)p_Pbase, 768, nullptr);
    }
    {
        dim3 g((NN+127)/128, 2);
        k_gemm_bf<<<g, 256>>>(x, x, (const uint32_t*)p_WEh, (const uint32_t*)p_WEl,
                              160, 80, (float*)p_Penc, 256, nullptr);
    }
    k_enc_edge<<<NE/64, 256>>>(ea, erow, ecol, encW1, encb1, encW2, encb2);

    cudaMemcpyAsync(p_node, x, (size_t)NN*ND*sizeof(float), cudaMemcpyDeviceToDevice, 0);

    cudaEventRecord(evB, s1);
    cudaStreamWaitEvent(0, evB, 0);

    for (int it = 0; it < 3; it++){
        dim3 g((NN+127)/128, 6);
        k_gemm_bf<<<g, 256>>>((const float*)p_node, (const float*)p_node,
                              (const uint32_t*)p_WPh + 80, (const uint32_t*)p_WPl + 80,
                              160, 160, (float*)p_P, 768, (const float*)p_Pbase);
        k_edge_tc<<<(NE+127)/128, 512, 153600>>>(erow, ecol, eb1, eb2, mb1, attv, ln_eg, ln_eb);
        k_node<<<NN/8, 256>>>(x, nW1, nb1, ln_ng, ln_nb);
    }

    float* out = (float*)d_out;
    if (out_size >= NN*ND + NE*ED){
        cudaMemcpyAsync(out,         p_node, (size_t)NN*ND*sizeof(float), cudaMemcpyDeviceToDevice, 0);
        cudaMemcpyAsync(out + NN*ND, p_edge, (size_t)NE*ED*sizeof(float), cudaMemcpyDeviceToDevice, 0);
    } else if (out_size == NN*ND){
        cudaMemcpyAsync(out, p_node, (size_t)NN*ND*sizeof(float), cudaMemcpyDeviceToDevice, 0);
    } else {
        size_t nel = (size_t)((out_size < NE*ED) ? out_size : NE*ED);
        cudaMemcpyAsync(out, p_edge, nel*sizeof(float), cudaMemcpyDeviceToDevice, 0);
    }
}

// round 13
// speedup vs baseline: 1.0179x; 1.0179x over previous
#include <cuda_runtime.h>
#include <cuda_bf16.h>
#include <math.h>
#include <stdint.h>

#define NN 50000
#define NE 200000
#define ND 160
#define ED 64
#define RD 8
#define HD 256
#define EH 128

// ---------------- scratch (device globals; no runtime allocation) ----------
__device__ float g_init_edge[NE*ED];
__device__ float g_edge_lat [NE*ED];
__device__ float g_node_lat [NN*ND];
__device__ float g_msg      [NE*HD];
__device__ float g_logit    [NE];
__device__ float g_P        [(size_t)NN*768];
__device__ float g_Pbase    [(size_t)NN*768];
__device__ float g_Penc     [(size_t)NN*256];
__device__ uint32_t gWPh[768*160], gWPl[768*160];
__device__ uint32_t gWEh[256*80],  gWEl[256*80];
__device__ uint32_t gB1h[256*64],  gB1l[256*64];
__device__ uint32_t gB2h[64*128],  gB2l[64*128];
__device__ uint32_t gB3h[256*32],  gB3l[256*32];
__device__ uint32_t gXh[(size_t)NN*80],  gXl[(size_t)NN*80];   // packed x
__device__ uint32_t gNLh[(size_t)NN*80], gNLl[(size_t)NN*80];  // packed node_lat
__device__ int   g_deg      [NN];
__device__ int   g_rowptr   [NN+1];
__device__ int   g_fill     [NN];
__device__ int   g_eids     [NE];
__device__ int   g_part     [64];

// ---------------- helpers ----------------------------------------------------
__device__ __forceinline__ void split2(float x, float y, uint32_t& hi, uint32_t& lo){
    __nv_bfloat162 h = __floats2bfloat162_rn(x, y);
    hi = *(uint32_t*)&h;
    float rx = x - __bfloat162float(h.x);
    float ry = y - __bfloat162float(h.y);
    __nv_bfloat162 l = __floats2bfloat162_rn(rx, ry);
    lo = *(uint32_t*)&l;
}
__device__ __forceinline__ void mma_bf16(
    float& c0, float& c1, float& c2, float& c3,
    uint32_t a0, uint32_t a1, uint32_t a2, uint32_t a3, uint32_t b0, uint32_t b1)
{
    asm volatile(
        "mma.sync.aligned.m16n8k16.row.col.f32.bf16.bf16.f32 "
        "{%0,%1,%2,%3}, {%4,%5,%6,%7}, {%8,%9}, {%0,%1,%2,%3};"
        : "+f"(c0), "+f"(c1), "+f"(c2), "+f"(c3)
        : "r"(a0), "r"(a1), "r"(a2), "r"(a3), "r"(b0), "r"(b1));
}
__device__ __forceinline__ void ldsm_x4(uint32_t& r0, uint32_t& r1, uint32_t& r2, uint32_t& r3, uint32_t a){
    asm volatile("ldmatrix.sync.aligned.m8n8.x4.shared.b16 {%0,%1,%2,%3}, [%4];"
        : "=r"(r0), "=r"(r1), "=r"(r2), "=r"(r3) : "r"(a));
}

// ---------------- CSR build --------------------------------------------------
__global__ void k_hist(const int* __restrict__ row){
    int e = blockIdx.x*blockDim.x + threadIdx.x;
    if (e < NE) atomicAdd(&g_deg[row[e]], 1);
}

__global__ void k_scan1(){
    __shared__ int ss[256];
    int b = blockIdx.x, base = b*1024, tid = threadIdx.x;
    int v[4], tsum = 0;
#pragma unroll
    for (int r = 0; r < 4; r++){
        int idx = base + tid*4 + r;
        v[r] = (idx < NN) ? g_deg[idx] : 0;
        tsum += v[r];
    }
    ss[tid] = tsum; __syncthreads();
    for (int off = 1; off < 256; off <<= 1){
        int add = (tid >= off) ? ss[tid-off] : 0;
        __syncthreads();
        ss[tid] += add;
        __syncthreads();
    }
    int run = ss[tid] - tsum;
#pragma unroll
    for (int r = 0; r < 4; r++){
        int idx = base + tid*4 + r;
        if (idx < NN) g_rowptr[idx] = run;
        run += v[r];
    }
    if (tid == 255) g_part[b] = ss[255];
}

__global__ void k_scan2(){
    if (threadIdx.x == 0){
        int run = 0;
        for (int i = 0; i < 49; i++){ int t = g_part[i]; g_part[i] = run; run += t; }
    }
}

__global__ void k_scan3(){
    int i = blockIdx.x*blockDim.x + threadIdx.x;
    if (i < NN) g_rowptr[i] += g_part[i >> 10];
    if (i == 0) g_rowptr[NN] = NE;
}

__global__ void k_scatter(const int* __restrict__ row){
    int e = blockIdx.x*blockDim.x + threadIdx.x;
    if (e < NE){
        int p = atomicAdd(&g_fill[row[e]], 1);
        g_eids[p] = e;
    }
}

// ---------------- pack weight tables (bf16 hi/lo, K-major) -------------------
__global__ void k_prep(const float* __restrict__ eW1, const float* __restrict__ mW1,
                       const float* __restrict__ encW1, const float* __restrict__ eW2)
{
    int i = blockIdx.x*blockDim.x + threadIdx.x;
    if (i < 768*160){
        int n = i/160, w = i - n*160, k = w*2;
        float f0, f1;
        if (n < 256){ f0 = eW1[k*256+n]; f1 = eW1[(k+1)*256+n]; }
        else if (n < 512){ int nn = n-256; f0 = eW1[(320+k)*256+nn]; f1 = eW1[(321+k)*256+nn]; }
        else { int nn = n-512; f0 = mW1[k*256+nn]; f1 = mW1[(k+1)*256+nn]; }
        split2(f0, f1, gWPh[i], gWPl[i]);
    }
    if (i < 256*80){
        int n = i/80, w = i - n*80, k = w*2;
        float f0, f1;
        if (n < 128){ f0 = encW1[k*128+n]; f1 = encW1[(k+1)*128+n]; }
        else { int nn = n-128; f0 = encW1[(160+k)*128+nn]; f1 = encW1[(161+k)*128+nn]; }
        split2(f0, f1, gWEh[i], gWEl[i]);
    }
    if (i < 256*64){
        int n = i/64, w = i - n*64, k = w*2;
        split2(eW1[(640+k)*256+n], eW1[(641+k)*256+n], gB1h[i], gB1l[i]);
    }
    if (i < 64*128){
        int n = i/128, w = i - n*128, k = w*2;
        split2(eW2[k*64+n], eW2[(k+1)*64+n], gB2h[i], gB2l[i]);
    }
    if (i < 256*32){
        int n = i/32, w = i - n*32, k = w*2;
        split2(mW1[(320+k)*256+n], mW1[(321+k)*256+n], gB3h[i], gB3l[i]);
    }
}

// ---------------- pack a [NN,160] fp32 matrix into bf16 hi/lo [NN,80] --------
__global__ void k_packA(const float* __restrict__ src,
                        uint32_t* __restrict__ dh, uint32_t* __restrict__ dl)
{
    int i = blockIdx.x*blockDim.x + threadIdx.x;
    if (i < NN*80){
        int n = i/80, w = i - n*80;
        float2 v = *(const float2*)&src[(size_t)n*ND + 2*w];
        split2(v.x, v.y, dh[i], dl[i]);
    }
}

// ---------------- bf16 3-split dense GEMM (m16n8k16), packed A ---------------
// out[m, n0+n] = (base?base:0) + sum_k A[m,k]*B[n0+n,k].  A packed [NN,80] u32.
__global__ __launch_bounds__(256,2) void k_gemm_bf(
    const uint32_t* __restrict__ Ah_, const uint32_t* __restrict__ Al_,
    const uint32_t* __restrict__ Bh, const uint32_t* __restrict__ Bl,
    int K, int bstrW,
    float* __restrict__ out, int ostride, const float* __restrict__ base)
{
    __shared__ uint32_t sAh[128*20], sAl[128*20], sBh[128*20], sBl[128*20];
    const int tid = threadIdx.x, wid = tid>>5, lane = tid&31;
    const int gid = lane>>2, tq = lane&3;
    const int warp_m = (wid & 1)*64, warp_n = (wid >> 1)*32;
    const int m0 = blockIdx.x*128, n0 = blockIdx.y*128;

    float c[4][4][4];
#pragma unroll
    for (int i = 0; i < 4; i++)
#pragma unroll
        for (int j = 0; j < 4; j++)
#pragma unroll
            for (int r = 0; r < 4; r++) c[i][j][r] = 0.f;

    const int nk = K >> 5;
    for (int ch = 0; ch < nk; ch++){
        const int kc2 = ch*16;    // word offset into packed rows
#pragma unroll
        for (int p = 0; p < 2; p++){
            int lin = tid + p*256;
            int row = lin>>2, q = lin&3;
            int gm = m0 + row;
            uint4 vh = make_uint4(0u,0u,0u,0u), vl = make_uint4(0u,0u,0u,0u);
            if (gm < NN){
                size_t g = (size_t)gm*80 + kc2 + q*4;
                vh = *(const uint4*)&Ah_[g];
                vl = *(const uint4*)&Al_[g];
            }
            *(uint4*)&sAh[row*20 + q*4] = vh;
            *(uint4*)&sAl[row*20 + q*4] = vl;
        }
#pragma unroll
        for (int p = 0; p < 2; p++){
            int lin = tid + p*256;
            int row = lin>>2, q = lin&3;
            size_t gofs = (size_t)(n0+row)*bstrW + kc2 + q*4;
            *(uint4*)&sBh[row*20 + q*4] = *(const uint4*)&Bh[gofs];
            *(uint4*)&sBl[row*20 + q*4] = *(const uint4*)&Bl[gofs];
        }
        __syncthreads();
#pragma unroll
        for (int s = 0; s < 2; s++){
            const int kb = s*8 + tq;
            uint32_t bh0[4], bh1[4], bl0[4], bl1[4];
#pragma unroll
            for (int nt = 0; nt < 4; nt++){
                int nr = warp_n + nt*8 + gid;
                bh0[nt] = sBh[nr*20 + kb]; bh1[nt] = sBh[nr*20 + kb + 4];
                bl0[nt] = sBl[nr*20 + kb]; bl1[nt] = sBl[nr*20 + kb + 4];
            }
#pragma unroll
            for (int mt = 0; mt < 4; mt++){
                int ar = warp_m + mt*16 + gid;
                uint32_t ah0 = sAh[ar*20+kb],     ah1 = sAh[(ar+8)*20+kb];
                uint32_t ah2 = sAh[ar*20+kb+4],   ah3 = sAh[(ar+8)*20+kb+4];
                uint32_t al0 = sAl[ar*20+kb],     al1 = sAl[(ar+8)*20+kb];
                uint32_t al2 = sAl[ar*20+kb+4],   al3 = sAl[(ar+8)*20+kb+4];
#pragma unroll
                for (int nt = 0; nt < 4; nt++){
                    mma_bf16(c[mt][nt][0], c[mt][nt][1], c[mt][nt][2], c[mt][nt][3],
                             ah0, ah1, ah2, ah3, bh0[nt], bh1[nt]);
                    mma_bf16(c[mt][nt][0], c[mt][nt][1], c[mt][nt][2], c[mt][nt][3],
                             ah0, ah1, ah2, ah3, bl0[nt], bl1[nt]);
                    mma_bf16(c[mt][nt][0], c[mt][nt][1], c[mt][nt][2], c[mt][nt][3],
                             al0, al1, al2, al3, bh0[nt], bh1[nt]);
                }
            }
        }
        __syncthreads();
    }

#pragma unroll
    for (int mt = 0; mt < 4; mt++){
        int r0 = m0 + warp_m + mt*16 + gid;
        int r1 = r0 + 8;
#pragma unroll
        for (int nt = 0; nt < 4; nt++){
            int gn = n0 + warp_n + nt*8 + tq*2;
            if (r0 < NN){
                float2 v = make_float2(c[mt][nt][0], c[mt][nt][1]);
                if (base){ float2 b = *(const float2*)&base[(size_t)r0*ostride + gn]; v.x += b.x; v.y += b.y; }
                *(float2*)&out[(size_t)r0*ostride + gn] = v;
            }
            if (r1 < NN){
                float2 v = make_float2(c[mt][nt][2], c[mt][nt][3]);
                if (base){ float2 b = *(const float2*)&base[(size_t)r1*ostride + gn]; v.x += b.x; v.y += b.y; }
                *(float2*)&out[(size_t)r1*ostride + gn] = v;
            }
        }
    }
}

// ---------------- fused edge kernel: ldmatrix A-operands (round-11) ----------
__global__ __launch_bounds__(512,1) void k_edge_tc(
    const int* __restrict__ row, const int* __restrict__ col,
    const float* __restrict__ eb1, const float* __restrict__ eb2,
    const float* __restrict__ mb1, const float* __restrict__ attv,
    const float* __restrict__ lgE, const float* __restrict__ lbE)
{
    extern __shared__ uint32_t esm[];
    uint32_t* Ah  = esm;              // [128][68]
    uint32_t* Al  = esm + 8704;
    uint32_t* B1h = esm + 17408;      // [256][20]
    uint32_t* B1l = esm + 22528;
    uint32_t* Hh  = esm;              // [128][132] overlay (phase2)
    uint32_t* Hl  = esm + 16896;
    uint32_t* B2h = esm + 33792;      // [64][36]
    uint32_t* B2l = esm + 36096;
    uint32_t* NEh = esm;              // [128][36] overlay
    uint32_t* NEl = esm + 4608;
    uint32_t* B3h = esm + 9216;       // [256][36]
    uint32_t* B3l = esm + 18432;
    __shared__ int sR[128], sC[128];
    __shared__ float sAtt[256];
    __shared__ float sLog[128];
    __shared__ float sSum[128], sSq[128], sMu[128], sInv[128];

    const int tid = threadIdx.x, wid = tid>>5, lane = tid&31;
    const int gid = lane>>2, tq = lane&3;
    const int warp_m  = (wid & 1)*64;
    const int warp_n  = (wid >> 1)*32;
    const int warp_n2 = (wid >> 1)*8;
    const int e0 = blockIdx.x*128;

    const int lrow = lane & 15;
    const int lkh  = (lane >> 4) << 2;
    const uint32_t aAh = (uint32_t)__cvta_generic_to_shared(Ah);
    const uint32_t aAl = (uint32_t)__cvta_generic_to_shared(Al);
    const uint32_t aHh = (uint32_t)__cvta_generic_to_shared(Hh);
    const uint32_t aHl = (uint32_t)__cvta_generic_to_shared(Hl);
    const uint32_t aNh = (uint32_t)__cvta_generic_to_shared(NEh);
    const uint32_t aNl = (uint32_t)__cvta_generic_to_shared(NEl);
    uint32_t offA[4], offH[4], offN[4];
#pragma unroll
    for (int mt = 0; mt < 4; mt++){
        int r = warp_m + mt*16 + lrow;
        offA[mt] = (uint32_t)((r*68  + lkh) * 4);
        offH[mt] = (uint32_t)((r*132 + lkh) * 4);
        offN[mt] = (uint32_t)((r*36  + lkh) * 4);
    }

    if (tid < 128){
        int ge = e0 + tid;
        sR[tid] = (ge < NE) ? row[ge] : 0;
        sC[tid] = (ge < NE) ? col[ge] : 0;
        sLog[tid] = 0.f; sSum[tid] = 0.f; sSq[tid] = 0.f;
    }
    if (tid < 256) sAtt[tid] = attv[tid];
    __syncthreads();

    // ---- phase 1: stage A + C init from P gathers ---------------------------
    for (int lin = tid; lin < 8192; lin += 512){
        int r = lin>>6, w = lin&63, k = w*2;
        float2 v = make_float2(0.f, 0.f);
        if (e0 + r < NE)
            v = (k < 64) ? *(const float2*)&g_init_edge[(size_t)(e0+r)*ED + k]
                         : *(const float2*)&g_edge_lat [(size_t)(e0+r)*ED + (k-64)];
        split2(v.x, v.y, Ah[r*68+w], Al[r*68+w]);
    }
    float c1[4][4][4];
#pragma unroll
    for (int mt = 0; mt < 4; mt++){
        int rA = warp_m + mt*16 + gid, rB = rA + 8;
        size_t prA = (size_t)sR[rA]*768, pcA = (size_t)sC[rA]*768;
        size_t prB = (size_t)sR[rB]*768, pcB = (size_t)sC[rB]*768;
#pragma unroll
        for (int nt = 0; nt < 4; nt++){
            int cn = warp_n + nt*8 + tq*2;
            float2 b  = *(const float2*)&eb1[cn];
            float2 a1 = *(const float2*)&g_P[prA + cn];
            float2 a2 = *(const float2*)&g_P[pcA + 256 + cn];
            float2 a3 = *(const float2*)&g_P[prB + cn];
            float2 a4 = *(const float2*)&g_P[pcB + 256 + cn];
            c1[mt][nt][0] = a1.x + a2.x + b.x;
            c1[mt][nt][1] = a1.y + a2.y + b.y;
            c1[mt][nt][2] = a3.x + a4.x + b.x;
            c1[mt][nt][3] = a3.y + a4.y + b.y;
        }
    }
    __syncthreads();

#pragma unroll
    for (int ch = 0; ch < 4; ch++){
        for (int lin = tid; lin < 1024; lin += 512){
            int r = lin>>2, q = lin&3;
            size_t gofs = (size_t)r*64 + ch*16 + q*4;
            *(uint4*)&B1h[r*20 + q*4] = *(const uint4*)&gB1h[gofs];
            *(uint4*)&B1l[r*20 + q*4] = *(const uint4*)&gB1l[gofs];
        }
        __syncthreads();
#pragma unroll
        for (int s = 0; s < 2; s++){
            int kb = s*8 + tq;
            uint32_t kw = (uint32_t)((ch*16 + s*8) * 4);
            uint32_t bh0[4], bh1[4], bl0[4], bl1[4];
#pragma unroll
            for (int nt = 0; nt < 4; nt++){
                int nr = warp_n + nt*8 + gid;
                bh0[nt] = B1h[nr*20+kb]; bh1[nt] = B1h[nr*20+kb+4];
                bl0[nt] = B1l[nr*20+kb]; bl1[nt] = B1l[nr*20+kb+4];
            }
#pragma unroll
            for (int mt = 0; mt < 4; mt++){
                uint32_t ah0,ah1,ah2,ah3, al0,al1,al2,al3;
                ldsm_x4(ah0,ah1,ah2,ah3, aAh + offA[mt] + kw);
                ldsm_x4(al0,al1,al2,al3, aAl + offA[mt] + kw);
#pragma unroll
                for (int nt = 0; nt < 4; nt++){
                    mma_bf16(c1[mt][nt][0],c1[mt][nt][1],c1[mt][nt][2],c1[mt][nt][3],
                             ah0,ah1,ah2,ah3, bh0[nt],bh1[nt]);
                    mma_bf16(c1[mt][nt][0],c1[mt][nt][1],c1[mt][nt][2],c1[mt][nt][3],
                             ah0,ah1,ah2,ah3, bl0[nt],bl1[nt]);
                    mma_bf16(c1[mt][nt][0],c1[mt][nt][1],c1[mt][nt][2],c1[mt][nt][3],
                             al0,al1,al2,al3, bh0[nt],bh1[nt]);
                }
            }
        }
        __syncthreads();
    }

    // write hidden (relu, bf16 split) over A/B1 region
#pragma unroll
    for (int mt = 0; mt < 4; mt++){
        int rA = warp_m + mt*16 + gid, rB = rA + 8;
#pragma unroll
        for (int nt = 0; nt < 4; nt++){
            int wcol = (warp_n>>1) + nt*4 + tq;
            float v0 = fmaxf(c1[mt][nt][0], 0.f), v1 = fmaxf(c1[mt][nt][1], 0.f);
            float v2 = fmaxf(c1[mt][nt][2], 0.f), v3 = fmaxf(c1[mt][nt][3], 0.f);
            split2(v0, v1, Hh[rA*132+wcol], Hl[rA*132+wcol]);
            split2(v2, v3, Hh[rB*132+wcol], Hl[rB*132+wcol]);
        }
    }
    __syncthreads();

    // ---- phase 2 ------------------------------------------------------------
    float c2[4][4];
#pragma unroll
    for (int mt = 0; mt < 4; mt++){
        float2 b = *(const float2*)&eb2[warp_n2 + tq*2];
        c2[mt][0] = b.x; c2[mt][1] = b.y; c2[mt][2] = b.x; c2[mt][3] = b.y;
    }
#pragma unroll
    for (int ch = 0; ch < 4; ch++){
        {
            int r = tid>>3, q = tid&7;
            size_t gofs = (size_t)r*128 + ch*32 + q*4;
            *(uint4*)&B2h[r*36 + q*4] = *(const uint4*)&gB2h[gofs];
            *(uint4*)&B2l[r*36 + q*4] = *(const uint4*)&gB2l[gofs];
        }
        __syncthreads();
#pragma unroll
        for (int s = 0; s < 4; s++){
            int kb = s*8 + tq;
            uint32_t kw = (uint32_t)((ch*32 + s*8) * 4);
            int nr = warp_n2 + gid;
            uint32_t bh0 = B2h[nr*36+kb], bh1 = B2h[nr*36+kb+4];
            uint32_t bl0 = B2l[nr*36+kb], bl1 = B2l[nr*36+kb+4];
#pragma unroll
            for (int mt = 0; mt < 4; mt++){
                uint32_t ah0,ah1,ah2,ah3, al0,al1,al2,al3;
                ldsm_x4(ah0,ah1,ah2,ah3, aHh + offH[mt] + kw);
                ldsm_x4(al0,al1,al2,al3, aHl + offH[mt] + kw);
                mma_bf16(c2[mt][0],c2[mt][1],c2[mt][2],c2[mt][3], ah0,ah1,ah2,ah3, bh0,bh1);
                mma_bf16(c2[mt][0],c2[mt][1],c2[mt][2],c2[mt][3], ah0,ah1,ah2,ah3, bl0,bl1);
                mma_bf16(c2[mt][0],c2[mt][1],c2[mt][2],c2[mt][3], al0,al1,al2,al3, bh0,bh1);
            }
        }
        __syncthreads();
    }

    // ---- NE pack + LN stats; stage full B3 (stride 36) -----------------------
#pragma unroll
    for (int mt = 0; mt < 4; mt++){
        int rA = warp_m + mt*16 + gid, rB = rA + 8;
        int cn = warp_n2 + tq*2;
        int wcol = (warp_n2>>1) + tq;
        split2(c2[mt][0], c2[mt][1], NEh[rA*36+wcol], NEl[rA*36+wcol]);
        split2(c2[mt][2], c2[mt][3], NEh[rB*36+wcol], NEl[rB*36+wcol]);
        float2 iA = make_float2(0.f,0.f), iB = make_float2(0.f,0.f);
        if (e0 + rA < NE) iA = *(const float2*)&g_init_edge[(size_t)(e0+rA)*ED + cn];
        if (e0 + rB < NE) iB = *(const float2*)&g_init_edge[(size_t)(e0+rB)*ED + cn];
        c2[mt][0] += iA.x; c2[mt][1] += iA.y;
        c2[mt][2] += iB.x; c2[mt][3] += iB.y;
        atomicAdd(&sSum[rA], c2[mt][0] + c2[mt][1]);
        atomicAdd(&sSq [rA], c2[mt][0]*c2[mt][0] + c2[mt][1]*c2[mt][1]);
        atomicAdd(&sSum[rB], c2[mt][2] + c2[mt][3]);
        atomicAdd(&sSq [rB], c2[mt][2]*c2[mt][2] + c2[mt][3]*c2[mt][3]);
    }
    for (int lin = tid; lin < 2048; lin += 512){
        int r = lin>>3, q = lin&7;
        size_t gofs = (size_t)r*32 + q*4;
        *(uint4*)&B3h[r*36 + q*4] = *(const uint4*)&gB3h[gofs];
        *(uint4*)&B3l[r*36 + q*4] = *(const uint4*)&gB3l[gofs];
    }
    float c3[4][4][4];
#pragma unroll
    for (int mt = 0; mt < 4; mt++){
        int rA = warp_m + mt*16 + gid, rB = rA + 8;
        size_t pcA = (size_t)sC[rA]*768, pcB = (size_t)sC[rB]*768;
#pragma unroll
        for (int nt = 0; nt < 4; nt++){
            int cn = warp_n + nt*8 + tq*2;
            float2 b  = *(const float2*)&mb1[cn];
            float2 a1 = *(const float2*)&g_P[pcA + 512 + cn];
            float2 a2 = *(const float2*)&g_P[pcB + 512 + cn];
            c3[mt][nt][0] = a1.x + b.x; c3[mt][nt][1] = a1.y + b.y;
            c3[mt][nt][2] = a2.x + b.x; c3[mt][nt][3] = a2.y + b.y;
        }
    }
    __syncthreads();

    if (tid < 128){
        float mu = sSum[tid] * (1.f/ED);
        float var = sSq[tid] * (1.f/ED) - mu*mu;
        sMu[tid] = mu;
        sInv[tid] = rsqrtf(var + 1e-5f);
    }
    __syncthreads();

#pragma unroll
    for (int mt = 0; mt < 4; mt++){
        int rA = warp_m + mt*16 + gid, rB = rA + 8;
        int cn = warp_n2 + tq*2;
        float g0 = lgE[cn], g1 = lgE[cn+1], b0 = lbE[cn], b1 = lbE[cn+1];
        if (e0 + rA < NE){
            float mu = sMu[rA], inv = sInv[rA];
            *(float2*)&g_edge_lat[(size_t)(e0+rA)*ED + cn] =
                make_float2((c2[mt][0]-mu)*inv*g0 + b0, (c2[mt][1]-mu)*inv*g1 + b1);
        }
        if (e0 + rB < NE){
            float mu = sMu[rB], inv = sInv[rB];
            *(float2*)&g_edge_lat[(size_t)(e0+rB)*ED + cn] =
                make_float2((c2[mt][2]-mu)*inv*g0 + b0, (c2[mt][3]-mu)*inv*g1 + b1);
        }
    }

    // ---- phase 3 MMA loop ----------------------------------------------------
#pragma unroll
    for (int s = 0; s < 4; s++){
        int ka = s*8 + tq;
        uint32_t kw = (uint32_t)((s*8) * 4);
        uint32_t bh0[4], bh1[4], bl0[4], bl1[4];
#pragma unroll
        for (int nt = 0; nt < 4; nt++){
            int nr = warp_n + nt*8 + gid;
            bh0[nt] = B3h[nr*36+ka]; bh1[nt] = B3h[nr*36+ka+4];
            bl0[nt] = B3l[nr*36+ka]; bl1[nt] = B3l[nr*36+ka+4];
        }
#pragma unroll
        for (int mt = 0; mt < 4; mt++){
            uint32_t ah0,ah1,ah2,ah3, al0,al1,al2,al3;
            ldsm_x4(ah0,ah1,ah2,ah3, aNh + offN[mt] + kw);
            ldsm_x4(al0,al1,al2,al3, aNl + offN[mt] + kw);
#pragma unroll
            for (int nt = 0; nt < 4; nt++){
                mma_bf16(c3[mt][nt][0],c3[mt][nt][1],c3[mt][nt][2],c3[mt][nt][3],
                         ah0,ah1,ah2,ah3, bh0[nt],bh1[nt]);
                mma_bf16(c3[mt][nt][0],c3[mt][nt][1],c3[mt][nt][2],c3[mt][nt][3],
                         ah0,ah1,ah2,ah3, bl0[nt],bl1[nt]);
                mma_bf16(c3[mt][nt][0],c3[mt][nt][1],c3[mt][nt][2],c3[mt][nt][3],
                         al0,al1,al2,al3, bh0[nt],bh1[nt]);
            }
        }
    }

    // epilogue: relu -> g_msg, attention partial dot, logit
    float pa[4][2];
#pragma unroll
    for (int mt = 0; mt < 4; mt++){ pa[mt][0] = 0.f; pa[mt][1] = 0.f; }
#pragma unroll
    for (int mt = 0; mt < 4; mt++){
        int rA = warp_m + mt*16 + gid, rB = rA + 8;
#pragma unroll
        for (int nt = 0; nt < 4; nt++){
            int cn = warp_n + nt*8 + tq*2;
            float av0 = sAtt[cn], av1 = sAtt[cn+1];
            float v0 = fmaxf(c3[mt][nt][0], 0.f), v1 = fmaxf(c3[mt][nt][1], 0.f);
            float v2 = fmaxf(c3[mt][nt][2], 0.f), v3 = fmaxf(c3[mt][nt][3], 0.f);
            if (e0 + rA < NE)
                *(float2*)&g_msg[(size_t)(e0+rA)*HD + cn] = make_float2(v0, v1);
            if (e0 + rB < NE)
                *(float2*)&g_msg[(size_t)(e0+rB)*HD + cn] = make_float2(v2, v3);
            pa[mt][0] += v0*av0 + v1*av1;
            pa[mt][1] += v2*av0 + v3*av1;
        }
    }
#pragma unroll
    for (int off = 1; off <= 2; off <<= 1){
#pragma unroll
        for (int mt = 0; mt < 4; mt++){
            pa[mt][0] += __shfl_xor_sync(0xffffffffu, pa[mt][0], off, 4);
            pa[mt][1] += __shfl_xor_sync(0xffffffffu, pa[mt][1], off, 4);
        }
    }
    if (tq == 0){
#pragma unroll
        for (int mt = 0; mt < 4; mt++){
            atomicAdd(&sLog[warp_m + mt*16 + gid],     pa[mt][0]);
            atomicAdd(&sLog[warp_m + mt*16 + gid + 8], pa[mt][1]);
        }
    }
    __syncthreads();
    if (tid < 128 && e0 + tid < NE){
        float p = sLog[tid];
        g_logit[e0+tid] = (p > 0.f) ? p : 0.2f*p;
    }
}

// ---------------- edge encoder tail (dual-writes init_edge + edge_lat) -------
__global__ __launch_bounds__(256,2) void k_enc_edge(
    const float* __restrict__ ea,
    const int* __restrict__ row, const int* __restrict__ col,
    const float* __restrict__ encW1, const float* __restrict__ encb1,
    const float* __restrict__ encW2, const float* __restrict__ encb2)
{
    __shared__ float As[64*9];
    __shared__ float Bs[16*64];
    __shared__ float Hid[64*132];
    __shared__ int sR[64], sC[64];

    const int e0 = blockIdx.x*64;
    const int tid = threadIdx.x, ty = tid>>4, tx = tid&15;
    if (tid < 64){ sR[tid] = row[e0+tid]; sC[tid] = col[e0+tid]; }
    __syncthreads();

    float c[4][8];
#pragma unroll
    for (int i = 0; i < 4; i++){
        int r = ty*4+i;
#pragma unroll
        for (int j = 0; j < 8; j++){
            int n = tx + 16*j;
            c[i][j] = g_Penc[(size_t)sR[r]*256 + n]
                    + g_Penc[(size_t)sC[r]*256 + 128 + n]
                    + encb1[n];
        }
    }
    for (int t = tid; t < 512; t += 256){
        int el = t>>3, kk = t&7;
        As[el*9+kk] = ea[(e0+el)*RD + kk];
    }
    for (int t = tid; t < 1024; t += 256){
        int kk = t>>7, n = t&127;
        Bs[t] = encW1[(320+kk)*EH + n];
    }
    __syncthreads();
#pragma unroll
    for (int kk = 0; kk < 8; kk++){
        float a0 = As[(ty*4+0)*9+kk], a1 = As[(ty*4+1)*9+kk];
        float a2 = As[(ty*4+2)*9+kk], a3 = As[(ty*4+3)*9+kk];
#pragma unroll
        for (int j = 0; j < 8; j++){
            float b = Bs[kk*128 + tx + 16*j];
            c[0][j] += a0*b; c[1][j] += a1*b; c[2][j] += a2*b; c[3][j] += a3*b;
        }
    }
    __syncthreads();
#pragma unroll
    for (int i = 0; i < 4; i++)
#pragma unroll
        for (int j = 0; j < 8; j++){
            int n = tx + 16*j;
            Hid[(ty*4+i)*132 + n] = fmaxf(c[i][j], 0.f);
        }
    __syncthreads();

    float c2[4][4];
#pragma unroll
    for (int i = 0; i < 4; i++)
#pragma unroll
        for (int j = 0; j < 4; j++) c2[i][j] = encb2[tx+16*j];

    for (int kc = 0; kc < 128; kc += 16){
        for (int t = tid; t < 1024; t += 256){
            int kk = t>>6, n = t&63;
            Bs[t] = encW2[(kc+kk)*ED + n];
        }
        __syncthreads();
#pragma unroll
        for (int kk = 0; kk < 16; kk++){
            float a0 = Hid[(ty*4+0)*132 + kc+kk], a1 = Hid[(ty*4+1)*132 + kc+kk];
            float a2 = Hid[(ty*4+2)*132 + kc+kk], a3 = Hid[(ty*4+3)*132 + kc+kk];
#pragma unroll
            for (int j = 0; j < 4; j++){
                float b = Bs[kk*64 + tx + 16*j];
                c2[0][j] += a0*b; c2[1][j] += a1*b; c2[2][j] += a2*b; c2[3][j] += a3*b;
            }
        }
        __syncthreads();
    }
#pragma unroll
    for (int i = 0; i < 4; i++)
#pragma unroll
        for (int j = 0; j < 4; j++){
            size_t o = (size_t)(e0+ty*4+i)*ED + tx + 16*j;
            g_init_edge[o] = c2[i][j];
            g_edge_lat[o]  = c2[i][j];
        }
}

// ---------------- node update (round-11: 16 threads/node, 16 nodes/block) ----
__global__ __launch_bounds__(256,1) void k_node(
    const float* __restrict__ x, const float* __restrict__ nW1,
    const float* __restrict__ nb1,
    const float* __restrict__ lg, const float* __restrict__ lb)
{
    __shared__ float agg[16*260];
    __shared__ float Bs[32*160];

    const int n0 = blockIdx.x*16;
    const int tid = threadIdx.x, g = tid>>4, t = tid&15;
    const int n = n0 + g;
    const int beg = g_rowptr[n], end = g_rowptr[n+1];

    float m = -1e30f;
    for (int i = beg+t; i < end; i += 16) m = fmaxf(m, g_logit[g_eids[i]]);
#pragma unroll
    for (int off = 8; off >= 1; off >>= 1) m = fmaxf(m, __shfl_xor_sync(0xffffffffu, m, off, 16));

    float den = 0.f;
    for (int i = beg+t; i < end; i += 16) den += expf(g_logit[g_eids[i]] - m);
#pragma unroll
    for (int off = 8; off >= 1; off >>= 1) den += __shfl_xor_sync(0xffffffffu, den, off, 16);
    den += 1e-16f;
    float inv_den = 1.f/den;

    float acc[16];
#pragma unroll
    for (int q = 0; q < 16; q++) acc[q] = 0.f;
    for (int i = beg; i < end; i++){
        int e = g_eids[i];
        float w = expf(g_logit[e] - m) * inv_den;
        const float* mr = g_msg + (size_t)e*HD;
#pragma unroll
        for (int q = 0; q < 16; q++) acc[q] += w * mr[t + 16*q];
    }
#pragma unroll
    for (int q = 0; q < 16; q++) agg[g*260 + t + 16*q] = acc[q];
    __syncthreads();

    float c[10];
#pragma unroll
    for (int j = 0; j < 10; j++) c[j] = 0.f;
    for (int kc = 0; kc < 256; kc += 32){
        for (int t2 = tid; t2 < 5120; t2 += 256){
            int kk = t2/160, nn = t2 - kk*160;
            Bs[t2] = nW1[(kc+kk)*ND + nn];
        }
        __syncthreads();
#pragma unroll 4
        for (int kk = 0; kk < 32; kk++){
            float a = agg[g*260 + kc+kk];
#pragma unroll
            for (int j = 0; j < 10; j++) c[j] += a * Bs[kk*160 + t + 16*j];
        }
        __syncthreads();
    }

    float rv[10], s = 0.f, s2 = 0.f;
#pragma unroll
    for (int j = 0; j < 10; j++){
        int cc = t + 16*j;
        float v = x[n*ND + cc] + c[j] + nb1[cc];
        rv[j] = v; s += v; s2 += v*v;
    }
#pragma unroll
    for (int off = 8; off >= 1; off >>= 1){
        s  += __shfl_xor_sync(0xffffffffu, s,  off, 16);
        s2 += __shfl_xor_sync(0xffffffffu, s2, off, 16);
    }
    float mu  = s * (1.f/ND);
    float var = s2 * (1.f/ND) - mu*mu;
    float inv = rsqrtf(var + 1e-5f);
#pragma unroll
    for (int j = 0; j < 10; j++){
        int cc = t + 16*j;
        g_node_lat[n*ND + cc] = (rv[j] - mu)*inv*lg[cc] + lb[cc];
    }
}

// ---------------- launch -----------------------------------------------------
extern "C" void kernel_launch(void* const* d_in, const int* in_sizes, int n_in,
                              void* d_out, int out_size)
{
    const float* x     = (const float*)d_in[0];
    const float* ea    = (const float*)d_in[1];
    const float* encW1 = (const float*)d_in[2];
    const float* encb1 = (const float*)d_in[3];
    const float* encW2 = (const float*)d_in[4];
    const float* encb2 = (const float*)d_in[5];
    const float* eW1   = (const float*)d_in[6];
    const float* eb1   = (const float*)d_in[7];
    const float* eW2   = (const float*)d_in[8];
    const float* eb2   = (const float*)d_in[9];
    const float* mW1   = (const float*)d_in[10];
    const float* mb1   = (const float*)d_in[11];
    const float* attv  = (const float*)d_in[12];
    const float* nW1   = (const float*)d_in[13];
    const float* nb1   = (const float*)d_in[14];
    const float* ln_ng = (const float*)d_in[15];
    const float* ln_nb = (const float*)d_in[16];
    const float* ln_eg = (const float*)d_in[17];
    const float* ln_eb = (const float*)d_in[18];
    const int*   erow  = (const int*)d_in[19];
    const int*   ecol  = (const int*)d_in[20];

    void *p_deg, *p_rowptr, *p_fill, *p_node, *p_edge, *p_P, *p_Pbase, *p_Penc;
    void *p_WEh, *p_WEl, *p_WPh, *p_WPl, *p_Xh, *p_Xl, *p_NLh, *p_NLl;
    cudaGetSymbolAddress(&p_deg,    g_deg);
    cudaGetSymbolAddress(&p_rowptr, g_rowptr);
    cudaGetSymbolAddress(&p_fill,   g_fill);
    cudaGetSymbolAddress(&p_node,   g_node_lat);
    cudaGetSymbolAddress(&p_edge,   g_edge_lat);
    cudaGetSymbolAddress(&p_P,      g_P);
    cudaGetSymbolAddress(&p_Pbase,  g_Pbase);
    cudaGetSymbolAddress(&p_Penc,   g_Penc);
    cudaGetSymbolAddress(&p_WEh,    gWEh);
    cudaGetSymbolAddress(&p_WEl,    gWEl);
    cudaGetSymbolAddress(&p_WPh,    gWPh);
    cudaGetSymbolAddress(&p_WPl,    gWPl);
    cudaGetSymbolAddress(&p_Xh,     gXh);
    cudaGetSymbolAddress(&p_Xl,     gXl);
    cudaGetSymbolAddress(&p_NLh,    gNLh);
    cudaGetSymbolAddress(&p_NLl,    gNLl);

    cudaFuncSetAttribute(k_edge_tc, cudaFuncAttributeMaxDynamicSharedMemorySize, 153600);

    static cudaStream_t s1 = nullptr;
    static cudaEvent_t evA = nullptr, evB = nullptr;
    if (s1 == nullptr){
        cudaStreamCreateWithFlags(&s1, cudaStreamNonBlocking);
        cudaEventCreateWithFlags(&evA, cudaEventDisableTiming);
        cudaEventCreateWithFlags(&evB, cudaEventDisableTiming);
    }

    // fork: CSR build on s1, GEMM prologue on stream 0
    cudaEventRecord(evA, 0);
    cudaStreamWaitEvent(s1, evA, 0);

    cudaMemsetAsync(p_deg, 0, NN*sizeof(int), s1);
    k_hist<<<(NE+255)/256, 256, 0, s1>>>(erow);
    k_scan1<<<49, 256, 0, s1>>>();
    k_scan2<<<1, 32, 0, s1>>>();
    k_scan3<<<(NN+255)/256, 256, 0, s1>>>();
    cudaMemcpyAsync(p_fill, p_rowptr, NN*sizeof(int), cudaMemcpyDeviceToDevice, s1);
    k_scatter<<<(NE+255)/256, 256, 0, s1>>>(erow);

    k_prep<<<480, 256>>>(eW1, mW1, encW1, eW2);
    k_packA<<<(NN*80+255)/256, 256>>>(x, (uint32_t*)p_Xh, (uint32_t*)p_Xl);
    {
        dim3 g((NN+127)/128, 6);
        k_gemm_bf<<<g, 256>>>((const uint32_t*)p_Xh, (const uint32_t*)p_Xl,
                              (const uint32_t*)p_WPh, (const uint32_t*)p_WPl,
                              160, 160, (float*)p_Pbase, 768, nullptr);
    }
    {
        dim3 g((NN+127)/128, 2);
        k_gemm_bf<<<g, 256>>>((const uint32_t*)p_Xh, (const uint32_t*)p_Xl,
                              (const uint32_t*)p_WEh, (const uint32_t*)p_WEl,
                              160, 80, (float*)p_Penc, 256, nullptr);
    }
    k_enc_edge<<<NE/64, 256>>>(ea, erow, ecol, encW1, encb1, encW2, encb2);

    cudaEventRecord(evB, s1);
    cudaStreamWaitEvent(0, evB, 0);

    for (int it = 0; it < 3; it++){
        const uint32_t* ah = (it == 0) ? (const uint32_t*)p_Xh : (const uint32_t*)p_NLh;
        const uint32_t* al = (it == 0) ? (const uint32_t*)p_Xl : (const uint32_t*)p_NLl;
        dim3 g((NN+127)/128, 6);
        k_gemm_bf<<<g, 256>>>(ah, al,
                              (const uint32_t*)p_WPh + 80, (const uint32_t*)p_WPl + 80,
                              160, 160, (float*)p_P, 768, (const float*)p_Pbase);
        k_edge_tc<<<(NE+127)/128, 512, 153600>>>(erow, ecol, eb1, eb2, mb1, attv, ln_eg, ln_eb);
        k_node<<<NN/16, 256>>>(x, nW1, nb1, ln_ng, ln_nb);
        if (it < 2)
            k_packA<<<(NN*80+255)/256, 256>>>((const float*)p_node,
                                              (uint32_t*)p_NLh, (uint32_t*)p_NLl);
    }

    float* out = (float*)d_out;
    if (out_size >= NN*ND + NE*ED){
        cudaMemcpyAsync(out,         p_node, (size_t)NN*ND*sizeof(float), cudaMemcpyDeviceToDevice, 0);
        cudaMemcpyAsync(out + NN*ND, p_edge, (size_t)NE*ED*sizeof(float), cudaMemcpyDeviceToDevice, 0);
    } else if (out_size == NN*ND){
        cudaMemcpyAsync(out, p_node, (size_t)NN*ND*sizeof(float), cudaMemcpyDeviceToDevice, 0);
    } else {
        size_t nel = (size_t)((out_size < NE*ED) ? out_size : NE*ED);
        cudaMemcpyAsync(out, p_edge, nel*sizeof(float), cudaMemcpyDeviceToDevice, 0);
    }
}

// round 14
// speedup vs baseline: 1.1369x; 1.1169x over previous
#include <cuda_runtime.h>
#include <cuda_bf16.h>
#include <math.h>
#include <stdint.h>

#define NN 50000
#define NE 200000
#define ND 160
#define ED 64
#define RD 8
#define HD 256
#define EH 128

// ---------------- scratch (device globals; no runtime allocation) ----------
__device__ float g_init_edge[NE*ED];
__device__ float g_edge_lat [NE*ED];
__device__ float g_node_lat [NN*ND];
__device__ float g_msg      [NE*HD];
__device__ float g_logit    [NE];
__device__ float g_P        [(size_t)NN*768];
__device__ float g_Pbase    [(size_t)NN*768];
__device__ float g_Penc     [(size_t)NN*256];
__device__ float g_tmp      [(size_t)NN*ND];
__device__ uint32_t gWPh[768*160], gWPl[768*160];
__device__ uint32_t gWEh[256*80],  gWEl[256*80];
__device__ uint32_t gWNh[256*128], gWNl[256*128];   // nW1 K-major, rows >=160 zero
__device__ uint32_t gB1h[256*64],  gB1l[256*64];
__device__ uint32_t gB2h[64*128],  gB2l[64*128];
__device__ uint32_t gB3h[256*32],  gB3l[256*32];
__device__ uint32_t gXh[(size_t)NN*80],  gXl[(size_t)NN*80];    // packed x
__device__ uint32_t gNLh[(size_t)NN*80], gNLl[(size_t)NN*80];   // packed node_lat
__device__ uint32_t gAGh[(size_t)NN*128], gAGl[(size_t)NN*128]; // packed agg
__device__ int   g_deg      [NN];
__device__ int   g_rowptr   [NN+1];
__device__ int   g_fill     [NN];
__device__ int   g_eids     [NE];
__device__ int   g_part     [64];

// ---------------- helpers ----------------------------------------------------
__device__ __forceinline__ void split2(float x, float y, uint32_t& hi, uint32_t& lo){
    __nv_bfloat162 h = __floats2bfloat162_rn(x, y);
    hi = *(uint32_t*)&h;
    float rx = x - __bfloat162float(h.x);
    float ry = y - __bfloat162float(h.y);
    __nv_bfloat162 l = __floats2bfloat162_rn(rx, ry);
    lo = *(uint32_t*)&l;
}
__device__ __forceinline__ void mma_bf16(
    float& c0, float& c1, float& c2, float& c3,
    uint32_t a0, uint32_t a1, uint32_t a2, uint32_t a3, uint32_t b0, uint32_t b1)
{
    asm volatile(
        "mma.sync.aligned.m16n8k16.row.col.f32.bf16.bf16.f32 "
        "{%0,%1,%2,%3}, {%4,%5,%6,%7}, {%8,%9}, {%0,%1,%2,%3};"
        : "+f"(c0), "+f"(c1), "+f"(c2), "+f"(c3)
        : "r"(a0), "r"(a1), "r"(a2), "r"(a3), "r"(b0), "r"(b1));
}
__device__ __forceinline__ void ldsm_x4(uint32_t& r0, uint32_t& r1, uint32_t& r2, uint32_t& r3, uint32_t a){
    asm volatile("ldmatrix.sync.aligned.m8n8.x4.shared.b16 {%0,%1,%2,%3}, [%4];"
        : "=r"(r0), "=r"(r1), "=r"(r2), "=r"(r3) : "r"(a));
}

// ---------------- CSR build --------------------------------------------------
__global__ void k_hist(const int* __restrict__ row){
    int e = blockIdx.x*blockDim.x + threadIdx.x;
    if (e < NE) atomicAdd(&g_deg[row[e]], 1);
}

__global__ void k_scan1(){
    __shared__ int ss[256];
    int b = blockIdx.x, base = b*1024, tid = threadIdx.x;
    int v[4], tsum = 0;
#pragma unroll
    for (int r = 0; r < 4; r++){
        int idx = base + tid*4 + r;
        v[r] = (idx < NN) ? g_deg[idx] : 0;
        tsum += v[r];
    }
    ss[tid] = tsum; __syncthreads();
    for (int off = 1; off < 256; off <<= 1){
        int add = (tid >= off) ? ss[tid-off] : 0;
        __syncthreads();
        ss[tid] += add;
        __syncthreads();
    }
    int run = ss[tid] - tsum;
#pragma unroll
    for (int r = 0; r < 4; r++){
        int idx = base + tid*4 + r;
        if (idx < NN) g_rowptr[idx] = run;
        run += v[r];
    }
    if (tid == 255) g_part[b] = ss[255];
}

__global__ void k_scan2(){
    if (threadIdx.x == 0){
        int run = 0;
        for (int i = 0; i < 49; i++){ int t = g_part[i]; g_part[i] = run; run += t; }
    }
}

__global__ void k_scan3(){
    int i = blockIdx.x*blockDim.x + threadIdx.x;
    if (i < NN) g_rowptr[i] += g_part[i >> 10];
    if (i == 0) g_rowptr[NN] = NE;
}

__global__ void k_scatter(const int* __restrict__ row){
    int e = blockIdx.x*blockDim.x + threadIdx.x;
    if (e < NE){
        int p = atomicAdd(&g_fill[row[e]], 1);
        g_eids[p] = e;
    }
}

// ---------------- pack weight tables (bf16 hi/lo, K-major) -------------------
__global__ void k_prep(const float* __restrict__ eW1, const float* __restrict__ mW1,
                       const float* __restrict__ encW1, const float* __restrict__ eW2,
                       const float* __restrict__ nW1)
{
    int i = blockIdx.x*blockDim.x + threadIdx.x;
    if (i < 768*160){
        int n = i/160, w = i - n*160, k = w*2;
        float f0, f1;
        if (n < 256){ f0 = eW1[k*256+n]; f1 = eW1[(k+1)*256+n]; }
        else if (n < 512){ int nn = n-256; f0 = eW1[(320+k)*256+nn]; f1 = eW1[(321+k)*256+nn]; }
        else { int nn = n-512; f0 = mW1[k*256+nn]; f1 = mW1[(k+1)*256+nn]; }
        split2(f0, f1, gWPh[i], gWPl[i]);
    }
    if (i < 256*80){
        int n = i/80, w = i - n*80, k = w*2;
        float f0, f1;
        if (n < 128){ f0 = encW1[k*128+n]; f1 = encW1[(k+1)*128+n]; }
        else { int nn = n-128; f0 = encW1[(160+k)*128+nn]; f1 = encW1[(161+k)*128+nn]; }
        split2(f0, f1, gWEh[i], gWEl[i]);
    }
    if (i < 256*128){
        int n = i>>7, w = i&127, k = w*2;
        uint32_t hi = 0u, lo = 0u;
        if (n < 160) split2(nW1[k*ND+n], nW1[(k+1)*ND+n], hi, lo);
        gWNh[i] = hi; gWNl[i] = lo;
    }
    if (i < 256*64){
        int n = i/64, w = i - n*64, k = w*2;
        split2(eW1[(640+k)*256+n], eW1[(641+k)*256+n], gB1h[i], gB1l[i]);
    }
    if (i < 64*128){
        int n = i/128, w = i - n*128, k = w*2;
        split2(eW2[k*64+n], eW2[(k+1)*64+n], gB2h[i], gB2l[i]);
    }
    if (i < 256*32){
        int n = i/32, w = i - n*32, k = w*2;
        split2(mW1[(320+k)*256+n], mW1[(321+k)*256+n], gB3h[i], gB3l[i]);
    }
}

// ---------------- pack a [NN,160] fp32 matrix into bf16 hi/lo [NN,80] --------
__global__ void k_packA(const float* __restrict__ src,
                        uint32_t* __restrict__ dh, uint32_t* __restrict__ dl)
{
    int i = blockIdx.x*blockDim.x + threadIdx.x;
    if (i < NN*80){
        int n = i/80, w = i - n*80;
        float2 v = *(const float2*)&src[(size_t)n*ND + 2*w];
        split2(v.x, v.y, dh[i], dl[i]);
    }
}

// ---------------- bf16 3-split dense GEMM (m16n8k16), packed A ---------------
// out[m, n0+n] = (base?base[m,n]:0) + (bias?bias[n]:0) + sum_k A[m,k]*B[n0+n,k]
__global__ __launch_bounds__(256,2) void k_gemm_bf(
    const uint32_t* __restrict__ Ah_, const uint32_t* __restrict__ Al_, int astrW,
    const uint32_t* __restrict__ Bh, const uint32_t* __restrict__ Bl,
    int K, int bstrW,
    float* __restrict__ out, int ostride, int ncols,
    const float* __restrict__ base, const float* __restrict__ bias)
{
    __shared__ uint32_t sAh[128*20], sAl[128*20], sBh[128*20], sBl[128*20];
    const int tid = threadIdx.x, wid = tid>>5, lane = tid&31;
    const int gid = lane>>2, tq = lane&3;
    const int warp_m = (wid & 1)*64, warp_n = (wid >> 1)*32;
    const int m0 = blockIdx.x*128, n0 = blockIdx.y*128;

    float c[4][4][4];
#pragma unroll
    for (int i = 0; i < 4; i++)
#pragma unroll
        for (int j = 0; j < 4; j++)
#pragma unroll
            for (int r = 0; r < 4; r++) c[i][j][r] = 0.f;

    const int nk = K >> 5;
    for (int ch = 0; ch < nk; ch++){
        const int kc2 = ch*16;
#pragma unroll
        for (int p = 0; p < 2; p++){
            int lin = tid + p*256;
            int row = lin>>2, q = lin&3;
            int gm = m0 + row;
            uint4 vh = make_uint4(0u,0u,0u,0u), vl = make_uint4(0u,0u,0u,0u);
            if (gm < NN){
                size_t g = (size_t)gm*astrW + kc2 + q*4;
                vh = *(const uint4*)&Ah_[g];
                vl = *(const uint4*)&Al_[g];
            }
            *(uint4*)&sAh[row*20 + q*4] = vh;
            *(uint4*)&sAl[row*20 + q*4] = vl;
        }
#pragma unroll
        for (int p = 0; p < 2; p++){
            int lin = tid + p*256;
            int row = lin>>2, q = lin&3;
            size_t gofs = (size_t)(n0+row)*bstrW + kc2 + q*4;
            *(uint4*)&sBh[row*20 + q*4] = *(const uint4*)&Bh[gofs];
            *(uint4*)&sBl[row*20 + q*4] = *(const uint4*)&Bl[gofs];
        }
        __syncthreads();
#pragma unroll
        for (int s = 0; s < 2; s++){
            const int kb = s*8 + tq;
            uint32_t bh0[4], bh1[4], bl0[4], bl1[4];
#pragma unroll
            for (int nt = 0; nt < 4; nt++){
                int nr = warp_n + nt*8 + gid;
                bh0[nt] = sBh[nr*20 + kb]; bh1[nt] = sBh[nr*20 + kb + 4];
                bl0[nt] = sBl[nr*20 + kb]; bl1[nt] = sBl[nr*20 + kb + 4];
            }
#pragma unroll
            for (int mt = 0; mt < 4; mt++){
                int ar = warp_m + mt*16 + gid;
                uint32_t ah0 = sAh[ar*20+kb],     ah1 = sAh[(ar+8)*20+kb];
                uint32_t ah2 = sAh[ar*20+kb+4],   ah3 = sAh[(ar+8)*20+kb+4];
                uint32_t al0 = sAl[ar*20+kb],     al1 = sAl[(ar+8)*20+kb];
                uint32_t al2 = sAl[ar*20+kb+4],   al3 = sAl[(ar+8)*20+kb+4];
#pragma unroll
                for (int nt = 0; nt < 4; nt++){
                    mma_bf16(c[mt][nt][0], c[mt][nt][1], c[mt][nt][2], c[mt][nt][3],
                             ah0, ah1, ah2, ah3, bh0[nt], bh1[nt]);
                    mma_bf16(c[mt][nt][0], c[mt][nt][1], c[mt][nt][2], c[mt][nt][3],
                             ah0, ah1, ah2, ah3, bl0[nt], bl1[nt]);
                    mma_bf16(c[mt][nt][0], c[mt][nt][1], c[mt][nt][2], c[mt][nt][3],
                             al0, al1, al2, al3, bh0[nt], bh1[nt]);
                }
            }
        }
        __syncthreads();
    }

#pragma unroll
    for (int mt = 0; mt < 4; mt++){
        int r0 = m0 + warp_m + mt*16 + gid;
        int r1 = r0 + 8;
#pragma unroll
        for (int nt = 0; nt < 4; nt++){
            int gn = n0 + warp_n + nt*8 + tq*2;
            if (gn >= ncols) continue;
            float bx = 0.f, by = 0.f;
            if (bias){ bx = bias[gn]; by = bias[gn+1]; }
            if (r0 < NN){
                float2 v = make_float2(c[mt][nt][0] + bx, c[mt][nt][1] + by);
                if (base){ float2 b = *(const float2*)&base[(size_t)r0*ostride + gn]; v.x += b.x; v.y += b.y; }
                *(float2*)&out[(size_t)r0*ostride + gn] = v;
            }
            if (r1 < NN){
                float2 v = make_float2(c[mt][nt][2] + bx, c[mt][nt][3] + by);
                if (base){ float2 b = *(const float2*)&base[(size_t)r1*ostride + gn]; v.x += b.x; v.y += b.y; }
                *(float2*)&out[(size_t)r1*ostride + gn] = v;
            }
        }
    }
}

// ---------------- fused edge kernel: ldmatrix A-operands (round-11) ----------
__global__ __launch_bounds__(512,1) void k_edge_tc(
    const int* __restrict__ row, const int* __restrict__ col,
    const float* __restrict__ eb1, const float* __restrict__ eb2,
    const float* __restrict__ mb1, const float* __restrict__ attv,
    const float* __restrict__ lgE, const float* __restrict__ lbE)
{
    extern __shared__ uint32_t esm[];
    uint32_t* Ah  = esm;              // [128][68]
    uint32_t* Al  = esm + 8704;
    uint32_t* B1h = esm + 17408;      // [256][20]
    uint32_t* B1l = esm + 22528;
    uint32_t* Hh  = esm;              // [128][132] overlay (phase2)
    uint32_t* Hl  = esm + 16896;
    uint32_t* B2h = esm + 33792;      // [64][36]
    uint32_t* B2l = esm + 36096;
    uint32_t* NEh = esm;              // [128][36] overlay
    uint32_t* NEl = esm + 4608;
    uint32_t* B3h = esm + 9216;       // [256][36]
    uint32_t* B3l = esm + 18432;
    __shared__ int sR[128], sC[128];
    __shared__ float sAtt[256];
    __shared__ float sLog[128];
    __shared__ float sSum[128], sSq[128], sMu[128], sInv[128];

    const int tid = threadIdx.x, wid = tid>>5, lane = tid&31;
    const int gid = lane>>2, tq = lane&3;
    const int warp_m  = (wid & 1)*64;
    const int warp_n  = (wid >> 1)*32;
    const int warp_n2 = (wid >> 1)*8;
    const int e0 = blockIdx.x*128;

    const int lrow = lane & 15;
    const int lkh  = (lane >> 4) << 2;
    const uint32_t aAh = (uint32_t)__cvta_generic_to_shared(Ah);
    const uint32_t aAl = (uint32_t)__cvta_generic_to_shared(Al);
    const uint32_t aHh = (uint32_t)__cvta_generic_to_shared(Hh);
    const uint32_t aHl = (uint32_t)__cvta_generic_to_shared(Hl);
    const uint32_t aNh = (uint32_t)__cvta_generic_to_shared(NEh);
    const uint32_t aNl = (uint32_t)__cvta_generic_to_shared(NEl);
    uint32_t offA[4], offH[4], offN[4];
#pragma unroll
    for (int mt = 0; mt < 4; mt++){
        int r = warp_m + mt*16 + lrow;
        offA[mt] = (uint32_t)((r*68  + lkh) * 4);
        offH[mt] = (uint32_t)((r*132 + lkh) * 4);
        offN[mt] = (uint32_t)((r*36  + lkh) * 4);
    }

    if (tid < 128){
        int ge = e0 + tid;
        sR[tid] = (ge < NE) ? row[ge] : 0;
        sC[tid] = (ge < NE) ? col[ge] : 0;
        sLog[tid] = 0.f; sSum[tid] = 0.f; sSq[tid] = 0.f;
    }
    if (tid < 256) sAtt[tid] = attv[tid];
    __syncthreads();

    // ---- phase 1: stage A + C init from P gathers ---------------------------
    for (int lin = tid; lin < 8192; lin += 512){
        int r = lin>>6, w = lin&63, k = w*2;
        float2 v = make_float2(0.f, 0.f);
        if (e0 + r < NE)
            v = (k < 64) ? *(const float2*)&g_init_edge[(size_t)(e0+r)*ED + k]
                         : *(const float2*)&g_edge_lat [(size_t)(e0+r)*ED + (k-64)];
        split2(v.x, v.y, Ah[r*68+w], Al[r*68+w]);
    }
    float c1[4][4][4];
#pragma unroll
    for (int mt = 0; mt < 4; mt++){
        int rA = warp_m + mt*16 + gid, rB = rA + 8;
        size_t prA = (size_t)sR[rA]*768, pcA = (size_t)sC[rA]*768;
        size_t prB = (size_t)sR[rB]*768, pcB = (size_t)sC[rB]*768;
#pragma unroll
        for (int nt = 0; nt < 4; nt++){
            int cn = warp_n + nt*8 + tq*2;
            float2 b  = *(const float2*)&eb1[cn];
            float2 a1 = *(const float2*)&g_P[prA + cn];
            float2 a2 = *(const float2*)&g_P[pcA + 256 + cn];
            float2 a3 = *(const float2*)&g_P[prB + cn];
            float2 a4 = *(const float2*)&g_P[pcB + 256 + cn];
            c1[mt][nt][0] = a1.x + a2.x + b.x;
            c1[mt][nt][1] = a1.y + a2.y + b.y;
            c1[mt][nt][2] = a3.x + a4.x + b.x;
            c1[mt][nt][3] = a3.y + a4.y + b.y;
        }
    }
    __syncthreads();

#pragma unroll
    for (int ch = 0; ch < 4; ch++){
        for (int lin = tid; lin < 1024; lin += 512){
            int r = lin>>2, q = lin&3;
            size_t gofs = (size_t)r*64 + ch*16 + q*4;
            *(uint4*)&B1h[r*20 + q*4] = *(const uint4*)&gB1h[gofs];
            *(uint4*)&B1l[r*20 + q*4] = *(const uint4*)&gB1l[gofs];
        }
        __syncthreads();
#pragma unroll
        for (int s = 0; s < 2; s++){
            int kb = s*8 + tq;
            uint32_t kw = (uint32_t)((ch*16 + s*8) * 4);
            uint32_t bh0[4], bh1[4], bl0[4], bl1[4];
#pragma unroll
            for (int nt = 0; nt < 4; nt++){
                int nr = warp_n + nt*8 + gid;
                bh0[nt] = B1h[nr*20+kb]; bh1[nt] = B1h[nr*20+kb+4];
                bl0[nt] = B1l[nr*20+kb]; bl1[nt] = B1l[nr*20+kb+4];
            }
#pragma unroll
            for (int mt = 0; mt < 4; mt++){
                uint32_t ah0,ah1,ah2,ah3, al0,al1,al2,al3;
                ldsm_x4(ah0,ah1,ah2,ah3, aAh + offA[mt] + kw);
                ldsm_x4(al0,al1,al2,al3, aAl + offA[mt] + kw);
#pragma unroll
                for (int nt = 0; nt < 4; nt++){
                    mma_bf16(c1[mt][nt][0],c1[mt][nt][1],c1[mt][nt][2],c1[mt][nt][3],
                             ah0,ah1,ah2,ah3, bh0[nt],bh1[nt]);
                    mma_bf16(c1[mt][nt][0],c1[mt][nt][1],c1[mt][nt][2],c1[mt][nt][3],
                             ah0,ah1,ah2,ah3, bl0[nt],bl1[nt]);
                    mma_bf16(c1[mt][nt][0],c1[mt][nt][1],c1[mt][nt][2],c1[mt][nt][3],
                             al0,al1,al2,al3, bh0[nt],bh1[nt]);
                }
            }
        }
        __syncthreads();
    }

    // write hidden (relu, bf16 split) over A/B1 region
#pragma unroll
    for (int mt = 0; mt < 4; mt++){
        int rA = warp_m + mt*16 + gid, rB = rA + 8;
#pragma unroll
        for (int nt = 0; nt < 4; nt++){
            int wcol = (warp_n>>1) + nt*4 + tq;
            float v0 = fmaxf(c1[mt][nt][0], 0.f), v1 = fmaxf(c1[mt][nt][1], 0.f);
            float v2 = fmaxf(c1[mt][nt][2], 0.f), v3 = fmaxf(c1[mt][nt][3], 0.f);
            split2(v0, v1, Hh[rA*132+wcol], Hl[rA*132+wcol]);
            split2(v2, v3, Hh[rB*132+wcol], Hl[rB*132+wcol]);
        }
    }
    __syncthreads();

    // ---- phase 2 ------------------------------------------------------------
    float c2[4][4];
#pragma unroll
    for (int mt = 0; mt < 4; mt++){
        float2 b = *(const float2*)&eb2[warp_n2 + tq*2];
        c2[mt][0] = b.x; c2[mt][1] = b.y; c2[mt][2] = b.x; c2[mt][3] = b.y;
    }
#pragma unroll
    for (int ch = 0; ch < 4; ch++){
        {
            int r = tid>>3, q = tid&7;
            size_t gofs = (size_t)r*128 + ch*32 + q*4;
            *(uint4*)&B2h[r*36 + q*4] = *(const uint4*)&gB2h[gofs];
            *(uint4*)&B2l[r*36 + q*4] = *(const uint4*)&gB2l[gofs];
        }
        __syncthreads();
#pragma unroll
        for (int s = 0; s < 4; s++){
            int kb = s*8 + tq;
            uint32_t kw = (uint32_t)((ch*32 + s*8) * 4);
            int nr = warp_n2 + gid;
            uint32_t bh0 = B2h[nr*36+kb], bh1 = B2h[nr*36+kb+4];
            uint32_t bl0 = B2l[nr*36+kb], bl1 = B2l[nr*36+kb+4];
#pragma unroll
            for (int mt = 0; mt < 4; mt++){
                uint32_t ah0,ah1,ah2,ah3, al0,al1,al2,al3;
                ldsm_x4(ah0,ah1,ah2,ah3, aHh + offH[mt] + kw);
                ldsm_x4(al0,al1,al2,al3, aHl + offH[mt] + kw);
                mma_bf16(c2[mt][0],c2[mt][1],c2[mt][2],c2[mt][3], ah0,ah1,ah2,ah3, bh0,bh1);
                mma_bf16(c2[mt][0],c2[mt][1],c2[mt][2],c2[mt][3], ah0,ah1,ah2,ah3, bl0,bl1);
                mma_bf16(c2[mt][0],c2[mt][1],c2[mt][2],c2[mt][3], al0,al1,al2,al3, bh0,bh1);
            }
        }
        __syncthreads();
    }

    // ---- NE pack + LN stats; stage full B3 (stride 36) -----------------------
#pragma unroll
    for (int mt = 0; mt < 4; mt++){
        int rA = warp_m + mt*16 + gid, rB = rA + 8;
        int cn = warp_n2 + tq*2;
        int wcol = (warp_n2>>1) + tq;
        split2(c2[mt][0], c2[mt][1], NEh[rA*36+wcol], NEl[rA*36+wcol]);
        split2(c2[mt][2], c2[mt][3], NEh[rB*36+wcol], NEl[rB*36+wcol]);
        float2 iA = make_float2(0.f,0.f), iB = make_float2(0.f,0.f);
        if (e0 + rA < NE) iA = *(const float2*)&g_init_edge[(size_t)(e0+rA)*ED + cn];
        if (e0 + rB < NE) iB = *(const float2*)&g_init_edge[(size_t)(e0+rB)*ED + cn];
        c2[mt][0] += iA.x; c2[mt][1] += iA.y;
        c2[mt][2] += iB.x; c2[mt][3] += iB.y;
        atomicAdd(&sSum[rA], c2[mt][0] + c2[mt][1]);
        atomicAdd(&sSq [rA], c2[mt][0]*c2[mt][0] + c2[mt][1]*c2[mt][1]);
        atomicAdd(&sSum[rB], c2[mt][2] + c2[mt][3]);
        atomicAdd(&sSq [rB], c2[mt][2]*c2[mt][2] + c2[mt][3]*c2[mt][3]);
    }
    for (int lin = tid; lin < 2048; lin += 512){
        int r = lin>>3, q = lin&7;
        size_t gofs = (size_t)r*32 + q*4;
        *(uint4*)&B3h[r*36 + q*4] = *(const uint4*)&gB3h[gofs];
        *(uint4*)&B3l[r*36 + q*4] = *(const uint4*)&gB3l[gofs];
    }
    float c3[4][4][4];
#pragma unroll
    for (int mt = 0; mt < 4; mt++){
        int rA = warp_m + mt*16 + gid, rB = rA + 8;
        size_t pcA = (size_t)sC[rA]*768, pcB = (size_t)sC[rB]*768;
#pragma unroll
        for (int nt = 0; nt < 4; nt++){
            int cn = warp_n + nt*8 + tq*2;
            float2 b  = *(const float2*)&mb1[cn];
            float2 a1 = *(const float2*)&g_P[pcA + 512 + cn];
            float2 a2 = *(const float2*)&g_P[pcB + 512 + cn];
            c3[mt][nt][0] = a1.x + b.x; c3[mt][nt][1] = a1.y + b.y;
            c3[mt][nt][2] = a2.x + b.x; c3[mt][nt][3] = a2.y + b.y;
        }
    }
    __syncthreads();

    if (tid < 128){
        float mu = sSum[tid] * (1.f/ED);
        float var = sSq[tid] * (1.f/ED) - mu*mu;
        sMu[tid] = mu;
        sInv[tid] = rsqrtf(var + 1e-5f);
    }
    __syncthreads();

#pragma unroll
    for (int mt = 0; mt < 4; mt++){
        int rA = warp_m + mt*16 + gid, rB = rA + 8;
        int cn = warp_n2 + tq*2;
        float g0 = lgE[cn], g1 = lgE[cn+1], b0 = lbE[cn], b1 = lbE[cn+1];
        if (e0 + rA < NE){
            float mu = sMu[rA], inv = sInv[rA];
            *(float2*)&g_edge_lat[(size_t)(e0+rA)*ED + cn] =
                make_float2((c2[mt][0]-mu)*inv*g0 + b0, (c2[mt][1]-mu)*inv*g1 + b1);
        }
        if (e0 + rB < NE){
            float mu = sMu[rB], inv = sInv[rB];
            *(float2*)&g_edge_lat[(size_t)(e0+rB)*ED + cn] =
                make_float2((c2[mt][2]-mu)*inv*g0 + b0, (c2[mt][3]-mu)*inv*g1 + b1);
        }
    }

    // ---- phase 3 MMA loop ----------------------------------------------------
#pragma unroll
    for (int s = 0; s < 4; s++){
        int ka = s*8 + tq;
        uint32_t kw = (uint32_t)((s*8) * 4);
        uint32_t bh0[4], bh1[4], bl0[4], bl1[4];
#pragma unroll
        for (int nt = 0; nt < 4; nt++){
            int nr = warp_n + nt*8 + gid;
            bh0[nt] = B3h[nr*36+ka]; bh1[nt] = B3h[nr*36+ka+4];
            bl0[nt] = B3l[nr*36+ka]; bl1[nt] = B3l[nr*36+ka+4];
        }
#pragma unroll
        for (int mt = 0; mt < 4; mt++){
            uint32_t ah0,ah1,ah2,ah3, al0,al1,al2,al3;
            ldsm_x4(ah0,ah1,ah2,ah3, aNh + offN[mt] + kw);
            ldsm_x4(al0,al1,al2,al3, aNl + offN[mt] + kw);
#pragma unroll
            for (int nt = 0; nt < 4; nt++){
                mma_bf16(c3[mt][nt][0],c3[mt][nt][1],c3[mt][nt][2],c3[mt][nt][3],
                         ah0,ah1,ah2,ah3, bh0[nt],bh1[nt]);
                mma_bf16(c3[mt][nt][0],c3[mt][nt][1],c3[mt][nt][2],c3[mt][nt][3],
                         ah0,ah1,ah2,ah3, bl0[nt],bl1[nt]);
                mma_bf16(c3[mt][nt][0],c3[mt][nt][1],c3[mt][nt][2],c3[mt][nt][3],
                         al0,al1,al2,al3, bh0[nt],bh1[nt]);
            }
        }
    }

    // epilogue: relu -> g_msg, attention partial dot, logit
    float pa[4][2];
#pragma unroll
    for (int mt = 0; mt < 4; mt++){ pa[mt][0] = 0.f; pa[mt][1] = 0.f; }
#pragma unroll
    for (int mt = 0; mt < 4; mt++){
        int rA = warp_m + mt*16 + gid, rB = rA + 8;
#pragma unroll
        for (int nt = 0; nt < 4; nt++){
            int cn = warp_n + nt*8 + tq*2;
            float av0 = sAtt[cn], av1 = sAtt[cn+1];
            float v0 = fmaxf(c3[mt][nt][0], 0.f), v1 = fmaxf(c3[mt][nt][1], 0.f);
            float v2 = fmaxf(c3[mt][nt][2], 0.f), v3 = fmaxf(c3[mt][nt][3], 0.f);
            if (e0 + rA < NE)
                *(float2*)&g_msg[(size_t)(e0+rA)*HD + cn] = make_float2(v0, v1);
            if (e0 + rB < NE)
                *(float2*)&g_msg[(size_t)(e0+rB)*HD + cn] = make_float2(v2, v3);
            pa[mt][0] += v0*av0 + v1*av1;
            pa[mt][1] += v2*av0 + v3*av1;
        }
    }
#pragma unroll
    for (int off = 1; off <= 2; off <<= 1){
#pragma unroll
        for (int mt = 0; mt < 4; mt++){
            pa[mt][0] += __shfl_xor_sync(0xffffffffu, pa[mt][0], off, 4);
            pa[mt][1] += __shfl_xor_sync(0xffffffffu, pa[mt][1], off, 4);
        }
    }
    if (tq == 0){
#pragma unroll
        for (int mt = 0; mt < 4; mt++){
            atomicAdd(&sLog[warp_m + mt*16 + gid],     pa[mt][0]);
            atomicAdd(&sLog[warp_m + mt*16 + gid + 8], pa[mt][1]);
        }
    }
    __syncthreads();
    if (tid < 128 && e0 + tid < NE){
        float p = sLog[tid];
        g_logit[e0+tid] = (p > 0.f) ? p : 0.2f*p;
    }
}

// ---------------- edge encoder tail (dual-writes init_edge + edge_lat) -------
__global__ __launch_bounds__(256,2) void k_enc_edge(
    const float* __restrict__ ea,
    const int* __restrict__ row, const int* __restrict__ col,
    const float* __restrict__ encW1, const float* __restrict__ encb1,
    const float* __restrict__ encW2, const float* __restrict__ encb2)
{
    __shared__ float As[64*9];
    __shared__ float Bs[16*64];
    __shared__ float Hid[64*132];
    __shared__ int sR[64], sC[64];

    const int e0 = blockIdx.x*64;
    const int tid = threadIdx.x, ty = tid>>4, tx = tid&15;
    if (tid < 64){ sR[tid] = row[e0+tid]; sC[tid] = col[e0+tid]; }
    __syncthreads();

    float c[4][8];
#pragma unroll
    for (int i = 0; i < 4; i++){
        int r = ty*4+i;
#pragma unroll
        for (int j = 0; j < 8; j++){
            int n = tx + 16*j;
            c[i][j] = g_Penc[(size_t)sR[r]*256 + n]
                    + g_Penc[(size_t)sC[r]*256 + 128 + n]
                    + encb1[n];
        }
    }
    for (int t = tid; t < 512; t += 256){
        int el = t>>3, kk = t&7;
        As[el*9+kk] = ea[(e0+el)*RD + kk];
    }
    for (int t = tid; t < 1024; t += 256){
        int kk = t>>7, n = t&127;
        Bs[t] = encW1[(320+kk)*EH + n];
    }
    __syncthreads();
#pragma unroll
    for (int kk = 0; kk < 8; kk++){
        float a0 = As[(ty*4+0)*9+kk], a1 = As[(ty*4+1)*9+kk];
        float a2 = As[(ty*4+2)*9+kk], a3 = As[(ty*4+3)*9+kk];
#pragma unroll
        for (int j = 0; j < 8; j++){
            float b = Bs[kk*128 + tx + 16*j];
            c[0][j] += a0*b; c[1][j] += a1*b; c[2][j] += a2*b; c[3][j] += a3*b;
        }
    }
    __syncthreads();
#pragma unroll
    for (int i = 0; i < 4; i++)
#pragma unroll
        for (int j = 0; j < 8; j++){
            int n = tx + 16*j;
            Hid[(ty*4+i)*132 + n] = fmaxf(c[i][j], 0.f);
        }
    __syncthreads();

    float c2[4][4];
#pragma unroll
    for (int i = 0; i < 4; i++)
#pragma unroll
        for (int j = 0; j < 4; j++) c2[i][j] = encb2[tx+16*j];

    for (int kc = 0; kc < 128; kc += 16){
        for (int t = tid; t < 1024; t += 256){
            int kk = t>>6, n = t&63;
            Bs[t] = encW2[(kc+kk)*ED + n];
        }
        __syncthreads();
#pragma unroll
        for (int kk = 0; kk < 16; kk++){
            float a0 = Hid[(ty*4+0)*132 + kc+kk], a1 = Hid[(ty*4+1)*132 + kc+kk];
            float a2 = Hid[(ty*4+2)*132 + kc+kk], a3 = Hid[(ty*4+3)*132 + kc+kk];
#pragma unroll
            for (int j = 0; j < 4; j++){
                float b = Bs[kk*64 + tx + 16*j];
                c2[0][j] += a0*b; c2[1][j] += a1*b; c2[2][j] += a2*b; c2[3][j] += a3*b;
            }
        }
        __syncthreads();
    }
#pragma unroll
    for (int i = 0; i < 4; i++)
#pragma unroll
        for (int j = 0; j < 4; j++){
            size_t o = (size_t)(e0+ty*4+i)*ED + tx + 16*j;
            g_init_edge[o] = c2[i][j];
            g_edge_lat[o]  = c2[i][j];
        }
}

// ---------------- k_agg: segment softmax + aggregation -> packed bf16 --------
__global__ __launch_bounds__(256,2) void k_agg()
{
    __shared__ float agg[16*260];

    const int n0 = blockIdx.x*16;
    const int tid = threadIdx.x, g = tid>>4, t = tid&15;
    const int n = n0 + g;
    const int beg = g_rowptr[n], end = g_rowptr[n+1];

    float m = -1e30f;
    for (int i = beg+t; i < end; i += 16) m = fmaxf(m, g_logit[g_eids[i]]);
#pragma unroll
    for (int off = 8; off >= 1; off >>= 1) m = fmaxf(m, __shfl_xor_sync(0xffffffffu, m, off, 16));

    float den = 0.f;
    for (int i = beg+t; i < end; i += 16) den += expf(g_logit[g_eids[i]] - m);
#pragma unroll
    for (int off = 8; off >= 1; off >>= 1) den += __shfl_xor_sync(0xffffffffu, den, off, 16);
    den += 1e-16f;
    float inv_den = 1.f/den;

    float acc[16];
#pragma unroll
    for (int q = 0; q < 16; q++) acc[q] = 0.f;
    for (int i = beg; i < end; i++){
        int e = g_eids[i];
        float w = expf(g_logit[e] - m) * inv_den;
        const float* mr = g_msg + (size_t)e*HD;
#pragma unroll
        for (int q = 0; q < 16; q++) acc[q] += w * mr[t + 16*q];
    }
#pragma unroll
    for (int q = 0; q < 16; q++) agg[g*260 + t + 16*q] = acc[q];
    __syncthreads();

    for (int i = tid; i < 2048; i += 256){
        int gg = i >> 7, q = i & 127;
        split2(agg[gg*260 + 2*q], agg[gg*260 + 2*q + 1],
               gAGh[(size_t)(n0+gg)*128 + q], gAGl[(size_t)(n0+gg)*128 + q]);
    }
}

// ---------------- node LN (from g_tmp); pack or fp32 output ------------------
__global__ void k_ln_node(const float* __restrict__ lg, const float* __restrict__ lb,
                          int write_fp32)
{
    int w = (blockIdx.x*blockDim.x + threadIdx.x) >> 5;
    int lane = threadIdx.x & 31;
    if (w >= NN) return;
    const float* tr = g_tmp + (size_t)w*ND;
    float v[5], s = 0.f, s2 = 0.f;
#pragma unroll
    for (int j = 0; j < 5; j++){
        float x = tr[lane + 32*j];
        v[j] = x; s += x; s2 += x*x;
    }
#pragma unroll
    for (int off = 16; off >= 1; off >>= 1){
        s  += __shfl_xor_sync(0xffffffffu, s,  off);
        s2 += __shfl_xor_sync(0xffffffffu, s2, off);
    }
    float mu  = s * (1.f/ND);
    float var = s2 * (1.f/ND) - mu*mu;
    float inv = rsqrtf(var + 1e-5f);
    if (write_fp32){
#pragma unroll
        for (int j = 0; j < 5; j++){
            int cc = lane + 32*j;
            g_node_lat[(size_t)w*ND + cc] = (v[j] - mu)*inv*lg[cc] + lb[cc];
        }
    } else {
        for (int q = lane; q < 80; q += 32){
            float a = (tr[2*q]   - mu)*inv*lg[2*q]   + lb[2*q];
            float b = (tr[2*q+1] - mu)*inv*lg[2*q+1] + lb[2*q+1];
            split2(a, b, gNLh[(size_t)w*80 + q], gNLl[(size_t)w*80 + q]);
        }
    }
}

// ---------------- launch -----------------------------------------------------
extern "C" void kernel_launch(void* const* d_in, const int* in_sizes, int n_in,
                              void* d_out, int out_size)
{
    const float* x     = (const float*)d_in[0];
    const float* ea    = (const float*)d_in[1];
    const float* encW1 = (const float*)d_in[2];
    const float* encb1 = (const float*)d_in[3];
    const float* encW2 = (const float*)d_in[4];
    const float* encb2 = (const float*)d_in[5];
    const float* eW1   = (const float*)d_in[6];
    const float* eb1   = (const float*)d_in[7];
    const float* eW2   = (const float*)d_in[8];
    const float* eb2   = (const float*)d_in[9];
    const float* mW1   = (const float*)d_in[10];
    const float* mb1   = (const float*)d_in[11];
    const float* attv  = (const float*)d_in[12];
    const float* nW1   = (const float*)d_in[13];
    const float* nb1   = (const float*)d_in[14];
    const float* ln_ng = (const float*)d_in[15];
    const float* ln_nb = (const float*)d_in[16];
    const float* ln_eg = (const float*)d_in[17];
    const float* ln_eb = (const float*)d_in[18];
    const int*   erow  = (const int*)d_in[19];
    const int*   ecol  = (const int*)d_in[20];

    void *p_deg, *p_rowptr, *p_fill, *p_node, *p_edge, *p_P, *p_Pbase, *p_Penc, *p_tmp;
    void *p_WEh, *p_WEl, *p_WPh, *p_WPl, *p_WNh, *p_WNl;
    void *p_Xh, *p_Xl, *p_NLh, *p_NLl, *p_AGh, *p_AGl;
    cudaGetSymbolAddress(&p_deg,    g_deg);
    cudaGetSymbolAddress(&p_rowptr, g_rowptr);
    cudaGetSymbolAddress(&p_fill,   g_fill);
    cudaGetSymbolAddress(&p_node,   g_node_lat);
    cudaGetSymbolAddress(&p_edge,   g_edge_lat);
    cudaGetSymbolAddress(&p_P,      g_P);
    cudaGetSymbolAddress(&p_Pbase,  g_Pbase);
    cudaGetSymbolAddress(&p_Penc,   g_Penc);
    cudaGetSymbolAddress(&p_tmp,    g_tmp);
    cudaGetSymbolAddress(&p_WEh,    gWEh);
    cudaGetSymbolAddress(&p_WEl,    gWEl);
    cudaGetSymbolAddress(&p_WPh,    gWPh);
    cudaGetSymbolAddress(&p_WPl,    gWPl);
    cudaGetSymbolAddress(&p_WNh,    gWNh);
    cudaGetSymbolAddress(&p_WNl,    gWNl);
    cudaGetSymbolAddress(&p_Xh,     gXh);
    cudaGetSymbolAddress(&p_Xl,     gXl);
    cudaGetSymbolAddress(&p_NLh,    gNLh);
    cudaGetSymbolAddress(&p_NLl,    gNLl);
    cudaGetSymbolAddress(&p_AGh,    gAGh);
    cudaGetSymbolAddress(&p_AGl,    gAGl);

    cudaFuncSetAttribute(k_edge_tc, cudaFuncAttributeMaxDynamicSharedMemorySize, 153600);

    static cudaStream_t s1 = nullptr;
    static cudaEvent_t evA = nullptr, evB = nullptr;
    if (s1 == nullptr){
        cudaStreamCreateWithFlags(&s1, cudaStreamNonBlocking);
        cudaEventCreateWithFlags(&evA, cudaEventDisableTiming);
        cudaEventCreateWithFlags(&evB, cudaEventDisableTiming);
    }

    // fork: CSR build on s1, GEMM prologue on stream 0
    cudaEventRecord(evA, 0);
    cudaStreamWaitEvent(s1, evA, 0);

    cudaMemsetAsync(p_deg, 0, NN*sizeof(int), s1);
    k_hist<<<(NE+255)/256, 256, 0, s1>>>(erow);
    k_scan1<<<49, 256, 0, s1>>>();
    k_scan2<<<1, 32, 0, s1>>>();
    k_scan3<<<(NN+255)/256, 256, 0, s1>>>();
    cudaMemcpyAsync(p_fill, p_rowptr, NN*sizeof(int), cudaMemcpyDeviceToDevice, s1);
    k_scatter<<<(NE+255)/256, 256, 0, s1>>>(erow);

    k_prep<<<480, 256>>>(eW1, mW1, encW1, eW2, nW1);
    k_packA<<<(NN*80+255)/256, 256>>>(x, (uint32_t*)p_Xh, (uint32_t*)p_Xl);
    {
        dim3 g((NN+127)/128, 6);
        k_gemm_bf<<<g, 256>>>((const uint32_t*)p_Xh, (const uint32_t*)p_Xl, 80,
                              (const uint32_t*)p_WPh, (const uint32_t*)p_WPl,
                              160, 160, (float*)p_Pbase, 768, 768, nullptr, nullptr);
    }
    {
        dim3 g((NN+127)/128, 2);
        k_gemm_bf<<<g, 256>>>((const uint32_t*)p_Xh, (const uint32_t*)p_Xl, 80,
                              (const uint32_t*)p_WEh, (const uint32_t*)p_WEl,
                              160, 80, (float*)p_Penc, 256, 256, nullptr, nullptr);
    }
    k_enc_edge<<<NE/64, 256>>>(ea, erow, ecol, encW1, encb1, encW2, encb2);

    cudaEventRecord(evB, s1);
    cudaStreamWaitEvent(0, evB, 0);

    for (int it = 0; it < 3; it++){
        const uint32_t* ah = (it == 0) ? (const uint32_t*)p_Xh : (const uint32_t*)p_NLh;
        const uint32_t* al = (it == 0) ? (const uint32_t*)p_Xl : (const uint32_t*)p_NLl;
        dim3 g((NN+127)/128, 6);
        k_gemm_bf<<<g, 256>>>(ah, al, 80,
                              (const uint32_t*)p_WPh + 80, (const uint32_t*)p_WPl + 80,
                              160, 160, (float*)p_P, 768, 768, (const float*)p_Pbase, nullptr);
        k_edge_tc<<<(NE+127)/128, 512, 153600>>>(erow, ecol, eb1, eb2, mb1, attv, ln_eg, ln_eb);
        k_agg<<<NN/16, 256>>>();
        {
            dim3 gn((NN+127)/128, 2);
            k_gemm_bf<<<gn, 256>>>((const uint32_t*)p_AGh, (const uint32_t*)p_AGl, 128,
                                   (const uint32_t*)p_WNh, (const uint32_t*)p_WNl,
                                   256, 128, (float*)p_tmp, 160, 160, x, nb1);
        }
        k_ln_node<<<(NN*32+255)/256, 256>>>(ln_ng, ln_nb, (it == 2) ? 1 : 0);
    }

    float* out = (float*)d_out;
    if (out_size >= NN*ND + NE*ED){
        cudaMemcpyAsync(out,         p_node, (size_t)NN*ND*sizeof(float), cudaMemcpyDeviceToDevice, 0);
        cudaMemcpyAsync(out + NN*ND, p_edge, (size_t)NE*ED*sizeof(float), cudaMemcpyDeviceToDevice, 0);
    } else if (out_size == NN*ND){
        cudaMemcpyAsync(out, p_node, (size_t)NN*ND*sizeof(float), cudaMemcpyDeviceToDevice, 0);
    } else {
        size_t nel = (size_t)((out_size < NE*ED) ? out_size : NE*ED);
        cudaMemcpyAsync(out, p_edge, nel*sizeof(float), cudaMemcpyDeviceToDevice, 0);
    }
}

// round 15
// speedup vs baseline: 1.1596x; 1.0200x over previous
#include <cuda_runtime.h>
#include <cuda_bf16.h>
#include <math.h>
#include <stdint.h>

#define NN 50000
#define NE 200000
#define ND 160
#define ED 64
#define RD 8
#define HD 256
#define EH 128

// ---------------- scratch (device globals; no runtime allocation) ----------
__device__ float g_init_edge[NE*ED];
__device__ float g_edge_lat [NE*ED];
__device__ float g_node_lat [NN*ND];
__device__ float g_msg      [NE*HD];
__device__ float g_logit    [NE];
__device__ float g_P        [(size_t)NN*768];
__device__ float g_Pbase    [(size_t)NN*768];
__device__ float g_Penc     [(size_t)NN*256];
__device__ uint32_t gWPh[768*160], gWPl[768*160];
__device__ uint32_t gWEh[256*80],  gWEl[256*80];
__device__ uint32_t gWNh[256*128], gWNl[256*128];   // nW1 K-major (n<160 valid)
__device__ uint32_t gB1h[256*64],  gB1l[256*64];
__device__ uint32_t gB2h[64*128],  gB2l[64*128];
__device__ uint32_t gB3h[256*32],  gB3l[256*32];
__device__ uint32_t gXh[(size_t)NN*80],  gXl[(size_t)NN*80];    // packed x
__device__ uint32_t gNLh[(size_t)NN*80], gNLl[(size_t)NN*80];   // packed node_lat
__device__ uint32_t gAGh[(size_t)NN*128], gAGl[(size_t)NN*128]; // packed agg
__device__ int   g_deg      [NN];
__device__ int   g_rowptr   [NN+1];
__device__ int   g_fill     [NN];
__device__ int   g_eids     [NE];
__device__ int   g_part     [64];

// ---------------- helpers ----------------------------------------------------
__device__ __forceinline__ void split2(float x, float y, uint32_t& hi, uint32_t& lo){
    __nv_bfloat162 h = __floats2bfloat162_rn(x, y);
    hi = *(uint32_t*)&h;
    float rx = x - __bfloat162float(h.x);
    float ry = y - __bfloat162float(h.y);
    __nv_bfloat162 l = __floats2bfloat162_rn(rx, ry);
    lo = *(uint32_t*)&l;
}
__device__ __forceinline__ void mma_bf16(
    float& c0, float& c1, float& c2, float& c3,
    uint32_t a0, uint32_t a1, uint32_t a2, uint32_t a3, uint32_t b0, uint32_t b1)
{
    asm volatile(
        "mma.sync.aligned.m16n8k16.row.col.f32.bf16.bf16.f32 "
        "{%0,%1,%2,%3}, {%4,%5,%6,%7}, {%8,%9}, {%0,%1,%2,%3};"
        : "+f"(c0), "+f"(c1), "+f"(c2), "+f"(c3)
        : "r"(a0), "r"(a1), "r"(a2), "r"(a3), "r"(b0), "r"(b1));
}
__device__ __forceinline__ void ldsm_x4(uint32_t& r0, uint32_t& r1, uint32_t& r2, uint32_t& r3, uint32_t a){
    asm volatile("ldmatrix.sync.aligned.m8n8.x4.shared.b16 {%0,%1,%2,%3}, [%4];"
        : "=r"(r0), "=r"(r1), "=r"(r2), "=r"(r3) : "r"(a));
}

// ---------------- CSR build --------------------------------------------------
__global__ void k_hist(const int* __restrict__ row){
    int e = blockIdx.x*blockDim.x + threadIdx.x;
    if (e < NE) atomicAdd(&g_deg[row[e]], 1);
}

__global__ void k_scan1(){
    __shared__ int ss[256];
    int b = blockIdx.x, base = b*1024, tid = threadIdx.x;
    int v[4], tsum = 0;
#pragma unroll
    for (int r = 0; r < 4; r++){
        int idx = base + tid*4 + r;
        v[r] = (idx < NN) ? g_deg[idx] : 0;
        tsum += v[r];
    }
    ss[tid] = tsum; __syncthreads();
    for (int off = 1; off < 256; off <<= 1){
        int add = (tid >= off) ? ss[tid-off] : 0;
        __syncthreads();
        ss[tid] += add;
        __syncthreads();
    }
    int run = ss[tid] - tsum;
#pragma unroll
    for (int r = 0; r < 4; r++){
        int idx = base + tid*4 + r;
        if (idx < NN) g_rowptr[idx] = run;
        run += v[r];
    }
    if (tid == 255) g_part[b] = ss[255];
}

__global__ void k_scan2(){
    if (threadIdx.x == 0){
        int run = 0;
        for (int i = 0; i < 49; i++){ int t = g_part[i]; g_part[i] = run; run += t; }
    }
}

__global__ void k_scan3(){
    int i = blockIdx.x*blockDim.x + threadIdx.x;
    if (i < NN) g_rowptr[i] += g_part[i >> 10];
    if (i == 0) g_rowptr[NN] = NE;
}

__global__ void k_scatter(const int* __restrict__ row){
    int e = blockIdx.x*blockDim.x + threadIdx.x;
    if (e < NE){
        int p = atomicAdd(&g_fill[row[e]], 1);
        g_eids[p] = e;
    }
}

// ---------------- pack weight tables (bf16 hi/lo, K-major) -------------------
__global__ void k_prep(const float* __restrict__ eW1, const float* __restrict__ mW1,
                       const float* __restrict__ encW1, const float* __restrict__ eW2,
                       const float* __restrict__ nW1)
{
    int i = blockIdx.x*blockDim.x + threadIdx.x;
    if (i < 768*160){
        int n = i/160, w = i - n*160, k = w*2;
        float f0, f1;
        if (n < 256){ f0 = eW1[k*256+n]; f1 = eW1[(k+1)*256+n]; }
        else if (n < 512){ int nn = n-256; f0 = eW1[(320+k)*256+nn]; f1 = eW1[(321+k)*256+nn]; }
        else { int nn = n-512; f0 = mW1[k*256+nn]; f1 = mW1[(k+1)*256+nn]; }
        split2(f0, f1, gWPh[i], gWPl[i]);
    }
    if (i < 256*80){
        int n = i/80, w = i - n*80, k = w*2;
        float f0, f1;
        if (n < 128){ f0 = encW1[k*128+n]; f1 = encW1[(k+1)*128+n]; }
        else { int nn = n-128; f0 = encW1[(160+k)*128+nn]; f1 = encW1[(161+k)*128+nn]; }
        split2(f0, f1, gWEh[i], gWEl[i]);
    }
    if (i < 256*128){
        int n = i>>7, w = i&127, k = w*2;
        uint32_t hi = 0u, lo = 0u;
        if (n < 160) split2(nW1[k*ND+n], nW1[(k+1)*ND+n], hi, lo);
        gWNh[i] = hi; gWNl[i] = lo;
    }
    if (i < 256*64){
        int n = i/64, w = i - n*64, k = w*2;
        split2(eW1[(640+k)*256+n], eW1[(641+k)*256+n], gB1h[i], gB1l[i]);
    }
    if (i < 64*128){
        int n = i/128, w = i - n*128, k = w*2;
        split2(eW2[k*64+n], eW2[(k+1)*64+n], gB2h[i], gB2l[i]);
    }
    if (i < 256*32){
        int n = i/32, w = i - n*32, k = w*2;
        split2(mW1[(320+k)*256+n], mW1[(321+k)*256+n], gB3h[i], gB3l[i]);
    }
}

// ---------------- pack a [NN,160] fp32 matrix into bf16 hi/lo [NN,80] --------
__global__ void k_packA(const float* __restrict__ src,
                        uint32_t* __restrict__ dh, uint32_t* __restrict__ dl)
{
    int i = blockIdx.x*blockDim.x + threadIdx.x;
    if (i < NN*80){
        int n = i/80, w = i - n*80;
        float2 v = *(const float2*)&src[(size_t)n*ND + 2*w];
        split2(v.x, v.y, dh[i], dl[i]);
    }
}

// ---------------- bf16 3-split dense GEMM (m16n8k16), packed A ---------------
__global__ __launch_bounds__(256,2) void k_gemm_bf(
    const uint32_t* __restrict__ Ah_, const uint32_t* __restrict__ Al_, int astrW,
    const uint32_t* __restrict__ Bh, const uint32_t* __restrict__ Bl,
    int K, int bstrW,
    float* __restrict__ out, int ostride, int ncols,
    const float* __restrict__ base, const float* __restrict__ bias)
{
    __shared__ uint32_t sAh[128*20], sAl[128*20], sBh[128*20], sBl[128*20];
    const int tid = threadIdx.x, wid = tid>>5, lane = tid&31;
    const int gid = lane>>2, tq = lane&3;
    const int warp_m = (wid & 1)*64, warp_n = (wid >> 1)*32;
    const int m0 = blockIdx.x*128, n0 = blockIdx.y*128;

    float c[4][4][4];
#pragma unroll
    for (int i = 0; i < 4; i++)
#pragma unroll
        for (int j = 0; j < 4; j++)
#pragma unroll
            for (int r = 0; r < 4; r++) c[i][j][r] = 0.f;

    const int nk = K >> 5;
    for (int ch = 0; ch < nk; ch++){
        const int kc2 = ch*16;
#pragma unroll
        for (int p = 0; p < 2; p++){
            int lin = tid + p*256;
            int row = lin>>2, q = lin&3;
            int gm = m0 + row;
            uint4 vh = make_uint4(0u,0u,0u,0u), vl = make_uint4(0u,0u,0u,0u);
            if (gm < NN){
                size_t g = (size_t)gm*astrW + kc2 + q*4;
                vh = *(const uint4*)&Ah_[g];
                vl = *(const uint4*)&Al_[g];
            }
            *(uint4*)&sAh[row*20 + q*4] = vh;
            *(uint4*)&sAl[row*20 + q*4] = vl;
        }
#pragma unroll
        for (int p = 0; p < 2; p++){
            int lin = tid + p*256;
            int row = lin>>2, q = lin&3;
            size_t gofs = (size_t)(n0+row)*bstrW + kc2 + q*4;
            *(uint4*)&sBh[row*20 + q*4] = *(const uint4*)&Bh[gofs];
            *(uint4*)&sBl[row*20 + q*4] = *(const uint4*)&Bl[gofs];
        }
        __syncthreads();
#pragma unroll
        for (int s = 0; s < 2; s++){
            const int kb = s*8 + tq;
            uint32_t bh0[4], bh1[4], bl0[4], bl1[4];
#pragma unroll
            for (int nt = 0; nt < 4; nt++){
                int nr = warp_n + nt*8 + gid;
                bh0[nt] = sBh[nr*20 + kb]; bh1[nt] = sBh[nr*20 + kb + 4];
                bl0[nt] = sBl[nr*20 + kb]; bl1[nt] = sBl[nr*20 + kb + 4];
            }
#pragma unroll
            for (int mt = 0; mt < 4; mt++){
                int ar = warp_m + mt*16 + gid;
                uint32_t ah0 = sAh[ar*20+kb],     ah1 = sAh[(ar+8)*20+kb];
                uint32_t ah2 = sAh[ar*20+kb+4],   ah3 = sAh[(ar+8)*20+kb+4];
                uint32_t al0 = sAl[ar*20+kb],     al1 = sAl[(ar+8)*20+kb];
                uint32_t al2 = sAl[ar*20+kb+4],   al3 = sAl[(ar+8)*20+kb+4];
#pragma unroll
                for (int nt = 0; nt < 4; nt++){
                    mma_bf16(c[mt][nt][0], c[mt][nt][1], c[mt][nt][2], c[mt][nt][3],
                             ah0, ah1, ah2, ah3, bh0[nt], bh1[nt]);
                    mma_bf16(c[mt][nt][0], c[mt][nt][1], c[mt][nt][2], c[mt][nt][3],
                             ah0, ah1, ah2, ah3, bl0[nt], bl1[nt]);
                    mma_bf16(c[mt][nt][0], c[mt][nt][1], c[mt][nt][2], c[mt][nt][3],
                             al0, al1, al2, al3, bh0[nt], bh1[nt]);
                }
            }
        }
        __syncthreads();
    }

#pragma unroll
    for (int mt = 0; mt < 4; mt++){
        int r0 = m0 + warp_m + mt*16 + gid;
        int r1 = r0 + 8;
#pragma unroll
        for (int nt = 0; nt < 4; nt++){
            int gn = n0 + warp_n + nt*8 + tq*2;
            if (gn >= ncols) continue;
            float bx = 0.f, by = 0.f;
            if (bias){ bx = bias[gn]; by = bias[gn+1]; }
            if (r0 < NN){
                float2 v = make_float2(c[mt][nt][0] + bx, c[mt][nt][1] + by);
                if (base){ float2 b = *(const float2*)&base[(size_t)r0*ostride + gn]; v.x += b.x; v.y += b.y; }
                *(float2*)&out[(size_t)r0*ostride + gn] = v;
            }
            if (r1 < NN){
                float2 v = make_float2(c[mt][nt][2] + bx, c[mt][nt][3] + by);
                if (base){ float2 b = *(const float2*)&base[(size_t)r1*ostride + gn]; v.x += b.x; v.y += b.y; }
                *(float2*)&out[(size_t)r1*ostride + gn] = v;
            }
        }
    }
}

// ---------------- fused node MLP + residual + LN -----------------------------
// tmp = agg @ nW1 + nb1 + x ; node_lat = LN(tmp).  CTA 128x160 (nt=5), K=256.
__global__ __launch_bounds__(256,2) void k_nmlp(
    const float* __restrict__ x, const float* __restrict__ nb1,
    const float* __restrict__ lg, const float* __restrict__ lb,
    int write_fp32)
{
    __shared__ uint32_t sAh[128*20], sAl[128*20], sBh[160*20], sBl[160*20];
    __shared__ float sSum[128], sSq[128], sMu[128], sInv[128];
    const int tid = threadIdx.x, wid = tid>>5, lane = tid&31;
    const int gid = lane>>2, tq = lane&3;
    const int warp_m = (wid & 1)*64, warp_n = (wid >> 1)*40;
    const int m0 = blockIdx.x*128;

    if (tid < 128){ sSum[tid] = 0.f; sSq[tid] = 0.f; }

    float c[4][5][4];
#pragma unroll
    for (int i = 0; i < 4; i++)
#pragma unroll
        for (int j = 0; j < 5; j++)
#pragma unroll
            for (int r = 0; r < 4; r++) c[i][j][r] = 0.f;

    for (int ch = 0; ch < 8; ch++){
        const int kc2 = ch*16;
#pragma unroll
        for (int p = 0; p < 2; p++){
            int lin = tid + p*256;
            int row = lin>>2, q = lin&3;
            int gm = m0 + row;
            uint4 vh = make_uint4(0u,0u,0u,0u), vl = make_uint4(0u,0u,0u,0u);
            if (gm < NN){
                size_t g = (size_t)gm*128 + kc2 + q*4;
                vh = *(const uint4*)&gAGh[g];
                vl = *(const uint4*)&gAGl[g];
            }
            *(uint4*)&sAh[row*20 + q*4] = vh;
            *(uint4*)&sAl[row*20 + q*4] = vl;
        }
        for (int lin = tid; lin < 640; lin += 256){
            int row = lin>>2, q = lin&3;
            size_t gofs = (size_t)row*128 + kc2 + q*4;
            *(uint4*)&sBh[row*20 + q*4] = *(const uint4*)&gWNh[gofs];
            *(uint4*)&sBl[row*20 + q*4] = *(const uint4*)&gWNl[gofs];
        }
        __syncthreads();
#pragma unroll
        for (int s = 0; s < 2; s++){
            const int kb = s*8 + tq;
            uint32_t bh0[5], bh1[5], bl0[5], bl1[5];
#pragma unroll
            for (int nt = 0; nt < 5; nt++){
                int nr = warp_n + nt*8 + gid;
                bh0[nt] = sBh[nr*20 + kb]; bh1[nt] = sBh[nr*20 + kb + 4];
                bl0[nt] = sBl[nr*20 + kb]; bl1[nt] = sBl[nr*20 + kb + 4];
            }
#pragma unroll
            for (int mt = 0; mt < 4; mt++){
                int ar = warp_m + mt*16 + gid;
                uint32_t ah0 = sAh[ar*20+kb],     ah1 = sAh[(ar+8)*20+kb];
                uint32_t ah2 = sAh[ar*20+kb+4],   ah3 = sAh[(ar+8)*20+kb+4];
                uint32_t al0 = sAl[ar*20+kb],     al1 = sAl[(ar+8)*20+kb];
                uint32_t al2 = sAl[ar*20+kb+4],   al3 = sAl[(ar+8)*20+kb+4];
#pragma unroll
                for (int nt = 0; nt < 5; nt++){
                    mma_bf16(c[mt][nt][0], c[mt][nt][1], c[mt][nt][2], c[mt][nt][3],
                             ah0, ah1, ah2, ah3, bh0[nt], bh1[nt]);
                    mma_bf16(c[mt][nt][0], c[mt][nt][1], c[mt][nt][2], c[mt][nt][3],
                             ah0, ah1, ah2, ah3, bl0[nt], bl1[nt]);
                    mma_bf16(c[mt][nt][0], c[mt][nt][1], c[mt][nt][2], c[mt][nt][3],
                             al0, al1, al2, al3, bh0[nt], bh1[nt]);
                }
            }
        }
        __syncthreads();
    }

    // epilogue: v = c + nb1 + x; row LN stats via smem atomics
#pragma unroll
    for (int mt = 0; mt < 4; mt++){
        int r0 = m0 + warp_m + mt*16 + gid;
        int r1 = r0 + 8;
        float s0 = 0.f, q0 = 0.f, s1 = 0.f, q1 = 0.f;
#pragma unroll
        for (int nt = 0; nt < 5; nt++){
            int gn = warp_n + nt*8 + tq*2;
            float bx = nb1[gn], by = nb1[gn+1];
            float x00 = 0.f, x01 = 0.f, x10 = 0.f, x11 = 0.f;
            if (r0 < NN){ float2 xv = *(const float2*)&x[(size_t)r0*ND + gn]; x00 = xv.x; x01 = xv.y; }
            if (r1 < NN){ float2 xv = *(const float2*)&x[(size_t)r1*ND + gn]; x10 = xv.x; x11 = xv.y; }
            float v0 = c[mt][nt][0] + bx + x00;
            float v1 = c[mt][nt][1] + by + x01;
            float v2 = c[mt][nt][2] + bx + x10;
            float v3 = c[mt][nt][3] + by + x11;
            c[mt][nt][0] = v0; c[mt][nt][1] = v1;
            c[mt][nt][2] = v2; c[mt][nt][3] = v3;
            s0 += v0 + v1; q0 += v0*v0 + v1*v1;
            s1 += v2 + v3; q1 += v2*v2 + v3*v3;
        }
        atomicAdd(&sSum[warp_m + mt*16 + gid],     s0);
        atomicAdd(&sSq [warp_m + mt*16 + gid],     q0);
        atomicAdd(&sSum[warp_m + mt*16 + gid + 8], s1);
        atomicAdd(&sSq [warp_m + mt*16 + gid + 8], q1);
    }
    __syncthreads();
    if (tid < 128){
        float mu = sSum[tid] * (1.f/ND);
        float var = sSq[tid] * (1.f/ND) - mu*mu;
        sMu[tid] = mu;
        sInv[tid] = rsqrtf(var + 1e-5f);
    }
    __syncthreads();

#pragma unroll
    for (int mt = 0; mt < 4; mt++){
        int lr0 = warp_m + mt*16 + gid, lr1 = lr0 + 8;
        int r0 = m0 + lr0, r1 = m0 + lr1;
        float mu0 = sMu[lr0], iv0 = sInv[lr0];
        float mu1 = sMu[lr1], iv1 = sInv[lr1];
#pragma unroll
        for (int nt = 0; nt < 5; nt++){
            int gn = warp_n + nt*8 + tq*2;
            float g0 = lg[gn], g1 = lg[gn+1], b0 = lb[gn], b1 = lb[gn+1];
            float o0 = (c[mt][nt][0]-mu0)*iv0*g0 + b0;
            float o1 = (c[mt][nt][1]-mu0)*iv0*g1 + b1;
            float o2 = (c[mt][nt][2]-mu1)*iv1*g0 + b0;
            float o3 = (c[mt][nt][3]-mu1)*iv1*g1 + b1;
            if (write_fp32){
                if (r0 < NN) *(float2*)&g_node_lat[(size_t)r0*ND + gn] = make_float2(o0, o1);
                if (r1 < NN) *(float2*)&g_node_lat[(size_t)r1*ND + gn] = make_float2(o2, o3);
            } else {
                int q = gn >> 1;
                if (r0 < NN) split2(o0, o1, gNLh[(size_t)r0*80 + q], gNLl[(size_t)r0*80 + q]);
                if (r1 < NN) split2(o2, o3, gNLh[(size_t)r1*80 + q], gNLl[(size_t)r1*80 + q]);
            }
        }
    }
}

// ---------------- fused edge kernel: ldmatrix A-operands ---------------------
__global__ __launch_bounds__(512,1) void k_edge_tc(
    const int* __restrict__ row, const int* __restrict__ col,
    const float* __restrict__ eb1, const float* __restrict__ eb2,
    const float* __restrict__ mb1, const float* __restrict__ attv,
    const float* __restrict__ lgE, const float* __restrict__ lbE)
{
    extern __shared__ uint32_t esm[];
    uint32_t* Ah  = esm;              // [128][68]
    uint32_t* Al  = esm + 8704;
    uint32_t* B1h = esm + 17408;      // [256][20]
    uint32_t* B1l = esm + 22528;
    uint32_t* Hh  = esm;              // [128][132] overlay (phase2)
    uint32_t* Hl  = esm + 16896;
    uint32_t* B2h = esm + 33792;      // [64][36]
    uint32_t* B2l = esm + 36096;
    uint32_t* NEh = esm;              // [128][36] overlay
    uint32_t* NEl = esm + 4608;
    uint32_t* B3h = esm + 9216;       // [256][36]
    uint32_t* B3l = esm + 18432;
    __shared__ int sR[128], sC[128];
    __shared__ float sAtt[256];
    __shared__ float sLog[128];
    __shared__ float sSum[128], sSq[128], sMu[128], sInv[128];

    const int tid = threadIdx.x, wid = tid>>5, lane = tid&31;
    const int gid = lane>>2, tq = lane&3;
    const int warp_m  = (wid & 1)*64;
    const int warp_n  = (wid >> 1)*32;
    const int warp_n2 = (wid >> 1)*8;
    const int e0 = blockIdx.x*128;

    const int lrow = lane & 15;
    const int lkh  = (lane >> 4) << 2;
    const uint32_t aAh = (uint32_t)__cvta_generic_to_shared(Ah);
    const uint32_t aAl = (uint32_t)__cvta_generic_to_shared(Al);
    const uint32_t aHh = (uint32_t)__cvta_generic_to_shared(Hh);
    const uint32_t aHl = (uint32_t)__cvta_generic_to_shared(Hl);
    const uint32_t aNh = (uint32_t)__cvta_generic_to_shared(NEh);
    const uint32_t aNl = (uint32_t)__cvta_generic_to_shared(NEl);
    uint32_t offA[4], offH[4], offN[4];
#pragma unroll
    for (int mt = 0; mt < 4; mt++){
        int r = warp_m + mt*16 + lrow;
        offA[mt] = (uint32_t)((r*68  + lkh) * 4);
        offH[mt] = (uint32_t)((r*132 + lkh) * 4);
        offN[mt] = (uint32_t)((r*36  + lkh) * 4);
    }

    if (tid < 128){
        int ge = e0 + tid;
        sR[tid] = (ge < NE) ? row[ge] : 0;
        sC[tid] = (ge < NE) ? col[ge] : 0;
        sLog[tid] = 0.f; sSum[tid] = 0.f; sSq[tid] = 0.f;
    }
    if (tid < 256) sAtt[tid] = attv[tid];
    __syncthreads();

    // ---- phase 1 ------------------------------------------------------------
    for (int lin = tid; lin < 8192; lin += 512){
        int r = lin>>6, w = lin&63, k = w*2;
        float2 v = make_float2(0.f, 0.f);
        if (e0 + r < NE)
            v = (k < 64) ? *(const float2*)&g_init_edge[(size_t)(e0+r)*ED + k]
                         : *(const float2*)&g_edge_lat [(size_t)(e0+r)*ED + (k-64)];
        split2(v.x, v.y, Ah[r*68+w], Al[r*68+w]);
    }
    float c1[4][4][4];
#pragma unroll
    for (int mt = 0; mt < 4; mt++){
        int rA = warp_m + mt*16 + gid, rB = rA + 8;
        size_t prA = (size_t)sR[rA]*768, pcA = (size_t)sC[rA]*768;
        size_t prB = (size_t)sR[rB]*768, pcB = (size_t)sC[rB]*768;
#pragma unroll
        for (int nt = 0; nt < 4; nt++){
            int cn = warp_n + nt*8 + tq*2;
            float2 b  = *(const float2*)&eb1[cn];
            float2 a1 = *(const float2*)&g_P[prA + cn];
            float2 a2 = *(const float2*)&g_P[pcA + 256 + cn];
            float2 a3 = *(const float2*)&g_P[prB + cn];
            float2 a4 = *(const float2*)&g_P[pcB + 256 + cn];
            c1[mt][nt][0] = a1.x + a2.x + b.x;
            c1[mt][nt][1] = a1.y + a2.y + b.y;
            c1[mt][nt][2] = a3.x + a4.x + b.x;
            c1[mt][nt][3] = a3.y + a4.y + b.y;
        }
    }
    __syncthreads();

#pragma unroll
    for (int ch = 0; ch < 4; ch++){
        for (int lin = tid; lin < 1024; lin += 512){
            int r = lin>>2, q = lin&3;
            size_t gofs = (size_t)r*64 + ch*16 + q*4;
            *(uint4*)&B1h[r*20 + q*4] = *(const uint4*)&gB1h[gofs];
            *(uint4*)&B1l[r*20 + q*4] = *(const uint4*)&gB1l[gofs];
        }
        __syncthreads();
#pragma unroll
        for (int s = 0; s < 2; s++){
            int kb = s*8 + tq;
            uint32_t kw = (uint32_t)((ch*16 + s*8) * 4);
            uint32_t bh0[4], bh1[4], bl0[4], bl1[4];
#pragma unroll
            for (int nt = 0; nt < 4; nt++){
                int nr = warp_n + nt*8 + gid;
                bh0[nt] = B1h[nr*20+kb]; bh1[nt] = B1h[nr*20+kb+4];
                bl0[nt] = B1l[nr*20+kb]; bl1[nt] = B1l[nr*20+kb+4];
            }
#pragma unroll
            for (int mt = 0; mt < 4; mt++){
                uint32_t ah0,ah1,ah2,ah3, al0,al1,al2,al3;
                ldsm_x4(ah0,ah1,ah2,ah3, aAh + offA[mt] + kw);
                ldsm_x4(al0,al1,al2,al3, aAl + offA[mt] + kw);
#pragma unroll
                for (int nt = 0; nt < 4; nt++){
                    mma_bf16(c1[mt][nt][0],c1[mt][nt][1],c1[mt][nt][2],c1[mt][nt][3],
                             ah0,ah1,ah2,ah3, bh0[nt],bh1[nt]);
                    mma_bf16(c1[mt][nt][0],c1[mt][nt][1],c1[mt][nt][2],c1[mt][nt][3],
                             ah0,ah1,ah2,ah3, bl0[nt],bl1[nt]);
                    mma_bf16(c1[mt][nt][0],c1[mt][nt][1],c1[mt][nt][2],c1[mt][nt][3],
                             al0,al1,al2,al3, bh0[nt],bh1[nt]);
                }
            }
        }
        __syncthreads();
    }

    // write hidden (relu, bf16 split) over A/B1 region
#pragma unroll
    for (int mt = 0; mt < 4; mt++){
        int rA = warp_m + mt*16 + gid, rB = rA + 8;
#pragma unroll
        for (int nt = 0; nt < 4; nt++){
            int wcol = (warp_n>>1) + nt*4 + tq;
            float v0 = fmaxf(c1[mt][nt][0], 0.f), v1 = fmaxf(c1[mt][nt][1], 0.f);
            float v2 = fmaxf(c1[mt][nt][2], 0.f), v3 = fmaxf(c1[mt][nt][3], 0.f);
            split2(v0, v1, Hh[rA*132+wcol], Hl[rA*132+wcol]);
            split2(v2, v3, Hh[rB*132+wcol], Hl[rB*132+wcol]);
        }
    }
    __syncthreads();

    // ---- phase 2 ------------------------------------------------------------
    float c2[4][4];
#pragma unroll
    for (int mt = 0; mt < 4; mt++){
        float2 b = *(const float2*)&eb2[warp_n2 + tq*2];
        c2[mt][0] = b.x; c2[mt][1] = b.y; c2[mt][2] = b.x; c2[mt][3] = b.y;
    }
#pragma unroll
    for (int ch = 0; ch < 4; ch++){
        {
            int r = tid>>3, q = tid&7;
            size_t gofs = (size_t)r*128 + ch*32 + q*4;
            *(uint4*)&B2h[r*36 + q*4] = *(const uint4*)&gB2h[gofs];
            *(uint4*)&B2l[r*36 + q*4] = *(const uint4*)&gB2l[gofs];
        }
        __syncthreads();
#pragma unroll
        for (int s = 0; s < 4; s++){
            int kb = s*8 + tq;
            uint32_t kw = (uint32_t)((ch*32 + s*8) * 4);
            int nr = warp_n2 + gid;
            uint32_t bh0 = B2h[nr*36+kb], bh1 = B2h[nr*36+kb+4];
            uint32_t bl0 = B2l[nr*36+kb], bl1 = B2l[nr*36+kb+4];
#pragma unroll
            for (int mt = 0; mt < 4; mt++){
                uint32_t ah0,ah1,ah2,ah3, al0,al1,al2,al3;
                ldsm_x4(ah0,ah1,ah2,ah3, aHh + offH[mt] + kw);
                ldsm_x4(al0,al1,al2,al3, aHl + offH[mt] + kw);
                mma_bf16(c2[mt][0],c2[mt][1],c2[mt][2],c2[mt][3], ah0,ah1,ah2,ah3, bh0,bh1);
                mma_bf16(c2[mt][0],c2[mt][1],c2[mt][2],c2[mt][3], ah0,ah1,ah2,ah3, bl0,bl1);
                mma_bf16(c2[mt][0],c2[mt][1],c2[mt][2],c2[mt][3], al0,al1,al2,al3, bh0,bh1);
            }
        }
        __syncthreads();
    }

    // ---- NE pack + LN stats; stage full B3 (stride 36) -----------------------
#pragma unroll
    for (int mt = 0; mt < 4; mt++){
        int rA = warp_m + mt*16 + gid, rB = rA + 8;
        int cn = warp_n2 + tq*2;
        int wcol = (warp_n2>>1) + tq;
        split2(c2[mt][0], c2[mt][1], NEh[rA*36+wcol], NEl[rA*36+wcol]);
        split2(c2[mt][2], c2[mt][3], NEh[rB*36+wcol], NEl[rB*36+wcol]);
        float2 iA = make_float2(0.f,0.f), iB = make_float2(0.f,0.f);
        if (e0 + rA < NE) iA = *(const float2*)&g_init_edge[(size_t)(e0+rA)*ED + cn];
        if (e0 + rB < NE) iB = *(const float2*)&g_init_edge[(size_t)(e0+rB)*ED + cn];
        c2[mt][0] += iA.x; c2[mt][1] += iA.y;
        c2[mt][2] += iB.x; c2[mt][3] += iB.y;
        atomicAdd(&sSum[rA], c2[mt][0] + c2[mt][1]);
        atomicAdd(&sSq [rA], c2[mt][0]*c2[mt][0] + c2[mt][1]*c2[mt][1]);
        atomicAdd(&sSum[rB], c2[mt][2] + c2[mt][3]);
        atomicAdd(&sSq [rB], c2[mt][2]*c2[mt][2] + c2[mt][3]*c2[mt][3]);
    }
    for (int lin = tid; lin < 2048; lin += 512){
        int r = lin>>3, q = lin&7;
        size_t gofs = (size_t)r*32 + q*4;
        *(uint4*)&B3h[r*36 + q*4] = *(const uint4*)&gB3h[gofs];
        *(uint4*)&B3l[r*36 + q*4] = *(const uint4*)&gB3l[gofs];
    }
    float c3[4][4][4];
#pragma unroll
    for (int mt = 0; mt < 4; mt++){
        int rA = warp_m + mt*16 + gid, rB = rA + 8;
        size_t pcA = (size_t)sC[rA]*768, pcB = (size_t)sC[rB]*768;
#pragma unroll
        for (int nt = 0; nt < 4; nt++){
            int cn = warp_n + nt*8 + tq*2;
            float2 b  = *(const float2*)&mb1[cn];
            float2 a1 = *(const float2*)&g_P[pcA + 512 + cn];
            float2 a2 = *(const float2*)&g_P[pcB + 512 + cn];
            c3[mt][nt][0] = a1.x + b.x; c3[mt][nt][1] = a1.y + b.y;
            c3[mt][nt][2] = a2.x + b.x; c3[mt][nt][3] = a2.y + b.y;
        }
    }
    __syncthreads();

    if (tid < 128){
        float mu = sSum[tid] * (1.f/ED);
        float var = sSq[tid] * (1.f/ED) - mu*mu;
        sMu[tid] = mu;
        sInv[tid] = rsqrtf(var + 1e-5f);
    }
    __syncthreads();

#pragma unroll
    for (int mt = 0; mt < 4; mt++){
        int rA = warp_m + mt*16 + gid, rB = rA + 8;
        int cn = warp_n2 + tq*2;
        float g0 = lgE[cn], g1 = lgE[cn+1], b0 = lbE[cn], b1 = lbE[cn+1];
        if (e0 + rA < NE){
            float mu = sMu[rA], inv = sInv[rA];
            *(float2*)&g_edge_lat[(size_t)(e0+rA)*ED + cn] =
                make_float2((c2[mt][0]-mu)*inv*g0 + b0, (c2[mt][1]-mu)*inv*g1 + b1);
        }
        if (e0 + rB < NE){
            float mu = sMu[rB], inv = sInv[rB];
            *(float2*)&g_edge_lat[(size_t)(e0+rB)*ED + cn] =
                make_float2((c2[mt][2]-mu)*inv*g0 + b0, (c2[mt][3]-mu)*inv*g1 + b1);
        }
    }

    // ---- phase 3 MMA loop ----------------------------------------------------
#pragma unroll
    for (int s = 0; s < 4; s++){
        int ka = s*8 + tq;
        uint32_t kw = (uint32_t)((s*8) * 4);
        uint32_t bh0[4], bh1[4], bl0[4], bl1[4];
#pragma unroll
        for (int nt = 0; nt < 4; nt++){
            int nr = warp_n + nt*8 + gid;
            bh0[nt] = B3h[nr*36+ka]; bh1[nt] = B3h[nr*36+ka+4];
            bl0[nt] = B3l[nr*36+ka]; bl1[nt] = B3l[nr*36+ka+4];
        }
#pragma unroll
        for (int mt = 0; mt < 4; mt++){
            uint32_t ah0,ah1,ah2,ah3, al0,al1,al2,al3;
            ldsm_x4(ah0,ah1,ah2,ah3, aNh + offN[mt] + kw);
            ldsm_x4(al0,al1,al2,al3, aNl + offN[mt] + kw);
#pragma unroll
            for (int nt = 0; nt < 4; nt++){
                mma_bf16(c3[mt][nt][0],c3[mt][nt][1],c3[mt][nt][2],c3[mt][nt][3],
                         ah0,ah1,ah2,ah3, bh0[nt],bh1[nt]);
                mma_bf16(c3[mt][nt][0],c3[mt][nt][1],c3[mt][nt][2],c3[mt][nt][3],
                         ah0,ah1,ah2,ah3, bl0[nt],bl1[nt]);
                mma_bf16(c3[mt][nt][0],c3[mt][nt][1],c3[mt][nt][2],c3[mt][nt][3],
                         al0,al1,al2,al3, bh0[nt],bh1[nt]);
            }
        }
    }

    // epilogue: relu -> g_msg, attention partial dot, logit
    float pa[4][2];
#pragma unroll
    for (int mt = 0; mt < 4; mt++){ pa[mt][0] = 0.f; pa[mt][1] = 0.f; }
#pragma unroll
    for (int mt = 0; mt < 4; mt++){
        int rA = warp_m + mt*16 + gid, rB = rA + 8;
#pragma unroll
        for (int nt = 0; nt < 4; nt++){
            int cn = warp_n + nt*8 + tq*2;
            float av0 = sAtt[cn], av1 = sAtt[cn+1];
            float v0 = fmaxf(c3[mt][nt][0], 0.f), v1 = fmaxf(c3[mt][nt][1], 0.f);
            float v2 = fmaxf(c3[mt][nt][2], 0.f), v3 = fmaxf(c3[mt][nt][3], 0.f);
            if (e0 + rA < NE)
                *(float2*)&g_msg[(size_t)(e0+rA)*HD + cn] = make_float2(v0, v1);
            if (e0 + rB < NE)
                *(float2*)&g_msg[(size_t)(e0+rB)*HD + cn] = make_float2(v2, v3);
            pa[mt][0] += v0*av0 + v1*av1;
            pa[mt][1] += v2*av0 + v3*av1;
        }
    }
#pragma unroll
    for (int off = 1; off <= 2; off <<= 1){
#pragma unroll
        for (int mt = 0; mt < 4; mt++){
            pa[mt][0] += __shfl_xor_sync(0xffffffffu, pa[mt][0], off, 4);
            pa[mt][1] += __shfl_xor_sync(0xffffffffu, pa[mt][1], off, 4);
        }
    }
    if (tq == 0){
#pragma unroll
        for (int mt = 0; mt < 4; mt++){
            atomicAdd(&sLog[warp_m + mt*16 + gid],     pa[mt][0]);
            atomicAdd(&sLog[warp_m + mt*16 + gid + 8], pa[mt][1]);
        }
    }
    __syncthreads();
    if (tid < 128 && e0 + tid < NE){
        float p = sLog[tid];
        g_logit[e0+tid] = (p > 0.f) ? p : 0.2f*p;
    }
}

// ---------------- edge encoder tail (dual-writes init_edge + edge_lat) -------
__global__ __launch_bounds__(256,2) void k_enc_edge(
    const float* __restrict__ ea,
    const int* __restrict__ row, const int* __restrict__ col,
    const float* __restrict__ encW1, const float* __restrict__ encb1,
    const float* __restrict__ encW2, const float* __restrict__ encb2)
{
    __shared__ float As[64*9];
    __shared__ float Bs[16*64];
    __shared__ float Hid[64*132];
    __shared__ int sR[64], sC[64];

    const int e0 = blockIdx.x*64;
    const int tid = threadIdx.x, ty = tid>>4, tx = tid&15;
    if (tid < 64){ sR[tid] = row[e0+tid]; sC[tid] = col[e0+tid]; }
    __syncthreads();

    float c[4][8];
#pragma unroll
    for (int i = 0; i < 4; i++){
        int r = ty*4+i;
#pragma unroll
        for (int j = 0; j < 8; j++){
            int n = tx + 16*j;
            c[i][j] = g_Penc[(size_t)sR[r]*256 + n]
                    + g_Penc[(size_t)sC[r]*256 + 128 + n]
                    + encb1[n];
        }
    }
    for (int t = tid; t < 512; t += 256){
        int el = t>>3, kk = t&7;
        As[el*9+kk] = ea[(e0+el)*RD + kk];
    }
    for (int t = tid; t < 1024; t += 256){
        int kk = t>>7, n = t&127;
        Bs[t] = encW1[(320+kk)*EH + n];
    }
    __syncthreads();
#pragma unroll
    for (int kk = 0; kk < 8; kk++){
        float a0 = As[(ty*4+0)*9+kk], a1 = As[(ty*4+1)*9+kk];
        float a2 = As[(ty*4+2)*9+kk], a3 = As[(ty*4+3)*9+kk];
#pragma unroll
        for (int j = 0; j < 8; j++){
            float b = Bs[kk*128 + tx + 16*j];
            c[0][j] += a0*b; c[1][j] += a1*b; c[2][j] += a2*b; c[3][j] += a3*b;
        }
    }
    __syncthreads();
#pragma unroll
    for (int i = 0; i < 4; i++)
#pragma unroll
        for (int j = 0; j < 8; j++){
            int n = tx + 16*j;
            Hid[(ty*4+i)*132 + n] = fmaxf(c[i][j], 0.f);
        }
    __syncthreads();

    float c2[4][4];
#pragma unroll
    for (int i = 0; i < 4; i++)
#pragma unroll
        for (int j = 0; j < 4; j++) c2[i][j] = encb2[tx+16*j];

    for (int kc = 0; kc < 128; kc += 16){
        for (int t = tid; t < 1024; t += 256){
            int kk = t>>6, n = t&63;
            Bs[t] = encW2[(kc+kk)*ED + n];
        }
        __syncthreads();
#pragma unroll
        for (int kk = 0; kk < 16; kk++){
            float a0 = Hid[(ty*4+0)*132 + kc+kk], a1 = Hid[(ty*4+1)*132 + kc+kk];
            float a2 = Hid[(ty*4+2)*132 + kc+kk], a3 = Hid[(ty*4+3)*132 + kc+kk];
#pragma unroll
            for (int j = 0; j < 4; j++){
                float b = Bs[kk*64 + tx + 16*j];
                c2[0][j] += a0*b; c2[1][j] += a1*b; c2[2][j] += a2*b; c2[3][j] += a3*b;
            }
        }
        __syncthreads();
    }
#pragma unroll
    for (int i = 0; i < 4; i++)
#pragma unroll
        for (int j = 0; j < 4; j++){
            size_t o = (size_t)(e0+ty*4+i)*ED + tx + 16*j;
            g_init_edge[o] = c2[i][j];
            g_edge_lat[o]  = c2[i][j];
        }
}

// ---------------- k_agg: segment softmax + aggregation -> packed bf16 --------
__global__ __launch_bounds__(256,2) void k_agg()
{
    __shared__ float agg[16*260];

    const int n0 = blockIdx.x*16;
    const int tid = threadIdx.x, g = tid>>4, t = tid&15;
    const int n = n0 + g;
    const int beg = g_rowptr[n], end = g_rowptr[n+1];

    float m = -1e30f;
    for (int i = beg+t; i < end; i += 16) m = fmaxf(m, g_logit[g_eids[i]]);
#pragma unroll
    for (int off = 8; off >= 1; off >>= 1) m = fmaxf(m, __shfl_xor_sync(0xffffffffu, m, off, 16));

    float den = 0.f;
    for (int i = beg+t; i < end; i += 16) den += expf(g_logit[g_eids[i]] - m);
#pragma unroll
    for (int off = 8; off >= 1; off >>= 1) den += __shfl_xor_sync(0xffffffffu, den, off, 16);
    den += 1e-16f;
    float inv_den = 1.f/den;

    float acc[16];
#pragma unroll
    for (int q = 0; q < 16; q++) acc[q] = 0.f;
    for (int i = beg; i < end; i++){
        int e = g_eids[i];
        float w = expf(g_logit[e] - m) * inv_den;
        const float* mr = g_msg + (size_t)e*HD;
#pragma unroll
        for (int q = 0; q < 16; q++) acc[q] += w * mr[t + 16*q];
    }
#pragma unroll
    for (int q = 0; q < 16; q++) agg[g*260 + t + 16*q] = acc[q];
    __syncthreads();

    for (int i = tid; i < 2048; i += 256){
        int gg = i >> 7, q = i & 127;
        split2(agg[gg*260 + 2*q], agg[gg*260 + 2*q + 1],
               gAGh[(size_t)(n0+gg)*128 + q], gAGl[(size_t)(n0+gg)*128 + q]);
    }
}

// ---------------- launch -----------------------------------------------------
extern "C" void kernel_launch(void* const* d_in, const int* in_sizes, int n_in,
                              void* d_out, int out_size)
{
    const float* x     = (const float*)d_in[0];
    const float* ea    = (const float*)d_in[1];
    const float* encW1 = (const float*)d_in[2];
    const float* encb1 = (const float*)d_in[3];
    const float* encW2 = (const float*)d_in[4];
    const float* encb2 = (const float*)d_in[5];
    const float* eW1   = (const float*)d_in[6];
    const float* eb1   = (const float*)d_in[7];
    const float* eW2   = (const float*)d_in[8];
    const float* eb2   = (const float*)d_in[9];
    const float* mW1   = (const float*)d_in[10];
    const float* mb1   = (const float*)d_in[11];
    const float* attv  = (const float*)d_in[12];
    const float* nW1   = (const float*)d_in[13];
    const float* nb1   = (const float*)d_in[14];
    const float* ln_ng = (const float*)d_in[15];
    const float* ln_nb = (const float*)d_in[16];
    const float* ln_eg = (const float*)d_in[17];
    const float* ln_eb = (const float*)d_in[18];
    const int*   erow  = (const int*)d_in[19];
    const int*   ecol  = (const int*)d_in[20];

    void *p_deg, *p_rowptr, *p_fill, *p_node, *p_edge, *p_P, *p_Pbase, *p_Penc;
    void *p_WEh, *p_WEl, *p_WPh, *p_WPl;
    void *p_Xh, *p_Xl, *p_NLh, *p_NLl;
    cudaGetSymbolAddress(&p_deg,    g_deg);
    cudaGetSymbolAddress(&p_rowptr, g_rowptr);
    cudaGetSymbolAddress(&p_fill,   g_fill);
    cudaGetSymbolAddress(&p_node,   g_node_lat);
    cudaGetSymbolAddress(&p_edge,   g_edge_lat);
    cudaGetSymbolAddress(&p_P,      g_P);
    cudaGetSymbolAddress(&p_Pbase,  g_Pbase);
    cudaGetSymbolAddress(&p_Penc,   g_Penc);
    cudaGetSymbolAddress(&p_WEh,    gWEh);
    cudaGetSymbolAddress(&p_WEl,    gWEl);
    cudaGetSymbolAddress(&p_WPh,    gWPh);
    cudaGetSymbolAddress(&p_WPl,    gWPl);
    cudaGetSymbolAddress(&p_Xh,     gXh);
    cudaGetSymbolAddress(&p_Xl,     gXl);
    cudaGetSymbolAddress(&p_NLh,    gNLh);
    cudaGetSymbolAddress(&p_NLl,    gNLl);

    cudaFuncSetAttribute(k_edge_tc, cudaFuncAttributeMaxDynamicSharedMemorySize, 153600);

    static cudaStream_t s1 = nullptr;
    static cudaEvent_t evA = nullptr, evB = nullptr;
    if (s1 == nullptr){
        cudaStreamCreateWithFlags(&s1, cudaStreamNonBlocking);
        cudaEventCreateWithFlags(&evA, cudaEventDisableTiming);
        cudaEventCreateWithFlags(&evB, cudaEventDisableTiming);
    }

    // fork: CSR build on s1, GEMM prologue on stream 0
    cudaEventRecord(evA, 0);
    cudaStreamWaitEvent(s1, evA, 0);

    cudaMemsetAsync(p_deg, 0, NN*sizeof(int), s1);
    k_hist<<<(NE+255)/256, 256, 0, s1>>>(erow);
    k_scan1<<<49, 256, 0, s1>>>();
    k_scan2<<<1, 32, 0, s1>>>();
    k_scan3<<<(NN+255)/256, 256, 0, s1>>>();
    cudaMemcpyAsync(p_fill, p_rowptr, NN*sizeof(int), cudaMemcpyDeviceToDevice, s1);
    k_scatter<<<(NE+255)/256, 256, 0, s1>>>(erow);

    k_prep<<<480, 256>>>(eW1, mW1, encW1, eW2, nW1);
    k_packA<<<(NN*80+255)/256, 256>>>(x, (uint32_t*)p_Xh, (uint32_t*)p_Xl);
    {
        dim3 g((NN+127)/128, 6);
        k_gemm_bf<<<g, 256>>>((const uint32_t*)p_Xh, (const uint32_t*)p_Xl, 80,
                              (const uint32_t*)p_WPh, (const uint32_t*)p_WPl,
                              160, 160, (float*)p_Pbase, 768, 768, nullptr, nullptr);
    }
    {
        dim3 g((NN+127)/128, 2);
        k_gemm_bf<<<g, 256>>>((const uint32_t*)p_Xh, (const uint32_t*)p_Xl, 80,
                              (const uint32_t*)p_WEh, (const uint32_t*)p_WEl,
                              160, 80, (float*)p_Penc, 256, 256, nullptr, nullptr);
    }
    k_enc_edge<<<NE/64, 256>>>(ea, erow, ecol, encW1, encb1, encW2, encb2);

    cudaEventRecord(evB, s1);
    cudaStreamWaitEvent(0, evB, 0);

    for (int it = 0; it < 3; it++){
        const uint32_t* ah = (it == 0) ? (const uint32_t*)p_Xh : (const uint32_t*)p_NLh;
        const uint32_t* al = (it == 0) ? (const uint32_t*)p_Xl : (const uint32_t*)p_NLl;
        dim3 g((NN+127)/128, 6);
        k_gemm_bf<<<g, 256>>>(ah, al, 80,
                              (const uint32_t*)p_WPh + 80, (const uint32_t*)p_WPl + 80,
                              160, 160, (float*)p_P, 768, 768, (const float*)p_Pbase, nullptr);
        k_edge_tc<<<(NE+127)/128, 512, 153600>>>(erow, ecol, eb1, eb2, mb1, attv, ln_eg, ln_eb);
        k_agg<<<NN/16, 256>>>();
        k_nmlp<<<(NN+127)/128, 256>>>(x, nb1, ln_ng, ln_nb, (it == 2) ? 1 : 0);
    }

    float* out = (float*)d_out;
    if (out_size >= NN*ND + NE*ED){
        cudaMemcpyAsync(out,         p_node, (size_t)NN*ND*sizeof(float), cudaMemcpyDeviceToDevice, 0);
        cudaMemcpyAsync(out + NN*ND, p_edge, (size_t)NE*ED*sizeof(float), cudaMemcpyDeviceToDevice, 0);
    } else if (out_size == NN*ND){
        cudaMemcpyAsync(out, p_node, (size_t)NN*ND*sizeof(float), cudaMemcpyDeviceToDevice, 0);
    } else {
        size_t nel = (size_t)((out_size < NE*ED) ? out_size : NE*ED);
        cudaMemcpyAsync(out, p_edge, nel*sizeof(float), cudaMemcpyDeviceToDevice, 0);
    }
}

// round 16
// speedup vs baseline: 1.1827x; 1.0199x over previous
#include <cuda_runtime.h>
#include <cuda_bf16.h>
#include <math.h>
#include <stdint.h>

#define NN 50000
#define NE 200000
#define ND 160
#define ED 64
#define RD 8
#define HD 256
#define EH 128

// ---------------- scratch (device globals; no runtime allocation) ----------
__device__ float g_init_edge[NE*ED];
__device__ float g_edge_lat [NE*ED];
__device__ float g_node_lat [NN*ND];
__device__ float g_msg      [NE*HD];
__device__ float g_logit    [NE];
__device__ float g_P        [(size_t)NN*768];
__device__ float g_Pbase    [(size_t)NN*768];
__device__ float g_Penc     [(size_t)NN*256];
__device__ uint32_t gWPh[768*160], gWPl[768*160];
__device__ uint32_t gW0h[768*80],  gW0l[768*80];    // combined W_x + W_nl (iter0)
__device__ uint32_t gWEh[256*80],  gWEl[256*80];
__device__ uint32_t gWNh[256*128], gWNl[256*128];   // nW1 K-major (n<160 valid)
__device__ uint32_t gB1h[256*64],  gB1l[256*64];
__device__ uint32_t gB2h[64*128],  gB2l[64*128];
__device__ uint32_t gB3h[256*32],  gB3l[256*32];
__device__ uint32_t gXh[(size_t)NN*80],  gXl[(size_t)NN*80];    // packed x
__device__ uint32_t gNLh[(size_t)NN*80], gNLl[(size_t)NN*80];   // packed node_lat
__device__ uint32_t gAGh[(size_t)NN*128], gAGl[(size_t)NN*128]; // packed agg
__device__ int   g_deg      [NN];
__device__ int   g_rowptr   [NN+1];
__device__ int   g_fill     [NN];
__device__ int   g_eids     [NE];
__device__ int   g_part     [64];

// ---------------- helpers ----------------------------------------------------
__device__ __forceinline__ void split2(float x, float y, uint32_t& hi, uint32_t& lo){
    __nv_bfloat162 h = __floats2bfloat162_rn(x, y);
    hi = *(uint32_t*)&h;
    float rx = x - __bfloat162float(h.x);
    float ry = y - __bfloat162float(h.y);
    __nv_bfloat162 l = __floats2bfloat162_rn(rx, ry);
    lo = *(uint32_t*)&l;
}
__device__ __forceinline__ void mma_bf16(
    float& c0, float& c1, float& c2, float& c3,
    uint32_t a0, uint32_t a1, uint32_t a2, uint32_t a3, uint32_t b0, uint32_t b1)
{
    asm volatile(
        "mma.sync.aligned.m16n8k16.row.col.f32.bf16.bf16.f32 "
        "{%0,%1,%2,%3}, {%4,%5,%6,%7}, {%8,%9}, {%0,%1,%2,%3};"
        : "+f"(c0), "+f"(c1), "+f"(c2), "+f"(c3)
        : "r"(a0), "r"(a1), "r"(a2), "r"(a3), "r"(b0), "r"(b1));
}
__device__ __forceinline__ void ldsm_x4(uint32_t& r0, uint32_t& r1, uint32_t& r2, uint32_t& r3, uint32_t a){
    asm volatile("ldmatrix.sync.aligned.m8n8.x4.shared.b16 {%0,%1,%2,%3}, [%4];"
        : "=r"(r0), "=r"(r1), "=r"(r2), "=r"(r3) : "r"(a));
}

// ---------------- CSR build --------------------------------------------------
__global__ void k_hist(const int* __restrict__ row){
    int e = blockIdx.x*blockDim.x + threadIdx.x;
    if (e < NE) atomicAdd(&g_deg[row[e]], 1);
}

__global__ void k_scan1(){
    __shared__ int ss[256];
    int b = blockIdx.x, base = b*1024, tid = threadIdx.x;
    int v[4], tsum = 0;
#pragma unroll
    for (int r = 0; r < 4; r++){
        int idx = base + tid*4 + r;
        v[r] = (idx < NN) ? g_deg[idx] : 0;
        tsum += v[r];
    }
    ss[tid] = tsum; __syncthreads();
    for (int off = 1; off < 256; off <<= 1){
        int add = (tid >= off) ? ss[tid-off] : 0;
        __syncthreads();
        ss[tid] += add;
        __syncthreads();
    }
    int run = ss[tid] - tsum;
#pragma unroll
    for (int r = 0; r < 4; r++){
        int idx = base + tid*4 + r;
        if (idx < NN) g_rowptr[idx] = run;
        run += v[r];
    }
    if (tid == 255) g_part[b] = ss[255];
}

__global__ void k_scan2(){
    if (threadIdx.x == 0){
        int run = 0;
        for (int i = 0; i < 49; i++){ int t = g_part[i]; g_part[i] = run; run += t; }
    }
}

__global__ void k_scan3(){
    int i = blockIdx.x*blockDim.x + threadIdx.x;
    if (i < NN) g_rowptr[i] += g_part[i >> 10];
    if (i == 0) g_rowptr[NN] = NE;
}

__global__ void k_scatter(const int* __restrict__ row){
    int e = blockIdx.x*blockDim.x + threadIdx.x;
    if (e < NE){
        int p = atomicAdd(&g_fill[row[e]], 1);
        g_eids[p] = e;
    }
}

// ---------------- pack weight tables (bf16 hi/lo, K-major) -------------------
__global__ void k_prep(const float* __restrict__ eW1, const float* __restrict__ mW1,
                       const float* __restrict__ encW1, const float* __restrict__ eW2,
                       const float* __restrict__ nW1)
{
    int i = blockIdx.x*blockDim.x + threadIdx.x;
    if (i < 768*160){
        int n = i/160, w = i - n*160, k = w*2;
        float f0, f1;
        if (n < 256){ f0 = eW1[k*256+n]; f1 = eW1[(k+1)*256+n]; }
        else if (n < 512){ int nn = n-256; f0 = eW1[(320+k)*256+nn]; f1 = eW1[(321+k)*256+nn]; }
        else { int nn = n-512; f0 = mW1[k*256+nn]; f1 = mW1[(k+1)*256+nn]; }
        split2(f0, f1, gWPh[i], gWPl[i]);
    }
    if (i < 768*80){
        // combined W0 = W_x + W_nl (k in [0,160): x row k + nl row k+160)
        int n = i/80, w = i - n*80, k = w*2;
        float f0, f1;
        if (n < 256){
            f0 = eW1[k*256+n]     + eW1[(k+160)*256+n];
            f1 = eW1[(k+1)*256+n] + eW1[(k+161)*256+n];
        } else if (n < 512){
            int nn = n-256;
            f0 = eW1[(320+k)*256+nn]   + eW1[(480+k)*256+nn];
            f1 = eW1[(321+k)*256+nn]   + eW1[(481+k)*256+nn];
        } else {
            int nn = n-512;
            f0 = mW1[k*256+nn]     + mW1[(160+k)*256+nn];
            f1 = mW1[(k+1)*256+nn] + mW1[(161+k)*256+nn];
        }
        split2(f0, f1, gW0h[i], gW0l[i]);
    }
    if (i < 256*80){
        int n = i/80, w = i - n*80, k = w*2;
        float f0, f1;
        if (n < 128){ f0 = encW1[k*128+n]; f1 = encW1[(k+1)*128+n]; }
        else { int nn = n-128; f0 = encW1[(160+k)*128+nn]; f1 = encW1[(161+k)*128+nn]; }
        split2(f0, f1, gWEh[i], gWEl[i]);
    }
    if (i < 256*128){
        int n = i>>7, w = i&127, k = w*2;
        uint32_t hi = 0u, lo = 0u;
        if (n < 160) split2(nW1[k*ND+n], nW1[(k+1)*ND+n], hi, lo);
        gWNh[i] = hi; gWNl[i] = lo;
    }
    if (i < 256*64){
        int n = i/64, w = i - n*64, k = w*2;
        split2(eW1[(640+k)*256+n], eW1[(641+k)*256+n], gB1h[i], gB1l[i]);
    }
    if (i < 64*128){
        int n = i/128, w = i - n*128, k = w*2;
        split2(eW2[k*64+n], eW2[(k+1)*64+n], gB2h[i], gB2l[i]);
    }
    if (i < 256*32){
        int n = i/32, w = i - n*32, k = w*2;
        split2(mW1[(320+k)*256+n], mW1[(321+k)*256+n], gB3h[i], gB3l[i]);
    }
}

// ---------------- pack a [NN,160] fp32 matrix into bf16 hi/lo [NN,80] --------
__global__ void k_packA(const float* __restrict__ src,
                        uint32_t* __restrict__ dh, uint32_t* __restrict__ dl)
{
    int i = blockIdx.x*blockDim.x + threadIdx.x;
    if (i < NN*80){
        int n = i/80, w = i - n*80;
        float2 v = *(const float2*)&src[(size_t)n*ND + 2*w];
        split2(v.x, v.y, dh[i], dl[i]);
    }
}

// ---------------- bf16 3-split dense GEMM (m16n8k16), packed A ---------------
__global__ __launch_bounds__(256,2) void k_gemm_bf(
    const uint32_t* __restrict__ Ah_, const uint32_t* __restrict__ Al_, int astrW,
    const uint32_t* __restrict__ Bh, const uint32_t* __restrict__ Bl,
    int K, int bstrW,
    float* __restrict__ out, int ostride, int ncols,
    const float* __restrict__ base, const float* __restrict__ bias)
{
    __shared__ uint32_t sAh[128*20], sAl[128*20], sBh[128*20], sBl[128*20];
    const int tid = threadIdx.x, wid = tid>>5, lane = tid&31;
    const int gid = lane>>2, tq = lane&3;
    const int warp_m = (wid & 1)*64, warp_n = (wid >> 1)*32;
    const int m0 = blockIdx.x*128, n0 = blockIdx.y*128;

    float c[4][4][4];
#pragma unroll
    for (int i = 0; i < 4; i++)
#pragma unroll
        for (int j = 0; j < 4; j++)
#pragma unroll
            for (int r = 0; r < 4; r++) c[i][j][r] = 0.f;

    const int nk = K >> 5;
    for (int ch = 0; ch < nk; ch++){
        const int kc2 = ch*16;
#pragma unroll
        for (int p = 0; p < 2; p++){
            int lin = tid + p*256;
            int row = lin>>2, q = lin&3;
            int gm = m0 + row;
            uint4 vh = make_uint4(0u,0u,0u,0u), vl = make_uint4(0u,0u,0u,0u);
            if (gm < NN){
                size_t g = (size_t)gm*astrW + kc2 + q*4;
                vh = *(const uint4*)&Ah_[g];
                vl = *(const uint4*)&Al_[g];
            }
            *(uint4*)&sAh[row*20 + q*4] = vh;
            *(uint4*)&sAl[row*20 + q*4] = vl;
        }
#pragma unroll
        for (int p = 0; p < 2; p++){
            int lin = tid + p*256;
            int row = lin>>2, q = lin&3;
            size_t gofs = (size_t)(n0+row)*bstrW + kc2 + q*4;
            *(uint4*)&sBh[row*20 + q*4] = *(const uint4*)&Bh[gofs];
            *(uint4*)&sBl[row*20 + q*4] = *(const uint4*)&Bl[gofs];
        }
        __syncthreads();
#pragma unroll
        for (int s = 0; s < 2; s++){
            const int kb = s*8 + tq;
            uint32_t bh0[4], bh1[4], bl0[4], bl1[4];
#pragma unroll
            for (int nt = 0; nt < 4; nt++){
                int nr = warp_n + nt*8 + gid;
                bh0[nt] = sBh[nr*20 + kb]; bh1[nt] = sBh[nr*20 + kb + 4];
                bl0[nt] = sBl[nr*20 + kb]; bl1[nt] = sBl[nr*20 + kb + 4];
            }
#pragma unroll
            for (int mt = 0; mt < 4; mt++){
                int ar = warp_m + mt*16 + gid;
                uint32_t ah0 = sAh[ar*20+kb],     ah1 = sAh[(ar+8)*20+kb];
                uint32_t ah2 = sAh[ar*20+kb+4],   ah3 = sAh[(ar+8)*20+kb+4];
                uint32_t al0 = sAl[ar*20+kb],     al1 = sAl[(ar+8)*20+kb];
                uint32_t al2 = sAl[ar*20+kb+4],   al3 = sAl[(ar+8)*20+kb+4];
#pragma unroll
                for (int nt = 0; nt < 4; nt++){
                    mma_bf16(c[mt][nt][0], c[mt][nt][1], c[mt][nt][2], c[mt][nt][3],
                             ah0, ah1, ah2, ah3, bh0[nt], bh1[nt]);
                    mma_bf16(c[mt][nt][0], c[mt][nt][1], c[mt][nt][2], c[mt][nt][3],
                             ah0, ah1, ah2, ah3, bl0[nt], bl1[nt]);
                    mma_bf16(c[mt][nt][0], c[mt][nt][1], c[mt][nt][2], c[mt][nt][3],
                             al0, al1, al2, al3, bh0[nt], bh1[nt]);
                }
            }
        }
        __syncthreads();
    }

#pragma unroll
    for (int mt = 0; mt < 4; mt++){
        int r0 = m0 + warp_m + mt*16 + gid;
        int r1 = r0 + 8;
#pragma unroll
        for (int nt = 0; nt < 4; nt++){
            int gn = n0 + warp_n + nt*8 + tq*2;
            if (gn >= ncols) continue;
            float bx = 0.f, by = 0.f;
            if (bias){ bx = bias[gn]; by = bias[gn+1]; }
            if (r0 < NN){
                float2 v = make_float2(c[mt][nt][0] + bx, c[mt][nt][1] + by);
                if (base){ float2 b = *(const float2*)&base[(size_t)r0*ostride + gn]; v.x += b.x; v.y += b.y; }
                *(float2*)&out[(size_t)r0*ostride + gn] = v;
            }
            if (r1 < NN){
                float2 v = make_float2(c[mt][nt][2] + bx, c[mt][nt][3] + by);
                if (base){ float2 b = *(const float2*)&base[(size_t)r1*ostride + gn]; v.x += b.x; v.y += b.y; }
                *(float2*)&out[(size_t)r1*ostride + gn] = v;
            }
        }
    }
}

// ---------------- fused node MLP + residual + LN -----------------------------
__global__ __launch_bounds__(256,2) void k_nmlp(
    const float* __restrict__ x, const float* __restrict__ nb1,
    const float* __restrict__ lg, const float* __restrict__ lb,
    int write_fp32)
{
    __shared__ uint32_t sAh[128*20], sAl[128*20], sBh[160*20], sBl[160*20];
    __shared__ float sSum[128], sSq[128], sMu[128], sInv[128];
    const int tid = threadIdx.x, wid = tid>>5, lane = tid&31;
    const int gid = lane>>2, tq = lane&3;
    const int warp_m = (wid & 1)*64, warp_n = (wid >> 1)*40;
    const int m0 = blockIdx.x*128;

    if (tid < 128){ sSum[tid] = 0.f; sSq[tid] = 0.f; }

    float c[4][5][4];
#pragma unroll
    for (int i = 0; i < 4; i++)
#pragma unroll
        for (int j = 0; j < 5; j++)
#pragma unroll
            for (int r = 0; r < 4; r++) c[i][j][r] = 0.f;

    for (int ch = 0; ch < 8; ch++){
        const int kc2 = ch*16;
#pragma unroll
        for (int p = 0; p < 2; p++){
            int lin = tid + p*256;
            int row = lin>>2, q = lin&3;
            int gm = m0 + row;
            uint4 vh = make_uint4(0u,0u,0u,0u), vl = make_uint4(0u,0u,0u,0u);
            if (gm < NN){
                size_t g = (size_t)gm*128 + kc2 + q*4;
                vh = *(const uint4*)&gAGh[g];
                vl = *(const uint4*)&gAGl[g];
            }
            *(uint4*)&sAh[row*20 + q*4] = vh;
            *(uint4*)&sAl[row*20 + q*4] = vl;
        }
        for (int lin = tid; lin < 640; lin += 256){
            int row = lin>>2, q = lin&3;
            size_t gofs = (size_t)row*128 + kc2 + q*4;
            *(uint4*)&sBh[row*20 + q*4] = *(const uint4*)&gWNh[gofs];
            *(uint4*)&sBl[row*20 + q*4] = *(const uint4*)&gWNl[gofs];
        }
        __syncthreads();
#pragma unroll
        for (int s = 0; s < 2; s++){
            const int kb = s*8 + tq;
            uint32_t bh0[5], bh1[5], bl0[5], bl1[5];
#pragma unroll
            for (int nt = 0; nt < 5; nt++){
                int nr = warp_n + nt*8 + gid;
                bh0[nt] = sBh[nr*20 + kb]; bh1[nt] = sBh[nr*20 + kb + 4];
                bl0[nt] = sBl[nr*20 + kb]; bl1[nt] = sBl[nr*20 + kb + 4];
            }
#pragma unroll
            for (int mt = 0; mt < 4; mt++){
                int ar = warp_m + mt*16 + gid;
                uint32_t ah0 = sAh[ar*20+kb],     ah1 = sAh[(ar+8)*20+kb];
                uint32_t ah2 = sAh[ar*20+kb+4],   ah3 = sAh[(ar+8)*20+kb+4];
                uint32_t al0 = sAl[ar*20+kb],     al1 = sAl[(ar+8)*20+kb];
                uint32_t al2 = sAl[ar*20+kb+4],   al3 = sAl[(ar+8)*20+kb+4];
#pragma unroll
                for (int nt = 0; nt < 5; nt++){
                    mma_bf16(c[mt][nt][0], c[mt][nt][1], c[mt][nt][2], c[mt][nt][3],
                             ah0, ah1, ah2, ah3, bh0[nt], bh1[nt]);
                    mma_bf16(c[mt][nt][0], c[mt][nt][1], c[mt][nt][2], c[mt][nt][3],
                             ah0, ah1, ah2, ah3, bl0[nt], bl1[nt]);
                    mma_bf16(c[mt][nt][0], c[mt][nt][1], c[mt][nt][2], c[mt][nt][3],
                             al0, al1, al2, al3, bh0[nt], bh1[nt]);
                }
            }
        }
        __syncthreads();
    }

    // epilogue: v = c + nb1 + x; row LN stats via smem atomics
#pragma unroll
    for (int mt = 0; mt < 4; mt++){
        int r0 = m0 + warp_m + mt*16 + gid;
        int r1 = r0 + 8;
        float s0 = 0.f, q0 = 0.f, s1 = 0.f, q1 = 0.f;
#pragma unroll
        for (int nt = 0; nt < 5; nt++){
            int gn = warp_n + nt*8 + tq*2;
            float bx = nb1[gn], by = nb1[gn+1];
            float x00 = 0.f, x01 = 0.f, x10 = 0.f, x11 = 0.f;
            if (r0 < NN){ float2 xv = *(const float2*)&x[(size_t)r0*ND + gn]; x00 = xv.x; x01 = xv.y; }
            if (r1 < NN){ float2 xv = *(const float2*)&x[(size_t)r1*ND + gn]; x10 = xv.x; x11 = xv.y; }
            float v0 = c[mt][nt][0] + bx + x00;
            float v1 = c[mt][nt][1] + by + x01;
            float v2 = c[mt][nt][2] + bx + x10;
            float v3 = c[mt][nt][3] + by + x11;
            c[mt][nt][0] = v0; c[mt][nt][1] = v1;
            c[mt][nt][2] = v2; c[mt][nt][3] = v3;
            s0 += v0 + v1; q0 += v0*v0 + v1*v1;
            s1 += v2 + v3; q1 += v2*v2 + v3*v3;
        }
        atomicAdd(&sSum[warp_m + mt*16 + gid],     s0);
        atomicAdd(&sSq [warp_m + mt*16 + gid],     q0);
        atomicAdd(&sSum[warp_m + mt*16 + gid + 8], s1);
        atomicAdd(&sSq [warp_m + mt*16 + gid + 8], q1);
    }
    __syncthreads();
    if (tid < 128){
        float mu = sSum[tid] * (1.f/ND);
        float var = sSq[tid] * (1.f/ND) - mu*mu;
        sMu[tid] = mu;
        sInv[tid] = rsqrtf(var + 1e-5f);
    }
    __syncthreads();

#pragma unroll
    for (int mt = 0; mt < 4; mt++){
        int lr0 = warp_m + mt*16 + gid, lr1 = lr0 + 8;
        int r0 = m0 + lr0, r1 = m0 + lr1;
        float mu0 = sMu[lr0], iv0 = sInv[lr0];
        float mu1 = sMu[lr1], iv1 = sInv[lr1];
#pragma unroll
        for (int nt = 0; nt < 5; nt++){
            int gn = warp_n + nt*8 + tq*2;
            float g0 = lg[gn], g1 = lg[gn+1], b0 = lb[gn], b1 = lb[gn+1];
            float o0 = (c[mt][nt][0]-mu0)*iv0*g0 + b0;
            float o1 = (c[mt][nt][1]-mu0)*iv0*g1 + b1;
            float o2 = (c[mt][nt][2]-mu1)*iv1*g0 + b0;
            float o3 = (c[mt][nt][3]-mu1)*iv1*g1 + b1;
            if (write_fp32){
                if (r0 < NN) *(float2*)&g_node_lat[(size_t)r0*ND + gn] = make_float2(o0, o1);
                if (r1 < NN) *(float2*)&g_node_lat[(size_t)r1*ND + gn] = make_float2(o2, o3);
            } else {
                int q = gn >> 1;
                if (r0 < NN) split2(o0, o1, gNLh[(size_t)r0*80 + q], gNLl[(size_t)r0*80 + q]);
                if (r1 < NN) split2(o2, o3, gNLh[(size_t)r1*80 + q], gNLl[(size_t)r1*80 + q]);
            }
        }
    }
}

// ---------------- fused edge kernel: ldmatrix A-operands ---------------------
__global__ __launch_bounds__(512,1) void k_edge_tc(
    const int* __restrict__ row, const int* __restrict__ col,
    const float* __restrict__ eb1, const float* __restrict__ eb2,
    const float* __restrict__ mb1, const float* __restrict__ attv,
    const float* __restrict__ lgE, const float* __restrict__ lbE)
{
    extern __shared__ uint32_t esm[];
    uint32_t* Ah  = esm;              // [128][68]
    uint32_t* Al  = esm + 8704;
    uint32_t* B1h = esm + 17408;      // [256][20]
    uint32_t* B1l = esm + 22528;
    uint32_t* Hh  = esm;              // [128][132] overlay (phase2)
    uint32_t* Hl  = esm + 16896;
    uint32_t* B2h = esm + 33792;      // [64][36]
    uint32_t* B2l = esm + 36096;
    uint32_t* NEh = esm;              // [128][36] overlay
    uint32_t* NEl = esm + 4608;
    uint32_t* B3h = esm + 9216;       // [256][36]
    uint32_t* B3l = esm + 18432;
    __shared__ int sR[128], sC[128];
    __shared__ float sAtt[256];
    __shared__ float sLog[128];
    __shared__ float sSum[128], sSq[128], sMu[128], sInv[128];

    const int tid = threadIdx.x, wid = tid>>5, lane = tid&31;
    const int gid = lane>>2, tq = lane&3;
    const int warp_m  = (wid & 1)*64;
    const int warp_n  = (wid >> 1)*32;
    const int warp_n2 = (wid >> 1)*8;
    const int e0 = blockIdx.x*128;

    const int lrow = lane & 15;
    const int lkh  = (lane >> 4) << 2;
    const uint32_t aAh = (uint32_t)__cvta_generic_to_shared(Ah);
    const uint32_t aAl = (uint32_t)__cvta_generic_to_shared(Al);
    const uint32_t aHh = (uint32_t)__cvta_generic_to_shared(Hh);
    const uint32_t aHl = (uint32_t)__cvta_generic_to_shared(Hl);
    const uint32_t aNh = (uint32_t)__cvta_generic_to_shared(NEh);
    const uint32_t aNl = (uint32_t)__cvta_generic_to_shared(NEl);
    uint32_t offA[4], offH[4], offN[4];
#pragma unroll
    for (int mt = 0; mt < 4; mt++){
        int r = warp_m + mt*16 + lrow;
        offA[mt] = (uint32_t)((r*68  + lkh) * 4);
        offH[mt] = (uint32_t)((r*132 + lkh) * 4);
        offN[mt] = (uint32_t)((r*36  + lkh) * 4);
    }

    if (tid < 128){
        int ge = e0 + tid;
        sR[tid] = (ge < NE) ? row[ge] : 0;
        sC[tid] = (ge < NE) ? col[ge] : 0;
        sLog[tid] = 0.f; sSum[tid] = 0.f; sSq[tid] = 0.f;
    }
    if (tid < 256) sAtt[tid] = attv[tid];
    __syncthreads();

    // ---- phase 1 ------------------------------------------------------------
    for (int lin = tid; lin < 8192; lin += 512){
        int r = lin>>6, w = lin&63, k = w*2;
        float2 v = make_float2(0.f, 0.f);
        if (e0 + r < NE)
            v = (k < 64) ? *(const float2*)&g_init_edge[(size_t)(e0+r)*ED + k]
                         : *(const float2*)&g_edge_lat [(size_t)(e0+r)*ED + (k-64)];
        split2(v.x, v.y, Ah[r*68+w], Al[r*68+w]);
    }
    float c1[4][4][4];
#pragma unroll
    for (int mt = 0; mt < 4; mt++){
        int rA = warp_m + mt*16 + gid, rB = rA + 8;
        size_t prA = (size_t)sR[rA]*768, pcA = (size_t)sC[rA]*768;
        size_t prB = (size_t)sR[rB]*768, pcB = (size_t)sC[rB]*768;
#pragma unroll
        for (int nt = 0; nt < 4; nt++){
            int cn = warp_n + nt*8 + tq*2;
            float2 b  = *(const float2*)&eb1[cn];
            float2 a1 = *(const float2*)&g_P[prA + cn];
            float2 a2 = *(const float2*)&g_P[pcA + 256 + cn];
            float2 a3 = *(const float2*)&g_P[prB + cn];
            float2 a4 = *(const float2*)&g_P[pcB + 256 + cn];
            c1[mt][nt][0] = a1.x + a2.x + b.x;
            c1[mt][nt][1] = a1.y + a2.y + b.y;
            c1[mt][nt][2] = a3.x + a4.x + b.x;
            c1[mt][nt][3] = a3.y + a4.y + b.y;
        }
    }
    __syncthreads();

#pragma unroll
    for (int ch = 0; ch < 4; ch++){
        for (int lin = tid; lin < 1024; lin += 512){
            int r = lin>>2, q = lin&3;
            size_t gofs = (size_t)r*64 + ch*16 + q*4;
            *(uint4*)&B1h[r*20 + q*4] = *(const uint4*)&gB1h[gofs];
            *(uint4*)&B1l[r*20 + q*4] = *(const uint4*)&gB1l[gofs];
        }
        __syncthreads();
#pragma unroll
        for (int s = 0; s < 2; s++){
            int kb = s*8 + tq;
            uint32_t kw = (uint32_t)((ch*16 + s*8) * 4);
            uint32_t bh0[4], bh1[4], bl0[4], bl1[4];
#pragma unroll
            for (int nt = 0; nt < 4; nt++){
                int nr = warp_n + nt*8 + gid;
                bh0[nt] = B1h[nr*20+kb]; bh1[nt] = B1h[nr*20+kb+4];
                bl0[nt] = B1l[nr*20+kb]; bl1[nt] = B1l[nr*20+kb+4];
            }
#pragma unroll
            for (int mt = 0; mt < 4; mt++){
                uint32_t ah0,ah1,ah2,ah3, al0,al1,al2,al3;
                ldsm_x4(ah0,ah1,ah2,ah3, aAh + offA[mt] + kw);
                ldsm_x4(al0,al1,al2,al3, aAl + offA[mt] + kw);
#pragma unroll
                for (int nt = 0; nt < 4; nt++){
                    mma_bf16(c1[mt][nt][0],c1[mt][nt][1],c1[mt][nt][2],c1[mt][nt][3],
                             ah0,ah1,ah2,ah3, bh0[nt],bh1[nt]);
                    mma_bf16(c1[mt][nt][0],c1[mt][nt][1],c1[mt][nt][2],c1[mt][nt][3],
                             ah0,ah1,ah2,ah3, bl0[nt],bl1[nt]);
                    mma_bf16(c1[mt][nt][0],c1[mt][nt][1],c1[mt][nt][2],c1[mt][nt][3],
                             al0,al1,al2,al3, bh0[nt],bh1[nt]);
                }
            }
        }
        __syncthreads();
    }

    // write hidden (relu, bf16 split) over A/B1 region
#pragma unroll
    for (int mt = 0; mt < 4; mt++){
        int rA = warp_m + mt*16 + gid, rB = rA + 8;
#pragma unroll
        for (int nt = 0; nt < 4; nt++){
            int wcol = (warp_n>>1) + nt*4 + tq;
            float v0 = fmaxf(c1[mt][nt][0], 0.f), v1 = fmaxf(c1[mt][nt][1], 0.f);
            float v2 = fmaxf(c1[mt][nt][2], 0.f), v3 = fmaxf(c1[mt][nt][3], 0.f);
            split2(v0, v1, Hh[rA*132+wcol], Hl[rA*132+wcol]);
            split2(v2, v3, Hh[rB*132+wcol], Hl[rB*132+wcol]);
        }
    }
    __syncthreads();

    // ---- phase 2 ------------------------------------------------------------
    float c2[4][4];
#pragma unroll
    for (int mt = 0; mt < 4; mt++){
        float2 b = *(const float2*)&eb2[warp_n2 + tq*2];
        c2[mt][0] = b.x; c2[mt][1] = b.y; c2[mt][2] = b.x; c2[mt][3] = b.y;
    }
#pragma unroll
    for (int ch = 0; ch < 4; ch++){
        {
            int r = tid>>3, q = tid&7;
            size_t gofs = (size_t)r*128 + ch*32 + q*4;
            *(uint4*)&B2h[r*36 + q*4] = *(const uint4*)&gB2h[gofs];
            *(uint4*)&B2l[r*36 + q*4] = *(const uint4*)&gB2l[gofs];
        }
        __syncthreads();
#pragma unroll
        for (int s = 0; s < 4; s++){
            int kb = s*8 + tq;
            uint32_t kw = (uint32_t)((ch*32 + s*8) * 4);
            int nr = warp_n2 + gid;
            uint32_t bh0 = B2h[nr*36+kb], bh1 = B2h[nr*36+kb+4];
            uint32_t bl0 = B2l[nr*36+kb], bl1 = B2l[nr*36+kb+4];
#pragma unroll
            for (int mt = 0; mt < 4; mt++){
                uint32_t ah0,ah1,ah2,ah3, al0,al1,al2,al3;
                ldsm_x4(ah0,ah1,ah2,ah3, aHh + offH[mt] + kw);
                ldsm_x4(al0,al1,al2,al3, aHl + offH[mt] + kw);
                mma_bf16(c2[mt][0],c2[mt][1],c2[mt][2],c2[mt][3], ah0,ah1,ah2,ah3, bh0,bh1);
                mma_bf16(c2[mt][0],c2[mt][1],c2[mt][2],c2[mt][3], ah0,ah1,ah2,ah3, bl0,bl1);
                mma_bf16(c2[mt][0],c2[mt][1],c2[mt][2],c2[mt][3], al0,al1,al2,al3, bh0,bh1);
            }
        }
        __syncthreads();
    }

    // ---- NE pack + LN stats; stage full B3 (stride 36) -----------------------
#pragma unroll
    for (int mt = 0; mt < 4; mt++){
        int rA = warp_m + mt*16 + gid, rB = rA + 8;
        int cn = warp_n2 + tq*2;
        int wcol = (warp_n2>>1) + tq;
        split2(c2[mt][0], c2[mt][1], NEh[rA*36+wcol], NEl[rA*36+wcol]);
        split2(c2[mt][2], c2[mt][3], NEh[rB*36+wcol], NEl[rB*36+wcol]);
        float2 iA = make_float2(0.f,0.f), iB = make_float2(0.f,0.f);
        if (e0 + rA < NE) iA = *(const float2*)&g_init_edge[(size_t)(e0+rA)*ED + cn];
        if (e0 + rB < NE) iB = *(const float2*)&g_init_edge[(size_t)(e0+rB)*ED + cn];
        c2[mt][0] += iA.x; c2[mt][1] += iA.y;
        c2[mt][2] += iB.x; c2[mt][3] += iB.y;
        atomicAdd(&sSum[rA], c2[mt][0] + c2[mt][1]);
        atomicAdd(&sSq [rA], c2[mt][0]*c2[mt][0] + c2[mt][1]*c2[mt][1]);
        atomicAdd(&sSum[rB], c2[mt][2] + c2[mt][3]);
        atomicAdd(&sSq [rB], c2[mt][2]*c2[mt][2] + c2[mt][3]*c2[mt][3]);
    }
    for (int lin = tid; lin < 2048; lin += 512){
        int r = lin>>3, q = lin&7;
        size_t gofs = (size_t)r*32 + q*4;
        *(uint4*)&B3h[r*36 + q*4] = *(const uint4*)&gB3h[gofs];
        *(uint4*)&B3l[r*36 + q*4] = *(const uint4*)&gB3l[gofs];
    }
    float c3[4][4][4];
#pragma unroll
    for (int mt = 0; mt < 4; mt++){
        int rA = warp_m + mt*16 + gid, rB = rA + 8;
        size_t pcA = (size_t)sC[rA]*768, pcB = (size_t)sC[rB]*768;
#pragma unroll
        for (int nt = 0; nt < 4; nt++){
            int cn = warp_n + nt*8 + tq*2;
            float2 b  = *(const float2*)&mb1[cn];
            float2 a1 = *(const float2*)&g_P[pcA + 512 + cn];
            float2 a2 = *(const float2*)&g_P[pcB + 512 + cn];
            c3[mt][nt][0] = a1.x + b.x; c3[mt][nt][1] = a1.y + b.y;
            c3[mt][nt][2] = a2.x + b.x; c3[mt][nt][3] = a2.y + b.y;
        }
    }
    __syncthreads();

    if (tid < 128){
        float mu = sSum[tid] * (1.f/ED);
        float var = sSq[tid] * (1.f/ED) - mu*mu;
        sMu[tid] = mu;
        sInv[tid] = rsqrtf(var + 1e-5f);
    }
    __syncthreads();

#pragma unroll
    for (int mt = 0; mt < 4; mt++){
        int rA = warp_m + mt*16 + gid, rB = rA + 8;
        int cn = warp_n2 + tq*2;
        float g0 = lgE[cn], g1 = lgE[cn+1], b0 = lbE[cn], b1 = lbE[cn+1];
        if (e0 + rA < NE){
            float mu = sMu[rA], inv = sInv[rA];
            *(float2*)&g_edge_lat[(size_t)(e0+rA)*ED + cn] =
                make_float2((c2[mt][0]-mu)*inv*g0 + b0, (c2[mt][1]-mu)*inv*g1 + b1);
        }
        if (e0 + rB < NE){
            float mu = sMu[rB], inv = sInv[rB];
            *(float2*)&g_edge_lat[(size_t)(e0+rB)*ED + cn] =
                make_float2((c2[mt][2]-mu)*inv*g0 + b0, (c2[mt][3]-mu)*inv*g1 + b1);
        }
    }

    // ---- phase 3 MMA loop ----------------------------------------------------
#pragma unroll
    for (int s = 0; s < 4; s++){
        int ka = s*8 + tq;
        uint32_t kw = (uint32_t)((s*8) * 4);
        uint32_t bh0[4], bh1[4], bl0[4], bl1[4];
#pragma unroll
        for (int nt = 0; nt < 4; nt++){
            int nr = warp_n + nt*8 + gid;
            bh0[nt] = B3h[nr*36+ka]; bh1[nt] = B3h[nr*36+ka+4];
            bl0[nt] = B3l[nr*36+ka]; bl1[nt] = B3l[nr*36+ka+4];
        }
#pragma unroll
        for (int mt = 0; mt < 4; mt++){
            uint32_t ah0,ah1,ah2,ah3, al0,al1,al2,al3;
            ldsm_x4(ah0,ah1,ah2,ah3, aNh + offN[mt] + kw);
            ldsm_x4(al0,al1,al2,al3, aNl + offN[mt] + kw);
#pragma unroll
            for (int nt = 0; nt < 4; nt++){
                mma_bf16(c3[mt][nt][0],c3[mt][nt][1],c3[mt][nt][2],c3[mt][nt][3],
                         ah0,ah1,ah2,ah3, bh0[nt],bh1[nt]);
                mma_bf16(c3[mt][nt][0],c3[mt][nt][1],c3[mt][nt][2],c3[mt][nt][3],
                         ah0,ah1,ah2,ah3, bl0[nt],bl1[nt]);
                mma_bf16(c3[mt][nt][0],c3[mt][nt][1],c3[mt][nt][2],c3[mt][nt][3],
                         al0,al1,al2,al3, bh0[nt],bh1[nt]);
            }
        }
    }

    // epilogue: relu -> g_msg, attention partial dot, logit
    float pa[4][2];
#pragma unroll
    for (int mt = 0; mt < 4; mt++){ pa[mt][0] = 0.f; pa[mt][1] = 0.f; }
#pragma unroll
    for (int mt = 0; mt < 4; mt++){
        int rA = warp_m + mt*16 + gid, rB = rA + 8;
#pragma unroll
        for (int nt = 0; nt < 4; nt++){
            int cn = warp_n + nt*8 + tq*2;
            float av0 = sAtt[cn], av1 = sAtt[cn+1];
            float v0 = fmaxf(c3[mt][nt][0], 0.f), v1 = fmaxf(c3[mt][nt][1], 0.f);
            float v2 = fmaxf(c3[mt][nt][2], 0.f), v3 = fmaxf(c3[mt][nt][3], 0.f);
            if (e0 + rA < NE)
                *(float2*)&g_msg[(size_t)(e0+rA)*HD + cn] = make_float2(v0, v1);
            if (e0 + rB < NE)
                *(float2*)&g_msg[(size_t)(e0+rB)*HD + cn] = make_float2(v2, v3);
            pa[mt][0] += v0*av0 + v1*av1;
            pa[mt][1] += v2*av0 + v3*av1;
        }
    }
#pragma unroll
    for (int off = 1; off <= 2; off <<= 1){
#pragma unroll
        for (int mt = 0; mt < 4; mt++){
            pa[mt][0] += __shfl_xor_sync(0xffffffffu, pa[mt][0], off, 4);
            pa[mt][1] += __shfl_xor_sync(0xffffffffu, pa[mt][1], off, 4);
        }
    }
    if (tq == 0){
#pragma unroll
        for (int mt = 0; mt < 4; mt++){
            atomicAdd(&sLog[warp_m + mt*16 + gid],     pa[mt][0]);
            atomicAdd(&sLog[warp_m + mt*16 + gid + 8], pa[mt][1]);
        }
    }
    __syncthreads();
    if (tid < 128 && e0 + tid < NE){
        float p = sLog[tid];
        g_logit[e0+tid] = (p > 0.f) ? p : 0.2f*p;
    }
}

// ---------------- edge encoder tail (dual-writes init_edge + edge_lat) -------
__global__ __launch_bounds__(256,2) void k_enc_edge(
    const float* __restrict__ ea,
    const int* __restrict__ row, const int* __restrict__ col,
    const float* __restrict__ encW1, const float* __restrict__ encb1,
    const float* __restrict__ encW2, const float* __restrict__ encb2)
{
    __shared__ float As[64*9];
    __shared__ float Bs[16*64];
    __shared__ float Hid[64*132];
    __shared__ int sR[64], sC[64];

    const int e0 = blockIdx.x*64;
    const int tid = threadIdx.x, ty = tid>>4, tx = tid&15;
    if (tid < 64){ sR[tid] = row[e0+tid]; sC[tid] = col[e0+tid]; }
    __syncthreads();

    float c[4][8];
#pragma unroll
    for (int i = 0; i < 4; i++){
        int r = ty*4+i;
#pragma unroll
        for (int j = 0; j < 8; j++){
            int n = tx + 16*j;
            c[i][j] = g_Penc[(size_t)sR[r]*256 + n]
                    + g_Penc[(size_t)sC[r]*256 + 128 + n]
                    + encb1[n];
        }
    }
    for (int t = tid; t < 512; t += 256){
        int el = t>>3, kk = t&7;
        As[el*9+kk] = ea[(e0+el)*RD + kk];
    }
    for (int t = tid; t < 1024; t += 256){
        int kk = t>>7, n = t&127;
        Bs[t] = encW1[(320+kk)*EH + n];
    }
    __syncthreads();
#pragma unroll
    for (int kk = 0; kk < 8; kk++){
        float a0 = As[(ty*4+0)*9+kk], a1 = As[(ty*4+1)*9+kk];
        float a2 = As[(ty*4+2)*9+kk], a3 = As[(ty*4+3)*9+kk];
#pragma unroll
        for (int j = 0; j < 8; j++){
            float b = Bs[kk*128 + tx + 16*j];
            c[0][j] += a0*b; c[1][j] += a1*b; c[2][j] += a2*b; c[3][j] += a3*b;
        }
    }
    __syncthreads();
#pragma unroll
    for (int i = 0; i < 4; i++)
#pragma unroll
        for (int j = 0; j < 8; j++){
            int n = tx + 16*j;
            Hid[(ty*4+i)*132 + n] = fmaxf(c[i][j], 0.f);
        }
    __syncthreads();

    float c2[4][4];
#pragma unroll
    for (int i = 0; i < 4; i++)
#pragma unroll
        for (int j = 0; j < 4; j++) c2[i][j] = encb2[tx+16*j];

    for (int kc = 0; kc < 128; kc += 16){
        for (int t = tid; t < 1024; t += 256){
            int kk = t>>6, n = t&63;
            Bs[t] = encW2[(kc+kk)*ED + n];
        }
        __syncthreads();
#pragma unroll
        for (int kk = 0; kk < 16; kk++){
            float a0 = Hid[(ty*4+0)*132 + kc+kk], a1 = Hid[(ty*4+1)*132 + kc+kk];
            float a2 = Hid[(ty*4+2)*132 + kc+kk], a3 = Hid[(ty*4+3)*132 + kc+kk];
#pragma unroll
            for (int j = 0; j < 4; j++){
                float b = Bs[kk*64 + tx + 16*j];
                c2[0][j] += a0*b; c2[1][j] += a1*b; c2[2][j] += a2*b; c2[3][j] += a3*b;
            }
        }
        __syncthreads();
    }
#pragma unroll
    for (int i = 0; i < 4; i++)
#pragma unroll
        for (int j = 0; j < 4; j++){
            size_t o = (size_t)(e0+ty*4+i)*ED + tx + 16*j;
            g_init_edge[o] = c2[i][j];
            g_edge_lat[o]  = c2[i][j];
        }
}

// ---------------- k_agg: segment softmax + aggregation -> packed bf16 --------
__global__ __launch_bounds__(256,2) void k_agg()
{
    __shared__ float agg[16*260];

    const int n0 = blockIdx.x*16;
    const int tid = threadIdx.x, g = tid>>4, t = tid&15;
    const int n = n0 + g;
    const int beg = g_rowptr[n], end = g_rowptr[n+1];

    float m = -1e30f;
    for (int i = beg+t; i < end; i += 16) m = fmaxf(m, g_logit[g_eids[i]]);
#pragma unroll
    for (int off = 8; off >= 1; off >>= 1) m = fmaxf(m, __shfl_xor_sync(0xffffffffu, m, off, 16));

    float den = 0.f;
    for (int i = beg+t; i < end; i += 16) den += expf(g_logit[g_eids[i]] - m);
#pragma unroll
    for (int off = 8; off >= 1; off >>= 1) den += __shfl_xor_sync(0xffffffffu, den, off, 16);
    den += 1e-16f;
    float inv_den = 1.f/den;

    float acc[16];
#pragma unroll
    for (int q = 0; q < 16; q++) acc[q] = 0.f;
    for (int i = beg; i < end; i++){
        int e = g_eids[i];
        float w = expf(g_logit[e] - m) * inv_den;
        const float* mr = g_msg + (size_t)e*HD;
#pragma unroll
        for (int q = 0; q < 16; q++) acc[q] += w * mr[t + 16*q];
    }
#pragma unroll
    for (int q = 0; q < 16; q++) agg[g*260 + t + 16*q] = acc[q];
    __syncthreads();

    for (int i = tid; i < 2048; i += 256){
        int gg = i >> 7, q = i & 127;
        split2(agg[gg*260 + 2*q], agg[gg*260 + 2*q + 1],
               gAGh[(size_t)(n0+gg)*128 + q], gAGl[(size_t)(n0+gg)*128 + q]);
    }
}

// ---------------- launch -----------------------------------------------------
extern "C" void kernel_launch(void* const* d_in, const int* in_sizes, int n_in,
                              void* d_out, int out_size)
{
    const float* x     = (const float*)d_in[0];
    const float* ea    = (const float*)d_in[1];
    const float* encW1 = (const float*)d_in[2];
    const float* encb1 = (const float*)d_in[3];
    const float* encW2 = (const float*)d_in[4];
    const float* encb2 = (const float*)d_in[5];
    const float* eW1   = (const float*)d_in[6];
    const float* eb1   = (const float*)d_in[7];
    const float* eW2   = (const float*)d_in[8];
    const float* eb2   = (const float*)d_in[9];
    const float* mW1   = (const float*)d_in[10];
    const float* mb1   = (const float*)d_in[11];
    const float* attv  = (const float*)d_in[12];
    const float* nW1   = (const float*)d_in[13];
    const float* nb1   = (const float*)d_in[14];
    const float* ln_ng = (const float*)d_in[15];
    const float* ln_nb = (const float*)d_in[16];
    const float* ln_eg = (const float*)d_in[17];
    const float* ln_eb = (const float*)d_in[18];
    const int*   erow  = (const int*)d_in[19];
    const int*   ecol  = (const int*)d_in[20];

    void *p_deg, *p_rowptr, *p_fill, *p_node, *p_edge, *p_P, *p_Pbase, *p_Penc;
    void *p_WEh, *p_WEl, *p_WPh, *p_WPl, *p_W0h, *p_W0l;
    void *p_Xh, *p_Xl, *p_NLh, *p_NLl;
    cudaGetSymbolAddress(&p_deg,    g_deg);
    cudaGetSymbolAddress(&p_rowptr, g_rowptr);
    cudaGetSymbolAddress(&p_fill,   g_fill);
    cudaGetSymbolAddress(&p_node,   g_node_lat);
    cudaGetSymbolAddress(&p_edge,   g_edge_lat);
    cudaGetSymbolAddress(&p_P,      g_P);
    cudaGetSymbolAddress(&p_Pbase,  g_Pbase);
    cudaGetSymbolAddress(&p_Penc,   g_Penc);
    cudaGetSymbolAddress(&p_WEh,    gWEh);
    cudaGetSymbolAddress(&p_WEl,    gWEl);
    cudaGetSymbolAddress(&p_WPh,    gWPh);
    cudaGetSymbolAddress(&p_WPl,    gWPl);
    cudaGetSymbolAddress(&p_W0h,    gW0h);
    cudaGetSymbolAddress(&p_W0l,    gW0l);
    cudaGetSymbolAddress(&p_Xh,     gXh);
    cudaGetSymbolAddress(&p_Xl,     gXl);
    cudaGetSymbolAddress(&p_NLh,    gNLh);
    cudaGetSymbolAddress(&p_NLl,    gNLl);

    cudaFuncSetAttribute(k_edge_tc, cudaFuncAttributeMaxDynamicSharedMemorySize, 153600);

    static cudaStream_t s1 = nullptr;
    static cudaEvent_t evA = nullptr, evPackA = nullptr, evCSR = nullptr, evC = nullptr;
    if (s1 == nullptr){
        cudaStreamCreateWithFlags(&s1, cudaStreamNonBlocking);
        cudaEventCreateWithFlags(&evA,     cudaEventDisableTiming);
        cudaEventCreateWithFlags(&evPackA, cudaEventDisableTiming);
        cudaEventCreateWithFlags(&evCSR,   cudaEventDisableTiming);
        cudaEventCreateWithFlags(&evC,     cudaEventDisableTiming);
    }

    // fork: CSR build + Pbase GEMM on s1, rest on stream 0
    cudaEventRecord(evA, 0);
    cudaStreamWaitEvent(s1, evA, 0);

    cudaMemsetAsync(p_deg, 0, NN*sizeof(int), s1);
    k_hist<<<(NE+255)/256, 256, 0, s1>>>(erow);
    k_scan1<<<49, 256, 0, s1>>>();
    k_scan2<<<1, 32, 0, s1>>>();
    k_scan3<<<(NN+255)/256, 256, 0, s1>>>();
    cudaMemcpyAsync(p_fill, p_rowptr, NN*sizeof(int), cudaMemcpyDeviceToDevice, s1);
    k_scatter<<<(NE+255)/256, 256, 0, s1>>>(erow);
    cudaEventRecord(evCSR, s1);

    // stream 0 prologue
    k_prep<<<480, 256>>>(eW1, mW1, encW1, eW2, nW1);
    k_packA<<<(NN*80+255)/256, 256>>>(x, (uint32_t*)p_Xh, (uint32_t*)p_Xl);
    cudaEventRecord(evPackA, 0);

    // Pbase GEMM moved to s1 (needed only from iteration 1)
    cudaStreamWaitEvent(s1, evPackA, 0);
    {
        dim3 g((NN+127)/128, 6);
        k_gemm_bf<<<g, 256, 0, s1>>>((const uint32_t*)p_Xh, (const uint32_t*)p_Xl, 80,
                              (const uint32_t*)p_WPh, (const uint32_t*)p_WPl,
                              160, 160, (float*)p_Pbase, 768, 768, nullptr, nullptr);
    }
    cudaEventRecord(evC, s1);

    {
        dim3 g((NN+127)/128, 2);
        k_gemm_bf<<<g, 256>>>((const uint32_t*)p_Xh, (const uint32_t*)p_Xl, 80,
                              (const uint32_t*)p_WEh, (const uint32_t*)p_WEl,
                              160, 80, (float*)p_Penc, 256, 256, nullptr, nullptr);
    }
    k_enc_edge<<<NE/64, 256>>>(ea, erow, ecol, encW1, encb1, encW2, encb2);

    for (int it = 0; it < 3; it++){
        dim3 g((NN+127)/128, 6);
        if (it == 0){
            // P0 = x @ (W_x + W_nl): combined table, no base read
            k_gemm_bf<<<g, 256>>>((const uint32_t*)p_Xh, (const uint32_t*)p_Xl, 80,
                                  (const uint32_t*)p_W0h, (const uint32_t*)p_W0l,
                                  160, 80, (float*)p_P, 768, 768, nullptr, nullptr);
        } else {
            if (it == 1) cudaStreamWaitEvent(0, evC, 0);   // join Pbase
            k_gemm_bf<<<g, 256>>>((const uint32_t*)p_NLh, (const uint32_t*)p_NLl, 80,
                                  (const uint32_t*)p_WPh + 80, (const uint32_t*)p_WPl + 80,
                                  160, 160, (float*)p_P, 768, 768, (const float*)p_Pbase, nullptr);
        }
        k_edge_tc<<<(NE+127)/128, 512, 153600>>>(erow, ecol, eb1, eb2, mb1, attv, ln_eg, ln_eb);
        if (it == 0) cudaStreamWaitEvent(0, evCSR, 0);     // join CSR before first agg
        k_agg<<<NN/16, 256>>>();
        k_nmlp<<<(NN+127)/128, 256>>>(x, nb1, ln_ng, ln_nb, (it == 2) ? 1 : 0);
    }

    float* out = (float*)d_out;
    if (out_size >= NN*ND + NE*ED){
        cudaMemcpyAsync(out,         p_node, (size_t)NN*ND*sizeof(float), cudaMemcpyDeviceToDevice, 0);
        cudaMemcpyAsync(out + NN*ND, p_edge, (size_t)NE*ED*sizeof(float), cudaMemcpyDeviceToDevice, 0);
    } else if (out_size == NN*ND){
        cudaMemcpyAsync(out, p_node, (size_t)NN*ND*sizeof(float), cudaMemcpyDeviceToDevice, 0);
    } else {
        size_t nel = (size_t)((out_size < NE*ED) ? out_size : NE*ED);
        cudaMemcpyAsync(out, p_edge, nel*sizeof(float), cudaMemcpyDeviceToDevice, 0);
    }
}